// round 9
// baseline (speedup 1.0000x reference)
#include <cuda_runtime.h>
#include <cuda_bf16.h>
#include <cstdint>
#include <math.h>

typedef unsigned int u32;
typedef unsigned long long u64;
typedef unsigned short u16;

#define BSZ 2
#define SEQ 2048
#define EMB 2048
#define NH 32
#define HD 64
#define MROWS (BSZ*SEQ)

// ---------------------------------------------------------------------------
// Scratch (device globals: allocation-free per harness rules)
// ---------------------------------------------------------------------------
__device__ __align__(16) __nv_bfloat16 g_ah[(size_t)MROWS * EMB];
__device__ __align__(16) __nv_bfloat16 g_al[(size_t)MROWS * EMB];
__device__ __align__(16) __nv_bfloat16 g_bh[(size_t)4 * EMB * EMB];  // W^T hi x4
__device__ __align__(16) __nv_bfloat16 g_bl[(size_t)4 * EMB * EMB];  // W^T lo x4
__device__ __align__(16) __nv_bfloat16 g_qh[(size_t)MROWS * EMB];
__device__ __align__(16) __nv_bfloat16 g_ql[(size_t)MROWS * EMB];
__device__ __align__(16) __nv_bfloat16 g_kh[(size_t)MROWS * EMB];
__device__ __align__(16) __nv_bfloat16 g_kl[(size_t)MROWS * EMB];
__device__ __align__(16) __nv_bfloat16 g_vh[(size_t)MROWS * EMB];
__device__ __align__(16) __nv_bfloat16 g_vl[(size_t)MROWS * EMB];
__device__ __align__(16) __nv_bfloat16 g_vth[(size_t)MROWS * EMB]; // V^T per (b,h)
__device__ __align__(16) __nv_bfloat16 g_vtl[(size_t)MROWS * EMB];

// ---------------------------------------------------------------------------
// Warp-MMA / cp.async helpers (baseline PTX: works on plain sm_103 target)
// ---------------------------------------------------------------------------
__device__ __forceinline__ u32 smem_u32(const void* p) {
    u32 a;
    asm("{ .reg .u64 t; cvta.to.shared.u64 t, %1; cvt.u32.u64 %0, t; }"
        : "=r"(a) : "l"(p));
    return a;
}
__device__ __forceinline__ void ldsm_x4(u32& r0, u32& r1, u32& r2, u32& r3,
                                        u32 addr) {
    asm volatile("ldmatrix.sync.aligned.m8n8.x4.shared.b16 {%0,%1,%2,%3}, [%4];"
                 : "=r"(r0), "=r"(r1), "=r"(r2), "=r"(r3) : "r"(addr));
}
__device__ __forceinline__ void mma_bf16(float* d, const u32* a, const u32* b) {
    asm volatile(
        "mma.sync.aligned.m16n8k16.row.col.f32.bf16.bf16.f32 "
        "{%0,%1,%2,%3}, {%4,%5,%6,%7}, {%8,%9}, {%0,%1,%2,%3};"
        : "+f"(d[0]), "+f"(d[1]), "+f"(d[2]), "+f"(d[3])
        : "r"(a[0]), "r"(a[1]), "r"(a[2]), "r"(a[3]), "r"(b[0]), "r"(b[1]));
}
__device__ __forceinline__ void cp16(u32 dst, const void* src) {
    asm volatile("cp.async.cg.shared.global [%0], [%1], 16;"
                 :: "r"(dst), "l"(src) : "memory");
}
#define CP_COMMIT() asm volatile("cp.async.commit_group;" ::: "memory")
#define CP_WAIT(n)  asm volatile("cp.async.wait_group %0;" :: "n"(n) : "memory")

// pack two fp32 -> bf16x2 (lo = x0), plus bf16x2 of the residuals
__device__ __forceinline__ void pack_hl(float x0, float x1, u32& hi, u32& lo) {
    asm("cvt.rn.bf16x2.f32 %0, %1, %2;" : "=r"(hi) : "f"(x1), "f"(x0));
    float h0 = __uint_as_float(hi << 16);
    float h1 = __uint_as_float(hi & 0xFFFF0000u);
    float r0 = x0 - h0, r1 = x1 - h1;
    asm("cvt.rn.bf16x2.f32 %0, %1, %2;" : "=r"(lo) : "f"(r1), "f"(r0));
}
#define SWZ64(o)  ((o) ^ (((o) >> 3) & 0x30))
#define SWZ128(o) ((o) ^ (((o) >> 3) & 0x70))

// ---------------------------------------------------------------------------
// Conversion kernels
// ---------------------------------------------------------------------------
__global__ void conv_rows(const float* __restrict__ X,
                          __nv_bfloat16* __restrict__ H,
                          __nv_bfloat16* __restrict__ L, int n4)
{
    int i = blockIdx.x * blockDim.x + threadIdx.x;
    if (i >= n4) return;
    float4 v = ((const float4*)X)[i];
    u32 h0, l0, h1, l1;
    pack_hl(v.x, v.y, h0, l0);
    pack_hl(v.z, v.w, h1, l1);
    ((uint2*)H)[i] = make_uint2(h0, h1);
    ((uint2*)L)[i] = make_uint2(l0, l1);
}

// All 4 weights W[K,N] fp32 -> W^T hi/lo bf16 [N,K], one launch (z selects W)
__global__ void conv_T4(const float* __restrict__ W0, const float* __restrict__ W1,
                        const float* __restrict__ W2, const float* __restrict__ W3,
                        __nv_bfloat16* __restrict__ Th,
                        __nv_bfloat16* __restrict__ Tl)
{
    __shared__ float t[32][33];
    int z = blockIdx.z;
    const float* W = (z == 0) ? W0 : (z == 1) ? W1 : (z == 2) ? W2 : W3;
    size_t zo = (size_t)z * EMB * EMB;
    int n0 = blockIdx.x * 32, k0 = blockIdx.y * 32;
    int x = threadIdx.x, y = threadIdx.y;  // 32 x 8
#pragma unroll
    for (int r = 0; r < 32; r += 8)
        t[y + r][x] = W[(size_t)(k0 + y + r) * EMB + n0 + x];
    __syncthreads();
#pragma unroll
    for (int r = 0; r < 32; r += 8) {
        float v = t[x][y + r];
        __nv_bfloat16 h = __float2bfloat16(v);
        size_t o = zo + (size_t)(n0 + y + r) * EMB + k0 + x;
        Th[o] = h;
        Tl[o] = __float2bfloat16(v - __bfloat162float(h));
    }
}

// Vh/Vl [token][h*64+d] -> VTh/VTl [(b*NH+h)*64+d][seq]
__global__ void conv_vt(const __nv_bfloat16* __restrict__ Vh,
                        const __nv_bfloat16* __restrict__ Vl,
                        __nv_bfloat16* __restrict__ VTh,
                        __nv_bfloat16* __restrict__ VTl)
{
    __shared__ u16 th[32][33], tl[32][33];
    int s0 = blockIdx.x * 32;
    int d0 = (blockIdx.y & 1) * 32;
    int hh = (blockIdx.y >> 1) & 31;
    int b  = blockIdx.y >> 6;
    int x = threadIdx.x, y = threadIdx.y;  // 32 x 8
#pragma unroll
    for (int r = 0; r < 32; r += 8) {
        size_t g = (size_t)(b * SEQ + s0 + y + r) * EMB + hh * HD + d0 + x;
        th[y + r][x] = *(const u16*)(Vh + g);
        tl[y + r][x] = *(const u16*)(Vl + g);
    }
    __syncthreads();
#pragma unroll
    for (int r = 0; r < 32; r += 8) {
        size_t o = ((size_t)((b * NH + hh) * HD) + d0 + y + r) * SEQ + s0 + x;
        *(u16*)(VTh + o) = th[x][y + r];
        *(u16*)(VTl + o) = tl[x][y + r];
    }
}

// ---------------------------------------------------------------------------
// Tensor-core GEMM via mma.sync (bf16 hi/lo split, fp32 accumulate),
// cp.async 3-stage pipeline. Tile 128x256, 512 threads (warp grid 2x8,
// warp tile 64x32 — unchanged per-warp code). Cuts L2 traffic 25% vs 128x128.
// mats 0,1,2 -> bf16 hi/lo outputs (Q,K,V); mat 3 -> fp32 C (out proj).
// Stage layout (48 KB): AH 0, AL 8192, BH 16384, BL 32768.
// ---------------------------------------------------------------------------
#define BKC 32
#define GSTG 49152
#define GSMEM (3 * GSTG)

__global__ __launch_bounds__(512, 1)
void gemm_mma(const __nv_bfloat16* __restrict__ Ah,
              const __nv_bfloat16* __restrict__ Al,
              const __nv_bfloat16* __restrict__ BhAll,
              const __nv_bfloat16* __restrict__ BlAll,
              const float* __restrict__ b0, const float* __restrict__ b1,
              const float* __restrict__ b2, const float* __restrict__ b3,
              __nv_bfloat16* __restrict__ H0, __nv_bfloat16* __restrict__ L0,
              __nv_bfloat16* __restrict__ H1, __nv_bfloat16* __restrict__ L1,
              __nv_bfloat16* __restrict__ H2, __nv_bfloat16* __restrict__ L2,
              float* __restrict__ C, int mat_base, int M, int K)
{
    extern __shared__ char smg[];
    u32 sb = smem_u32(smg);
    const int N = EMB;

    int tid = threadIdx.x;
    int wid = tid / 32, lid = tid % 32;
    int wm = wid / 8, wn = wid % 8;        // warp grid 2 x 8
    int mat = mat_base + (blockIdx.x >> 3);
    int bm = blockIdx.y * 128, bn = (blockIdx.x & 7) * 256;

    const __nv_bfloat16* Bh = BhAll + (size_t)mat * EMB * EMB;
    const __nv_bfloat16* Bl = BlAll + (size_t)mat * EMB * EMB;
    const float* bias = (mat == 0) ? b0 : (mat == 1) ? b1 : (mat == 2) ? b2 : b3;

    float acc[4][4][4];
#pragma unroll
    for (int mt = 0; mt < 4; mt++)
#pragma unroll
        for (int nt = 0; nt < 4; nt++)
#pragma unroll
            for (int e = 0; e < 4; e++) acc[mt][nt][e] = 0.f;

    int a_r = (lid & 15);
    int a_h = (lid >> 4);
    int b_n = ((lid >> 4) << 3) + (lid & 7);
    int b_h = ((lid >> 3) & 1);

    int a_row = tid >> 2, a_ch = tid & 3;     // 512 threads -> 128 rows x 4 chunks
    int b_row[2], b_ch[2];                     // 256 rows x 4 chunks, 2 per thread
#pragma unroll
    for (int i = 0; i < 2; i++) {
        int c = tid + i * 512;
        b_row[i] = c >> 2;
        b_ch[i] = c & 3;
    }

#define GEMM_ISSUE(stage, k0)                                                  \
    do {                                                                       \
        u32 base_ = sb + (stage) * GSTG;                                       \
        {                                                                      \
            u32 so = SWZ64((u32)(a_row * 64 + a_ch * 16));                     \
            size_t ga = (size_t)(bm + a_row) * K + (k0) + a_ch * 8;            \
            cp16(base_ + so, Ah + ga);                                         \
            cp16(base_ + 8192 + so, Al + ga);                                  \
        }                                                                      \
        _Pragma("unroll")                                                      \
        for (int i = 0; i < 2; i++) {                                          \
            u32 so = SWZ64((u32)(b_row[i] * 64 + b_ch[i] * 16));               \
            size_t gb = (size_t)(bn + b_row[i]) * K + (k0) + b_ch[i] * 8;      \
            cp16(base_ + 16384 + so, Bh + gb);                                 \
            cp16(base_ + 32768 + so, Bl + gb);                                 \
        }                                                                      \
        CP_COMMIT();                                                           \
    } while (0)

    int niter = K / BKC;
    GEMM_ISSUE(0, 0);
    GEMM_ISSUE(1, BKC);

    for (int it = 0; it < niter; it++) {
        if (it + 2 < niter) {
            int st = (it + 2) % 3;
            GEMM_ISSUE(st, (it + 2) * BKC);
            CP_WAIT(2);
        } else if (it + 1 < niter) {
            CP_WAIT(1);
        } else {
            CP_WAIT(0);
        }
        __syncthreads();

        u32 baseAh = sb + (it % 3) * GSTG;
        u32 baseAl = baseAh + 8192;
        u32 baseBh = baseAh + 16384;
        u32 baseBl = baseAh + 32768;

#pragma unroll
        for (int ks = 0; ks < 2; ks++) {
            u32 af[4][4], bhf[4][2], blf[4][2];
#pragma unroll
            for (int mt = 0; mt < 4; mt++) {
                int r = wm * 64 + mt * 16 + a_r;
                u32 addr = baseAh + SWZ64((u32)(r * 64 + (ks * 2 + a_h) * 16));
                ldsm_x4(af[mt][0], af[mt][1], af[mt][2], af[mt][3], addr);
            }
#pragma unroll
            for (int np = 0; np < 2; np++) {
                int n = wn * 32 + np * 16 + b_n;
                u32 off = SWZ64((u32)(n * 64 + (ks * 2 + b_h) * 16));
                ldsm_x4(bhf[np * 2][0], bhf[np * 2][1],
                        bhf[np * 2 + 1][0], bhf[np * 2 + 1][1], baseBh + off);
                ldsm_x4(blf[np * 2][0], blf[np * 2][1],
                        blf[np * 2 + 1][0], blf[np * 2 + 1][1], baseBl + off);
            }
#pragma unroll
            for (int mt = 0; mt < 4; mt++)
#pragma unroll
                for (int nt = 0; nt < 4; nt++)
                    mma_bf16(acc[mt][nt], af[mt], bhf[nt]);
#pragma unroll
            for (int mt = 0; mt < 4; mt++)
#pragma unroll
                for (int nt = 0; nt < 4; nt++)
                    mma_bf16(acc[mt][nt], af[mt], blf[nt]);
#pragma unroll
            for (int mt = 0; mt < 4; mt++) {
                int r = wm * 64 + mt * 16 + a_r;
                u32 addr = baseAl + SWZ64((u32)(r * 64 + (ks * 2 + a_h) * 16));
                ldsm_x4(af[mt][0], af[mt][1], af[mt][2], af[mt][3], addr);
            }
#pragma unroll
            for (int mt = 0; mt < 4; mt++)
#pragma unroll
                for (int nt = 0; nt < 4; nt++)
                    mma_bf16(acc[mt][nt], af[mt], bhf[nt]);
        }
        __syncthreads();
    }

    __nv_bfloat16* H = (mat == 0) ? H0 : (mat == 1) ? H1 : H2;
    __nv_bfloat16* L = (mat == 0) ? L0 : (mat == 1) ? L1 : L2;

    int rr = lid >> 2, cc2 = (lid & 3) * 2;
#pragma unroll
    for (int mt = 0; mt < 4; mt++) {
        int r0 = bm + wm * 64 + mt * 16 + rr;
#pragma unroll
        for (int nt = 0; nt < 4; nt++) {
            int col = bn + wn * 32 + nt * 8 + cc2;
            float bb0 = bias[col], bb1 = bias[col + 1];
            float v00 = acc[mt][nt][0] + bb0, v01 = acc[mt][nt][1] + bb1;
            float v10 = acc[mt][nt][2] + bb0, v11 = acc[mt][nt][3] + bb1;
            if (mat == 3) {
                *(float2*)&C[(size_t)r0 * N + col] = make_float2(v00, v01);
                *(float2*)&C[(size_t)(r0 + 8) * N + col] = make_float2(v10, v11);
            } else {
                u32 hi, lo;
                pack_hl(v00, v01, hi, lo);
                *(u32*)&H[(size_t)r0 * N + col] = hi;
                *(u32*)&L[(size_t)r0 * N + col] = lo;
                pack_hl(v10, v11, hi, lo);
                *(u32*)&H[(size_t)(r0 + 8) * N + col] = hi;
                *(u32*)&L[(size_t)(r0 + 8) * N + col] = lo;
            }
        }
    }
}

// ---------------------------------------------------------------------------
// Tensor-core causal flash attention (bf16 hi/lo, fp32 softmax),
// cp.async 2-stage K/V pipeline. Longest CTAs (large qb) launch first.
// RoPE mathematically eliminated (head-only rotation; q.k invariant).
// CTA: 128 q rows, 8 warps (warp = 16 q rows x full 64-col kv tile).
// ---------------------------------------------------------------------------
#define ABQ 128
#define ABK 64
#define OQH 0
#define OQL 16384
#define AKV 32768
#define ASTG 32768
#define ASMEM (AKV + 2 * ASTG)

__global__ __launch_bounds__(256)
void flash_attn_tc(const __nv_bfloat16* __restrict__ qh_,
                   const __nv_bfloat16* __restrict__ ql_,
                   const __nv_bfloat16* __restrict__ kh_,
                   const __nv_bfloat16* __restrict__ kl_,
                   const __nv_bfloat16* __restrict__ vth_,
                   const __nv_bfloat16* __restrict__ vtl_,
                   __nv_bfloat16* __restrict__ aoh,
                   __nv_bfloat16* __restrict__ aol)
{
    extern __shared__ char smc[];
    u32 sb = smem_u32(smc);
    int tid = threadIdx.x, wid = tid / 32, lid = tid % 32;
    int qb = gridDim.x - 1 - blockIdx.x;   // longest work first
    int h = blockIdx.y, b = blockIdx.z;
    int q0 = qb * ABQ;
    int warp_row = q0 + wid * 16;

    // Load Q tile (128x64 hi/lo), SW128 rows
#pragma unroll
    for (int i = 0; i < 4; i++) {
        int c = tid + i * 256;
        int r = c >> 3, ch = c & 7;
        u32 so = SWZ128((u32)(r * 128 + ch * 16));
        size_t g = (size_t)(b * SEQ + q0 + r) * EMB + h * HD + ch * 8;
        *(uint4*)(smc + OQH + so) = *(const uint4*)(qh_ + g);
        *(uint4*)(smc + OQL + so) = *(const uint4*)(ql_ + g);
    }

    int v_r[2], v_ch[2];
#pragma unroll
    for (int i = 0; i < 2; i++) {
        int c = tid + i * 256;
        v_r[i] = c >> 3;
        v_ch[i] = c & 7;
    }

#define ATTN_ISSUE(stage, kb)                                                  \
    do {                                                                       \
        u32 base_ = sb + AKV + (stage) * ASTG;                                 \
        _Pragma("unroll")                                                      \
        for (int i = 0; i < 2; i++) {                                          \
            int r = v_r[i], ch = v_ch[i];                                      \
            u32 so = SWZ128((u32)(r * 128 + ch * 16));                         \
            size_t gk = (size_t)(b * SEQ + (kb) * ABK + r) * EMB + h * HD + ch * 8; \
            size_t gv = ((size_t)((b * NH + h) * HD) + r) * SEQ + (kb) * ABK + ch * 8; \
            cp16(base_ + so, kh_ + gk);                                        \
            cp16(base_ + 8192 + so, kl_ + gk);                                 \
            cp16(base_ + 16384 + so, vth_ + gv);                               \
            cp16(base_ + 24576 + so, vtl_ + gv);                               \
        }                                                                      \
        CP_COMMIT();                                                           \
    } while (0)

    float m_i[2], l_i[2], o[8][4];
    m_i[0] = m_i[1] = -INFINITY;
    l_i[0] = l_i[1] = 0.f;
#pragma unroll
    for (int nt = 0; nt < 8; nt++)
#pragma unroll
        for (int e = 0; e < 4; e++) o[nt][e] = 0.f;

    const float scale = 0.125f;  // 1/sqrt(64)
    int r1 = lid >> 2;
    int a_r = lid & 15, a_h = lid >> 4;
    int b_n = ((lid >> 4) << 3) + (lid & 7), b_h = (lid >> 3) & 1;

    int nkb = 2 * qb + 2;
    ATTN_ISSUE(0, 0);

    for (int kb = 0; kb < nkb; kb++) {
        if (kb + 1 < nkb) {
            ATTN_ISSUE((kb + 1) & 1, kb + 1);
            CP_WAIT(1);
        } else {
            CP_WAIT(0);
        }
        __syncthreads();

        if (kb * ABK <= warp_row + 15) {   // not fully masked
            u32 bk = sb + AKV + (kb & 1) * ASTG;
            u32 okh = bk, okl = bk + 8192, ovh = bk + 16384, ovl = bk + 24576;

            // ---- S = Q K^T (hi/lo, 3 passes) ----
            float s[8][4];
#pragma unroll
            for (int nt = 0; nt < 8; nt++)
#pragma unroll
                for (int e = 0; e < 4; e++) s[nt][e] = 0.f;

#pragma unroll
            for (int kc = 0; kc < 4; kc++) {
                u32 af[4], bhf[8][2], blf[8][2];
                u32 arow = (u32)((wid * 16 + a_r) * 128 + (kc * 2 + a_h) * 16);
                ldsm_x4(af[0], af[1], af[2], af[3], sb + OQH + SWZ128(arow));
#pragma unroll
                for (int g = 0; g < 4; g++) {
                    int n = g * 16 + b_n;
                    u32 off = SWZ128((u32)(n * 128 + (kc * 2 + b_h) * 16));
                    ldsm_x4(bhf[g * 2][0], bhf[g * 2][1],
                            bhf[g * 2 + 1][0], bhf[g * 2 + 1][1], okh + off);
                    ldsm_x4(blf[g * 2][0], blf[g * 2][1],
                            blf[g * 2 + 1][0], blf[g * 2 + 1][1], okl + off);
                }
#pragma unroll
                for (int nt = 0; nt < 8; nt++) mma_bf16(s[nt], af, bhf[nt]);
#pragma unroll
                for (int nt = 0; nt < 8; nt++) mma_bf16(s[nt], af, blf[nt]);
                ldsm_x4(af[0], af[1], af[2], af[3], sb + OQL + SWZ128(arow));
#pragma unroll
                for (int nt = 0; nt < 8; nt++) mma_bf16(s[nt], af, bhf[nt]);
            }

            // ---- scale + causal mask ----
            bool needmask = (kb * ABK + ABK - 1 > warp_row);
#pragma unroll
            for (int nt = 0; nt < 8; nt++) {
#pragma unroll
                for (int e = 0; e < 4; e++) {
                    s[nt][e] *= scale;
                    if (needmask) {
                        int row = warp_row + r1 + ((e >> 1) << 3);
                        int col = kb * ABK + nt * 8 + (lid & 3) * 2 + (e & 1);
                        if (col > row) s[nt][e] = -INFINITY;
                    }
                }
            }

            // ---- online softmax (rows r1, r1+8) ----
#pragma unroll
            for (int half = 0; half < 2; half++) {
                float mx = -INFINITY;
#pragma unroll
                for (int nt = 0; nt < 8; nt++)
                    mx = fmaxf(mx, fmaxf(s[nt][half * 2], s[nt][half * 2 + 1]));
                mx = fmaxf(mx, __shfl_xor_sync(0xffffffffu, mx, 1));
                mx = fmaxf(mx, __shfl_xor_sync(0xffffffffu, mx, 2));
                float m_new = fmaxf(m_i[half], mx);
                float corr = __expf(m_i[half] - m_new);
                m_i[half] = m_new;
                float rs = 0.f;
#pragma unroll
                for (int nt = 0; nt < 8; nt++) {
                    float p0 = __expf(s[nt][half * 2] - m_new);
                    float p1 = __expf(s[nt][half * 2 + 1] - m_new);
                    s[nt][half * 2] = p0;
                    s[nt][half * 2 + 1] = p1;
                    rs += p0 + p1;
                }
                rs += __shfl_xor_sync(0xffffffffu, rs, 1);
                rs += __shfl_xor_sync(0xffffffffu, rs, 2);
                l_i[half] = l_i[half] * corr + rs;
#pragma unroll
                for (int nt = 0; nt < 8; nt++) {
                    o[nt][half * 2] *= corr;
                    o[nt][half * 2 + 1] *= corr;
                }
            }

            // ---- O += P V (hi/lo, 3 passes); P repacked in-register ----
#pragma unroll
            for (int kc = 0; kc < 4; kc++) {
                u32 ph[4], pl[4];
                pack_hl(s[2 * kc][0], s[2 * kc][1], ph[0], pl[0]);
                pack_hl(s[2 * kc][2], s[2 * kc][3], ph[1], pl[1]);
                pack_hl(s[2 * kc + 1][0], s[2 * kc + 1][1], ph[2], pl[2]);
                pack_hl(s[2 * kc + 1][2], s[2 * kc + 1][3], ph[3], pl[3]);

                u32 bvh[8][2], bvl[8][2];
#pragma unroll
                for (int g = 0; g < 4; g++) {
                    int n = g * 16 + b_n;
                    u32 off = SWZ128((u32)(n * 128 + (kc * 2 + b_h) * 16));
                    ldsm_x4(bvh[g * 2][0], bvh[g * 2][1],
                            bvh[g * 2 + 1][0], bvh[g * 2 + 1][1], ovh + off);
                    ldsm_x4(bvl[g * 2][0], bvl[g * 2][1],
                            bvl[g * 2 + 1][0], bvl[g * 2 + 1][1], ovl + off);
                }
#pragma unroll
                for (int nt = 0; nt < 8; nt++) mma_bf16(o[nt], ph, bvh[nt]);
#pragma unroll
                for (int nt = 0; nt < 8; nt++) mma_bf16(o[nt], ph, bvl[nt]);
#pragma unroll
                for (int nt = 0; nt < 8; nt++) mma_bf16(o[nt], pl, bvh[nt]);
            }
        }
        __syncthreads();
    }

    // ---- epilogue: normalize, split to hi/lo bf16, store ----
#pragma unroll
    for (int half = 0; half < 2; half++) {
        float inv = 1.f / l_i[half];
        int row = warp_row + r1 + half * 8;
        size_t base = (size_t)(b * SEQ + row) * EMB + h * HD;
#pragma unroll
        for (int nt = 0; nt < 8; nt++) {
            int col = nt * 8 + (lid & 3) * 2;
            float v0 = o[nt][half * 2] * inv;
            float v1 = o[nt][half * 2 + 1] * inv;
            u32 hi, lo;
            pack_hl(v0, v1, hi, lo);
            *(u32*)&aoh[base + col] = hi;
            *(u32*)&aol[base + col] = lo;
        }
    }
}

// ---------------------------------------------------------------------------
// Launch
// ---------------------------------------------------------------------------
extern "C" void kernel_launch(void* const* d_in, const int* in_sizes, int n_in,
                              void* d_out, int out_size)
{
    const float* x  = (const float*)d_in[0];
    const float* Wq = (const float*)d_in[1];
    const float* bq = (const float*)d_in[2];
    const float* Wk = (const float*)d_in[3];
    const float* bk = (const float*)d_in[4];
    const float* Wv = (const float*)d_in[5];
    const float* bv = (const float*)d_in[6];
    const float* Wo = (const float*)d_in[7];
    const float* bo = (const float*)d_in[8];
    float* out = (float*)d_out;

    __nv_bfloat16 *ah, *al, *bh, *bl, *qh, *ql, *kh, *kl, *vh, *vl, *vth, *vtl;
    cudaGetSymbolAddress((void**)&ah, g_ah);
    cudaGetSymbolAddress((void**)&al, g_al);
    cudaGetSymbolAddress((void**)&bh, g_bh);
    cudaGetSymbolAddress((void**)&bl, g_bl);
    cudaGetSymbolAddress((void**)&qh, g_qh);
    cudaGetSymbolAddress((void**)&ql, g_ql);
    cudaGetSymbolAddress((void**)&kh, g_kh);
    cudaGetSymbolAddress((void**)&kl, g_kl);
    cudaGetSymbolAddress((void**)&vh, g_vh);
    cudaGetSymbolAddress((void**)&vl, g_vl);
    cudaGetSymbolAddress((void**)&vth, g_vth);
    cudaGetSymbolAddress((void**)&vtl, g_vtl);

    cudaFuncSetAttribute(gemm_mma,
                         cudaFuncAttributeMaxDynamicSharedMemorySize, GSMEM);
    cudaFuncSetAttribute(flash_attn_tc,
                         cudaFuncAttributeMaxDynamicSharedMemorySize, ASMEM);

    dim3 ct(32, 8);
    dim3 cg4(EMB / 32, EMB / 32, 4);
    int n4 = MROWS * EMB / 4;
    dim3 qkvgrid(3 * EMB / 256, MROWS / 128);   // (24, 32): fused Q,K,V
    dim3 ogrid(EMB / 256, MROWS / 128);         // (8, 32): out proj
    dim3 vtgrid(SEQ / 32, BSZ * NH * 2);
    dim3 agrid(SEQ / ABQ, NH, BSZ);             // (16, 32, 2)

    // split x; convert all 4 weights
    conv_rows<<<(n4 + 255) / 256, 256>>>(x, ah, al, n4);
    conv_T4<<<cg4, ct>>>(Wq, Wk, Wv, Wo, bh, bl);

    // fused QKV projection -> bf16 hi/lo
    gemm_mma<<<qkvgrid, 512, GSMEM>>>(ah, al, bh, bl, bq, bk, bv, bo,
                                      qh, ql, kh, kl, vh, vl, NULL, 0,
                                      MROWS, EMB);
    conv_vt<<<vtgrid, ct>>>(vh, vl, vth, vtl);

    // attention -> hi/lo into ah/al (x-split no longer needed)
    flash_attn_tc<<<agrid, 256, ASMEM>>>(qh, ql, kh, kl, vth, vtl, ah, al);

    // output projection (mat 3, fp32 out)
    gemm_mma<<<ogrid, 512, GSMEM>>>(ah, al, bh, bl, bq, bk, bv, bo,
                                    qh, ql, kh, kl, vh, vl, out, 3,
                                    MROWS, EMB);
}

// round 10
// speedup vs baseline: 1.1289x; 1.1289x over previous
#include <cuda_runtime.h>
#include <cuda_bf16.h>
#include <cstdint>
#include <math.h>

typedef unsigned int u32;
typedef unsigned long long u64;
typedef unsigned short u16;

#define BSZ 2
#define SEQ 2048
#define EMB 2048
#define NH 32
#define HD 64
#define MROWS (BSZ*SEQ)

// ---------------------------------------------------------------------------
// Scratch (device globals: allocation-free per harness rules)
// ---------------------------------------------------------------------------
__device__ __align__(16) __nv_bfloat16 g_ah[(size_t)MROWS * EMB];
__device__ __align__(16) __nv_bfloat16 g_al[(size_t)MROWS * EMB];
__device__ __align__(16) __nv_bfloat16 g_bh[(size_t)4 * EMB * EMB];  // W^T hi x4
__device__ __align__(16) __nv_bfloat16 g_bl[(size_t)4 * EMB * EMB];  // W^T lo x4
__device__ __align__(16) __nv_bfloat16 g_qh[(size_t)MROWS * EMB];
__device__ __align__(16) __nv_bfloat16 g_ql[(size_t)MROWS * EMB];
__device__ __align__(16) __nv_bfloat16 g_kh[(size_t)MROWS * EMB];
__device__ __align__(16) __nv_bfloat16 g_kl[(size_t)MROWS * EMB];
__device__ __align__(16) __nv_bfloat16 g_vh[(size_t)MROWS * EMB];
__device__ __align__(16) __nv_bfloat16 g_vl[(size_t)MROWS * EMB];

// ---------------------------------------------------------------------------
// Warp-MMA / cp.async helpers (baseline PTX: works on plain sm_103 target)
// ---------------------------------------------------------------------------
__device__ __forceinline__ u32 smem_u32(const void* p) {
    u32 a;
    asm("{ .reg .u64 t; cvta.to.shared.u64 t, %1; cvt.u32.u64 %0, t; }"
        : "=r"(a) : "l"(p));
    return a;
}
__device__ __forceinline__ void ldsm_x4(u32& r0, u32& r1, u32& r2, u32& r3,
                                        u32 addr) {
    asm volatile("ldmatrix.sync.aligned.m8n8.x4.shared.b16 {%0,%1,%2,%3}, [%4];"
                 : "=r"(r0), "=r"(r1), "=r"(r2), "=r"(r3) : "r"(addr));
}
__device__ __forceinline__ void ldsm_x4t(u32& r0, u32& r1, u32& r2, u32& r3,
                                         u32 addr) {
    asm volatile("ldmatrix.sync.aligned.m8n8.x4.trans.shared.b16 {%0,%1,%2,%3}, [%4];"
                 : "=r"(r0), "=r"(r1), "=r"(r2), "=r"(r3) : "r"(addr));
}
__device__ __forceinline__ void mma_bf16(float* d, const u32* a, const u32* b) {
    asm volatile(
        "mma.sync.aligned.m16n8k16.row.col.f32.bf16.bf16.f32 "
        "{%0,%1,%2,%3}, {%4,%5,%6,%7}, {%8,%9}, {%0,%1,%2,%3};"
        : "+f"(d[0]), "+f"(d[1]), "+f"(d[2]), "+f"(d[3])
        : "r"(a[0]), "r"(a[1]), "r"(a[2]), "r"(a[3]), "r"(b[0]), "r"(b[1]));
}
__device__ __forceinline__ void cp16(u32 dst, const void* src) {
    asm volatile("cp.async.cg.shared.global [%0], [%1], 16;"
                 :: "r"(dst), "l"(src) : "memory");
}
#define CP_COMMIT() asm volatile("cp.async.commit_group;" ::: "memory")
#define CP_WAIT(n)  asm volatile("cp.async.wait_group %0;" :: "n"(n) : "memory")

// pack two fp32 -> bf16x2 (lo = x0), plus bf16x2 of the residuals
__device__ __forceinline__ void pack_hl(float x0, float x1, u32& hi, u32& lo) {
    asm("cvt.rn.bf16x2.f32 %0, %1, %2;" : "=r"(hi) : "f"(x1), "f"(x0));
    float h0 = __uint_as_float(hi << 16);
    float h1 = __uint_as_float(hi & 0xFFFF0000u);
    float r0 = x0 - h0, r1 = x1 - h1;
    asm("cvt.rn.bf16x2.f32 %0, %1, %2;" : "=r"(lo) : "f"(r1), "f"(r0));
}
#define SWZ64(o)  ((o) ^ (((o) >> 3) & 0x30))
#define SWZ128(o) ((o) ^ (((o) >> 3) & 0x70))

// ---------------------------------------------------------------------------
// Conversion kernels
// ---------------------------------------------------------------------------
__global__ void conv_rows(const float* __restrict__ X,
                          __nv_bfloat16* __restrict__ H,
                          __nv_bfloat16* __restrict__ L, int n4)
{
    int i = blockIdx.x * blockDim.x + threadIdx.x;
    if (i >= n4) return;
    float4 v = ((const float4*)X)[i];
    u32 h0, l0, h1, l1;
    pack_hl(v.x, v.y, h0, l0);
    pack_hl(v.z, v.w, h1, l1);
    ((uint2*)H)[i] = make_uint2(h0, h1);
    ((uint2*)L)[i] = make_uint2(l0, l1);
}

// All 4 weights W[K,N] fp32 -> W^T hi/lo bf16 [N,K], one launch (z selects W)
__global__ void conv_T4(const float* __restrict__ W0, const float* __restrict__ W1,
                        const float* __restrict__ W2, const float* __restrict__ W3,
                        __nv_bfloat16* __restrict__ Th,
                        __nv_bfloat16* __restrict__ Tl)
{
    __shared__ float t[32][33];
    int z = blockIdx.z;
    const float* W = (z == 0) ? W0 : (z == 1) ? W1 : (z == 2) ? W2 : W3;
    size_t zo = (size_t)z * EMB * EMB;
    int n0 = blockIdx.x * 32, k0 = blockIdx.y * 32;
    int x = threadIdx.x, y = threadIdx.y;  // 32 x 8
#pragma unroll
    for (int r = 0; r < 32; r += 8)
        t[y + r][x] = W[(size_t)(k0 + y + r) * EMB + n0 + x];
    __syncthreads();
#pragma unroll
    for (int r = 0; r < 32; r += 8) {
        float v = t[x][y + r];
        __nv_bfloat16 h = __float2bfloat16(v);
        size_t o = zo + (size_t)(n0 + y + r) * EMB + k0 + x;
        Th[o] = h;
        Tl[o] = __float2bfloat16(v - __bfloat162float(h));
    }
}

// ---------------------------------------------------------------------------
// Tensor-core GEMM via mma.sync (bf16 hi/lo split, fp32 accumulate),
// cp.async 3-stage pipeline. ROUND-8 SHAPE (proven best): 128x128 tile,
// 256 threads, 2 CTAs/SM. mats 0,1,2 -> bf16 hi/lo (Q,K,V); mat 3 -> fp32 C.
// Stage layout (32 KB): AH 0, AL 8192, BH 16384, BL 24576.
// ---------------------------------------------------------------------------
#define BKC 32
#define GSTG 32768
#define GSMEM (3 * GSTG)

__global__ __launch_bounds__(256, 2)
void gemm_mma(const __nv_bfloat16* __restrict__ Ah,
              const __nv_bfloat16* __restrict__ Al,
              const __nv_bfloat16* __restrict__ BhAll,
              const __nv_bfloat16* __restrict__ BlAll,
              const float* __restrict__ b0, const float* __restrict__ b1,
              const float* __restrict__ b2, const float* __restrict__ b3,
              __nv_bfloat16* __restrict__ H0, __nv_bfloat16* __restrict__ L0,
              __nv_bfloat16* __restrict__ H1, __nv_bfloat16* __restrict__ L1,
              __nv_bfloat16* __restrict__ H2, __nv_bfloat16* __restrict__ L2,
              float* __restrict__ C, int mat_base, int M, int K)
{
    extern __shared__ char smg[];
    u32 sb = smem_u32(smg);
    const int N = EMB;

    int tid = threadIdx.x;
    int wid = tid / 32, lid = tid % 32;
    int wm = wid / 4, wn = wid % 4;        // warp grid 2 x 4
    int mat = mat_base + (blockIdx.x >> 4);
    int bm = blockIdx.y * 128, bn = (blockIdx.x & 15) * 128;

    const __nv_bfloat16* Bh = BhAll + (size_t)mat * EMB * EMB;
    const __nv_bfloat16* Bl = BlAll + (size_t)mat * EMB * EMB;
    const float* bias = (mat == 0) ? b0 : (mat == 1) ? b1 : (mat == 2) ? b2 : b3;

    float acc[4][4][4];
#pragma unroll
    for (int mt = 0; mt < 4; mt++)
#pragma unroll
        for (int nt = 0; nt < 4; nt++)
#pragma unroll
            for (int e = 0; e < 4; e++) acc[mt][nt][e] = 0.f;

    int a_r = (lid & 15);
    int a_h = (lid >> 4);
    int b_n = ((lid >> 4) << 3) + (lid & 7);
    int b_h = ((lid >> 3) & 1);

    int l_row[2], l_ch[2];
#pragma unroll
    for (int cc = 0; cc < 2; cc++) {
        int c = tid + cc * 256;
        l_row[cc] = c >> 2;
        l_ch[cc] = c & 3;
    }

#define GEMM_ISSUE(stage, k0)                                                  \
    do {                                                                       \
        u32 base_ = sb + (stage) * GSTG;                                       \
        _Pragma("unroll")                                                      \
        for (int cc = 0; cc < 2; cc++) {                                       \
            int row = l_row[cc], ch = l_ch[cc];                                \
            u32 so = SWZ64((u32)(row * 64 + ch * 16));                         \
            size_t ga = (size_t)(bm + row) * K + (k0) + ch * 8;                \
            size_t gb = (size_t)(bn + row) * K + (k0) + ch * 8;                \
            cp16(base_ + so, Ah + ga);                                         \
            cp16(base_ + 8192 + so, Al + ga);                                  \
            cp16(base_ + 16384 + so, Bh + gb);                                 \
            cp16(base_ + 24576 + so, Bl + gb);                                 \
        }                                                                      \
        CP_COMMIT();                                                           \
    } while (0)

    int niter = K / BKC;
    GEMM_ISSUE(0, 0);
    GEMM_ISSUE(1, BKC);

    for (int it = 0; it < niter; it++) {
        if (it + 2 < niter) {
            int st = (it + 2) % 3;
            GEMM_ISSUE(st, (it + 2) * BKC);
            CP_WAIT(2);
        } else if (it + 1 < niter) {
            CP_WAIT(1);
        } else {
            CP_WAIT(0);
        }
        __syncthreads();

        u32 baseAh = sb + (it % 3) * GSTG;
        u32 baseAl = baseAh + 8192;
        u32 baseBh = baseAh + 16384;
        u32 baseBl = baseAh + 24576;

#pragma unroll
        for (int ks = 0; ks < 2; ks++) {
            u32 af[4][4], bhf[4][2], blf[4][2];
#pragma unroll
            for (int mt = 0; mt < 4; mt++) {
                int r = wm * 64 + mt * 16 + a_r;
                u32 addr = baseAh + SWZ64((u32)(r * 64 + (ks * 2 + a_h) * 16));
                ldsm_x4(af[mt][0], af[mt][1], af[mt][2], af[mt][3], addr);
            }
#pragma unroll
            for (int np = 0; np < 2; np++) {
                int n = wn * 32 + np * 16 + b_n;
                u32 off = SWZ64((u32)(n * 64 + (ks * 2 + b_h) * 16));
                ldsm_x4(bhf[np * 2][0], bhf[np * 2][1],
                        bhf[np * 2 + 1][0], bhf[np * 2 + 1][1], baseBh + off);
                ldsm_x4(blf[np * 2][0], blf[np * 2][1],
                        blf[np * 2 + 1][0], blf[np * 2 + 1][1], baseBl + off);
            }
#pragma unroll
            for (int mt = 0; mt < 4; mt++)
#pragma unroll
                for (int nt = 0; nt < 4; nt++)
                    mma_bf16(acc[mt][nt], af[mt], bhf[nt]);
#pragma unroll
            for (int mt = 0; mt < 4; mt++)
#pragma unroll
                for (int nt = 0; nt < 4; nt++)
                    mma_bf16(acc[mt][nt], af[mt], blf[nt]);
#pragma unroll
            for (int mt = 0; mt < 4; mt++) {
                int r = wm * 64 + mt * 16 + a_r;
                u32 addr = baseAl + SWZ64((u32)(r * 64 + (ks * 2 + a_h) * 16));
                ldsm_x4(af[mt][0], af[mt][1], af[mt][2], af[mt][3], addr);
            }
#pragma unroll
            for (int mt = 0; mt < 4; mt++)
#pragma unroll
                for (int nt = 0; nt < 4; nt++)
                    mma_bf16(acc[mt][nt], af[mt], bhf[nt]);
        }
        __syncthreads();
    }

    __nv_bfloat16* H = (mat == 0) ? H0 : (mat == 1) ? H1 : H2;
    __nv_bfloat16* L = (mat == 0) ? L0 : (mat == 1) ? L1 : L2;

    int rr = lid >> 2, cc2 = (lid & 3) * 2;
#pragma unroll
    for (int mt = 0; mt < 4; mt++) {
        int r0 = bm + wm * 64 + mt * 16 + rr;
#pragma unroll
        for (int nt = 0; nt < 4; nt++) {
            int col = bn + wn * 32 + nt * 8 + cc2;
            float bb0 = bias[col], bb1 = bias[col + 1];
            float v00 = acc[mt][nt][0] + bb0, v01 = acc[mt][nt][1] + bb1;
            float v10 = acc[mt][nt][2] + bb0, v11 = acc[mt][nt][3] + bb1;
            if (mat == 3) {
                *(float2*)&C[(size_t)r0 * N + col] = make_float2(v00, v01);
                *(float2*)&C[(size_t)(r0 + 8) * N + col] = make_float2(v10, v11);
            } else {
                u32 hi, lo;
                pack_hl(v00, v01, hi, lo);
                *(u32*)&H[(size_t)r0 * N + col] = hi;
                *(u32*)&L[(size_t)r0 * N + col] = lo;
                pack_hl(v10, v11, hi, lo);
                *(u32*)&H[(size_t)(r0 + 8) * N + col] = hi;
                *(u32*)&L[(size_t)(r0 + 8) * N + col] = lo;
            }
        }
    }
}

// ---------------------------------------------------------------------------
// Tensor-core causal flash attention (bf16 hi/lo, fp32 softmax),
// cp.async 2-stage K/V pipeline. V kept row-major [kv][d] in smem; PV's
// B-fragments come from ldmatrix.trans -> no V^T conversion pass needed.
// RoPE mathematically eliminated (head-only rotation; q.k invariant).
// CTA: 128 q rows, 8 warps (warp = 16 q rows x full 64-col kv tile).
// ---------------------------------------------------------------------------
#define ABQ 128
#define ABK 64
#define OQH 0
#define OQL 16384
#define AKV 32768
#define ASTG 32768
#define ASMEM (AKV + 2 * ASTG)

__global__ __launch_bounds__(256)
void flash_attn_tc(const __nv_bfloat16* __restrict__ qh_,
                   const __nv_bfloat16* __restrict__ ql_,
                   const __nv_bfloat16* __restrict__ kh_,
                   const __nv_bfloat16* __restrict__ kl_,
                   const __nv_bfloat16* __restrict__ vh_,
                   const __nv_bfloat16* __restrict__ vl_,
                   __nv_bfloat16* __restrict__ aoh,
                   __nv_bfloat16* __restrict__ aol)
{
    extern __shared__ char smc[];
    u32 sb = smem_u32(smc);
    int tid = threadIdx.x, wid = tid / 32, lid = tid % 32;
    int qb = gridDim.x - 1 - blockIdx.x;   // longest work first
    int h = blockIdx.y, b = blockIdx.z;
    int q0 = qb * ABQ;
    int warp_row = q0 + wid * 16;

    // Load Q tile (128x64 hi/lo), SW128 rows
#pragma unroll
    for (int i = 0; i < 4; i++) {
        int c = tid + i * 256;
        int r = c >> 3, ch = c & 7;
        u32 so = SWZ128((u32)(r * 128 + ch * 16));
        size_t g = (size_t)(b * SEQ + q0 + r) * EMB + h * HD + ch * 8;
        *(uint4*)(smc + OQH + so) = *(const uint4*)(qh_ + g);
        *(uint4*)(smc + OQL + so) = *(const uint4*)(ql_ + g);
    }

    int v_r[2], v_ch[2];
#pragma unroll
    for (int i = 0; i < 2; i++) {
        int c = tid + i * 256;
        v_r[i] = c >> 3;
        v_ch[i] = c & 7;
    }

// K and V now use the SAME row-major [kv][d] addressing (gk pattern)
#define ATTN_ISSUE(stage, kb)                                                  \
    do {                                                                       \
        u32 base_ = sb + AKV + (stage) * ASTG;                                 \
        _Pragma("unroll")                                                      \
        for (int i = 0; i < 2; i++) {                                          \
            int r = v_r[i], ch = v_ch[i];                                      \
            u32 so = SWZ128((u32)(r * 128 + ch * 16));                         \
            size_t gk = (size_t)(b * SEQ + (kb) * ABK + r) * EMB + h * HD + ch * 8; \
            cp16(base_ + so, kh_ + gk);                                        \
            cp16(base_ + 8192 + so, kl_ + gk);                                 \
            cp16(base_ + 16384 + so, vh_ + gk);                                \
            cp16(base_ + 24576 + so, vl_ + gk);                                \
        }                                                                      \
        CP_COMMIT();                                                           \
    } while (0)

    float m_i[2], l_i[2], o[8][4];
    m_i[0] = m_i[1] = -INFINITY;
    l_i[0] = l_i[1] = 0.f;
#pragma unroll
    for (int nt = 0; nt < 8; nt++)
#pragma unroll
        for (int e = 0; e < 4; e++) o[nt][e] = 0.f;

    const float scale = 0.125f;  // 1/sqrt(64)
    int r1 = lid >> 2;
    int a_r = lid & 15, a_h = lid >> 4;
    int b_n = ((lid >> 4) << 3) + (lid & 7), b_h = (lid >> 3) & 1;
    // trans-ldmatrix lane decomposition for V (rows = kv, cols = d)
    int t_r16 = (lid & 7) + ((lid >> 3) & 1) * 8;   // kv offset within 16
    int t_cb  = ((lid >> 4) & 1) * 16;              // d byte offset (8 cols)

    int nkb = 2 * qb + 2;
    ATTN_ISSUE(0, 0);

    for (int kb = 0; kb < nkb; kb++) {
        if (kb + 1 < nkb) {
            ATTN_ISSUE((kb + 1) & 1, kb + 1);
            CP_WAIT(1);
        } else {
            CP_WAIT(0);
        }
        __syncthreads();

        if (kb * ABK <= warp_row + 15) {   // not fully masked
            u32 bk = sb + AKV + (kb & 1) * ASTG;
            u32 okh = bk, okl = bk + 8192, ovh = bk + 16384, ovl = bk + 24576;

            // ---- S = Q K^T (hi/lo, 3 passes) ----
            float s[8][4];
#pragma unroll
            for (int nt = 0; nt < 8; nt++)
#pragma unroll
                for (int e = 0; e < 4; e++) s[nt][e] = 0.f;

#pragma unroll
            for (int kc = 0; kc < 4; kc++) {
                u32 af[4], bhf[8][2], blf[8][2];
                u32 arow = (u32)((wid * 16 + a_r) * 128 + (kc * 2 + a_h) * 16);
                ldsm_x4(af[0], af[1], af[2], af[3], sb + OQH + SWZ128(arow));
#pragma unroll
                for (int g = 0; g < 4; g++) {
                    int n = g * 16 + b_n;
                    u32 off = SWZ128((u32)(n * 128 + (kc * 2 + b_h) * 16));
                    ldsm_x4(bhf[g * 2][0], bhf[g * 2][1],
                            bhf[g * 2 + 1][0], bhf[g * 2 + 1][1], okh + off);
                    ldsm_x4(blf[g * 2][0], blf[g * 2][1],
                            blf[g * 2 + 1][0], blf[g * 2 + 1][1], okl + off);
                }
#pragma unroll
                for (int nt = 0; nt < 8; nt++) mma_bf16(s[nt], af, bhf[nt]);
#pragma unroll
                for (int nt = 0; nt < 8; nt++) mma_bf16(s[nt], af, blf[nt]);
                ldsm_x4(af[0], af[1], af[2], af[3], sb + OQL + SWZ128(arow));
#pragma unroll
                for (int nt = 0; nt < 8; nt++) mma_bf16(s[nt], af, bhf[nt]);
            }

            // ---- scale + causal mask ----
            bool needmask = (kb * ABK + ABK - 1 > warp_row);
#pragma unroll
            for (int nt = 0; nt < 8; nt++) {
#pragma unroll
                for (int e = 0; e < 4; e++) {
                    s[nt][e] *= scale;
                    if (needmask) {
                        int row = warp_row + r1 + ((e >> 1) << 3);
                        int col = kb * ABK + nt * 8 + (lid & 3) * 2 + (e & 1);
                        if (col > row) s[nt][e] = -INFINITY;
                    }
                }
            }

            // ---- online softmax (rows r1, r1+8) ----
#pragma unroll
            for (int half = 0; half < 2; half++) {
                float mx = -INFINITY;
#pragma unroll
                for (int nt = 0; nt < 8; nt++)
                    mx = fmaxf(mx, fmaxf(s[nt][half * 2], s[nt][half * 2 + 1]));
                mx = fmaxf(mx, __shfl_xor_sync(0xffffffffu, mx, 1));
                mx = fmaxf(mx, __shfl_xor_sync(0xffffffffu, mx, 2));
                float m_new = fmaxf(m_i[half], mx);
                float corr = __expf(m_i[half] - m_new);
                m_i[half] = m_new;
                float rs = 0.f;
#pragma unroll
                for (int nt = 0; nt < 8; nt++) {
                    float p0 = __expf(s[nt][half * 2] - m_new);
                    float p1 = __expf(s[nt][half * 2 + 1] - m_new);
                    s[nt][half * 2] = p0;
                    s[nt][half * 2 + 1] = p1;
                    rs += p0 + p1;
                }
                rs += __shfl_xor_sync(0xffffffffu, rs, 1);
                rs += __shfl_xor_sync(0xffffffffu, rs, 2);
                l_i[half] = l_i[half] * corr + rs;
#pragma unroll
                for (int nt = 0; nt < 8; nt++) {
                    o[nt][half * 2] *= corr;
                    o[nt][half * 2 + 1] *= corr;
                }
            }

            // ---- O += P V (hi/lo, 3 passes); V fragments via ldmatrix.trans
            //      from row-major [kv][d] tile (matrix order kv-lo/kv-hi x
            //      d-lo/d-hi matches {b0,b1} of adjacent n-tiles) ----
#pragma unroll
            for (int kc = 0; kc < 4; kc++) {
                u32 ph[4], pl[4];
                pack_hl(s[2 * kc][0], s[2 * kc][1], ph[0], pl[0]);
                pack_hl(s[2 * kc][2], s[2 * kc][3], ph[1], pl[1]);
                pack_hl(s[2 * kc + 1][0], s[2 * kc + 1][1], ph[2], pl[2]);
                pack_hl(s[2 * kc + 1][2], s[2 * kc + 1][3], ph[3], pl[3]);

                u32 bvh[8][2], bvl[8][2];
                u32 trow = (u32)((kc * 16 + t_r16) * 128);
#pragma unroll
                for (int g = 0; g < 4; g++) {
                    u32 off = SWZ128(trow + g * 32 + t_cb);
                    ldsm_x4t(bvh[g * 2][0], bvh[g * 2][1],
                             bvh[g * 2 + 1][0], bvh[g * 2 + 1][1], ovh + off);
                    ldsm_x4t(bvl[g * 2][0], bvl[g * 2][1],
                             bvl[g * 2 + 1][0], bvl[g * 2 + 1][1], ovl + off);
                }
#pragma unroll
                for (int nt = 0; nt < 8; nt++) mma_bf16(o[nt], ph, bvh[nt]);
#pragma unroll
                for (int nt = 0; nt < 8; nt++) mma_bf16(o[nt], ph, bvl[nt]);
#pragma unroll
                for (int nt = 0; nt < 8; nt++) mma_bf16(o[nt], pl, bvh[nt]);
            }
        }
        __syncthreads();
    }

    // ---- epilogue: normalize, split to hi/lo bf16, store ----
#pragma unroll
    for (int half = 0; half < 2; half++) {
        float inv = 1.f / l_i[half];
        int row = warp_row + r1 + half * 8;
        size_t base = (size_t)(b * SEQ + row) * EMB + h * HD;
#pragma unroll
        for (int nt = 0; nt < 8; nt++) {
            int col = nt * 8 + (lid & 3) * 2;
            float v0 = o[nt][half * 2] * inv;
            float v1 = o[nt][half * 2 + 1] * inv;
            u32 hi, lo;
            pack_hl(v0, v1, hi, lo);
            *(u32*)&aoh[base + col] = hi;
            *(u32*)&aol[base + col] = lo;
        }
    }
}

// ---------------------------------------------------------------------------
// Launch
// ---------------------------------------------------------------------------
extern "C" void kernel_launch(void* const* d_in, const int* in_sizes, int n_in,
                              void* d_out, int out_size)
{
    const float* x  = (const float*)d_in[0];
    const float* Wq = (const float*)d_in[1];
    const float* bq = (const float*)d_in[2];
    const float* Wk = (const float*)d_in[3];
    const float* bk = (const float*)d_in[4];
    const float* Wv = (const float*)d_in[5];
    const float* bv = (const float*)d_in[6];
    const float* Wo = (const float*)d_in[7];
    const float* bo = (const float*)d_in[8];
    float* out = (float*)d_out;

    __nv_bfloat16 *ah, *al, *bh, *bl, *qh, *ql, *kh, *kl, *vh, *vl;
    cudaGetSymbolAddress((void**)&ah, g_ah);
    cudaGetSymbolAddress((void**)&al, g_al);
    cudaGetSymbolAddress((void**)&bh, g_bh);
    cudaGetSymbolAddress((void**)&bl, g_bl);
    cudaGetSymbolAddress((void**)&qh, g_qh);
    cudaGetSymbolAddress((void**)&ql, g_ql);
    cudaGetSymbolAddress((void**)&kh, g_kh);
    cudaGetSymbolAddress((void**)&kl, g_kl);
    cudaGetSymbolAddress((void**)&vh, g_vh);
    cudaGetSymbolAddress((void**)&vl, g_vl);

    cudaFuncSetAttribute(gemm_mma,
                         cudaFuncAttributeMaxDynamicSharedMemorySize, GSMEM);
    cudaFuncSetAttribute(flash_attn_tc,
                         cudaFuncAttributeMaxDynamicSharedMemorySize, ASMEM);

    dim3 ct(32, 8);
    dim3 cg4(EMB / 32, EMB / 32, 4);
    int n4 = MROWS * EMB / 4;
    dim3 qkvgrid(3 * EMB / 128, MROWS / 128);   // (48, 32): fused Q,K,V
    dim3 ogrid(EMB / 128, MROWS / 128);         // (16, 32): out proj
    dim3 agrid(SEQ / ABQ, NH, BSZ);             // (16, 32, 2)

    // split x; convert all 4 weights
    conv_rows<<<(n4 + 255) / 256, 256>>>(x, ah, al, n4);
    conv_T4<<<cg4, ct>>>(Wq, Wk, Wv, Wo, bh, bl);

    // fused QKV projection -> bf16 hi/lo
    gemm_mma<<<qkvgrid, 256, GSMEM>>>(ah, al, bh, bl, bq, bk, bv, bo,
                                      qh, ql, kh, kl, vh, vl, NULL, 0,
                                      MROWS, EMB);

    // attention -> hi/lo into ah/al (x-split no longer needed); V read directly
    flash_attn_tc<<<agrid, 256, ASMEM>>>(qh, ql, kh, kl, vh, vl, ah, al);

    // output projection (mat 3, fp32 out)
    gemm_mma<<<ogrid, 256, GSMEM>>>(ah, al, bh, bl, bq, bk, bv, bo,
                                    qh, ql, kh, kl, vh, vl, out, 3,
                                    MROWS, EMB);
}

// round 11
// speedup vs baseline: 1.1358x; 1.0061x over previous
#include <cuda_runtime.h>
#include <cuda_bf16.h>
#include <cstdint>
#include <math.h>

typedef unsigned int u32;
typedef unsigned long long u64;
typedef unsigned short u16;

#define BSZ 2
#define SEQ 2048
#define EMB 2048
#define NH 32
#define HD 64
#define MROWS (BSZ*SEQ)

// ---------------------------------------------------------------------------
// Scratch (device globals: allocation-free per harness rules)
// ---------------------------------------------------------------------------
__device__ __align__(16) __nv_bfloat16 g_ah[(size_t)MROWS * EMB];
__device__ __align__(16) __nv_bfloat16 g_al[(size_t)MROWS * EMB];
__device__ __align__(16) __nv_bfloat16 g_bh[(size_t)4 * EMB * EMB];  // W^T hi x4
__device__ __align__(16) __nv_bfloat16 g_bl[(size_t)4 * EMB * EMB];  // W^T lo x4
__device__ __align__(16) __nv_bfloat16 g_qh[(size_t)MROWS * EMB];
__device__ __align__(16) __nv_bfloat16 g_ql[(size_t)MROWS * EMB];
__device__ __align__(16) __nv_bfloat16 g_kh[(size_t)MROWS * EMB];
__device__ __align__(16) __nv_bfloat16 g_kl[(size_t)MROWS * EMB];
__device__ __align__(16) __nv_bfloat16 g_vh[(size_t)MROWS * EMB];
__device__ __align__(16) __nv_bfloat16 g_vl[(size_t)MROWS * EMB];

// ---------------------------------------------------------------------------
// Warp-MMA / cp.async helpers (baseline PTX: works on plain sm_103 target)
// ---------------------------------------------------------------------------
__device__ __forceinline__ u32 smem_u32(const void* p) {
    u32 a;
    asm("{ .reg .u64 t; cvta.to.shared.u64 t, %1; cvt.u32.u64 %0, t; }"
        : "=r"(a) : "l"(p));
    return a;
}
__device__ __forceinline__ void ldsm_x4(u32& r0, u32& r1, u32& r2, u32& r3,
                                        u32 addr) {
    asm volatile("ldmatrix.sync.aligned.m8n8.x4.shared.b16 {%0,%1,%2,%3}, [%4];"
                 : "=r"(r0), "=r"(r1), "=r"(r2), "=r"(r3) : "r"(addr));
}
__device__ __forceinline__ void ldsm_x4t(u32& r0, u32& r1, u32& r2, u32& r3,
                                         u32 addr) {
    asm volatile("ldmatrix.sync.aligned.m8n8.x4.trans.shared.b16 {%0,%1,%2,%3}, [%4];"
                 : "=r"(r0), "=r"(r1), "=r"(r2), "=r"(r3) : "r"(addr));
}
__device__ __forceinline__ void mma_bf16(float* d, const u32* a, const u32* b) {
    asm volatile(
        "mma.sync.aligned.m16n8k16.row.col.f32.bf16.bf16.f32 "
        "{%0,%1,%2,%3}, {%4,%5,%6,%7}, {%8,%9}, {%0,%1,%2,%3};"
        : "+f"(d[0]), "+f"(d[1]), "+f"(d[2]), "+f"(d[3])
        : "r"(a[0]), "r"(a[1]), "r"(a[2]), "r"(a[3]), "r"(b[0]), "r"(b[1]));
}
__device__ __forceinline__ void cp16(u32 dst, const void* src) {
    asm volatile("cp.async.cg.shared.global [%0], [%1], 16;"
                 :: "r"(dst), "l"(src) : "memory");
}
#define CP_COMMIT() asm volatile("cp.async.commit_group;" ::: "memory")
#define CP_WAIT(n)  asm volatile("cp.async.wait_group %0;" :: "n"(n) : "memory")

// pack two fp32 -> bf16x2 (lo = x0), plus bf16x2 of the residuals
__device__ __forceinline__ void pack_hl(float x0, float x1, u32& hi, u32& lo) {
    asm("cvt.rn.bf16x2.f32 %0, %1, %2;" : "=r"(hi) : "f"(x1), "f"(x0));
    float h0 = __uint_as_float(hi << 16);
    float h1 = __uint_as_float(hi & 0xFFFF0000u);
    float r0 = x0 - h0, r1 = x1 - h1;
    asm("cvt.rn.bf16x2.f32 %0, %1, %2;" : "=r"(lo) : "f"(r1), "f"(r0));
}
#define SWZ64(o)  ((o) ^ (((o) >> 3) & 0x30))
#define SWZ128(o) ((o) ^ (((o) >> 3) & 0x70))

// ---------------------------------------------------------------------------
// Conversion kernels
// ---------------------------------------------------------------------------
__global__ void conv_rows(const float* __restrict__ X,
                          __nv_bfloat16* __restrict__ H,
                          __nv_bfloat16* __restrict__ L, int n4)
{
    int i = blockIdx.x * blockDim.x + threadIdx.x;
    if (i >= n4) return;
    float4 v = ((const float4*)X)[i];
    u32 h0, l0, h1, l1;
    pack_hl(v.x, v.y, h0, l0);
    pack_hl(v.z, v.w, h1, l1);
    ((uint2*)H)[i] = make_uint2(h0, h1);
    ((uint2*)L)[i] = make_uint2(l0, l1);
}

// All 4 weights W[K,N] fp32 -> W^T hi/lo bf16 [N,K], one launch (z selects W)
__global__ void conv_T4(const float* __restrict__ W0, const float* __restrict__ W1,
                        const float* __restrict__ W2, const float* __restrict__ W3,
                        __nv_bfloat16* __restrict__ Th,
                        __nv_bfloat16* __restrict__ Tl)
{
    __shared__ float t[32][33];
    int z = blockIdx.z;
    const float* W = (z == 0) ? W0 : (z == 1) ? W1 : (z == 2) ? W2 : W3;
    size_t zo = (size_t)z * EMB * EMB;
    int n0 = blockIdx.x * 32, k0 = blockIdx.y * 32;
    int x = threadIdx.x, y = threadIdx.y;  // 32 x 8
#pragma unroll
    for (int r = 0; r < 32; r += 8)
        t[y + r][x] = W[(size_t)(k0 + y + r) * EMB + n0 + x];
    __syncthreads();
#pragma unroll
    for (int r = 0; r < 32; r += 8) {
        float v = t[x][y + r];
        __nv_bfloat16 h = __float2bfloat16(v);
        size_t o = zo + (size_t)(n0 + y + r) * EMB + k0 + x;
        Th[o] = h;
        Tl[o] = __float2bfloat16(v - __bfloat162float(h));
    }
}

// ---------------------------------------------------------------------------
// Tensor-core GEMM via mma.sync (bf16 hi/lo split, fp32 accumulate),
// cp.async 3-stage pipeline. ROUND-8 SHAPE (proven best): 128x128 tile,
// 256 threads, 2 CTAs/SM. mats 0,1,2 -> bf16 hi/lo (Q,K,V); mat 3 -> fp32 C.
// Stage layout (32 KB): AH 0, AL 8192, BH 16384, BL 24576.
// ---------------------------------------------------------------------------
#define BKC 32
#define GSTG 32768
#define GSMEM (3 * GSTG)

__global__ __launch_bounds__(256, 2)
void gemm_mma(const __nv_bfloat16* __restrict__ Ah,
              const __nv_bfloat16* __restrict__ Al,
              const __nv_bfloat16* __restrict__ BhAll,
              const __nv_bfloat16* __restrict__ BlAll,
              const float* __restrict__ b0, const float* __restrict__ b1,
              const float* __restrict__ b2, const float* __restrict__ b3,
              __nv_bfloat16* __restrict__ H0, __nv_bfloat16* __restrict__ L0,
              __nv_bfloat16* __restrict__ H1, __nv_bfloat16* __restrict__ L1,
              __nv_bfloat16* __restrict__ H2, __nv_bfloat16* __restrict__ L2,
              float* __restrict__ C, int mat_base, int M, int K)
{
    extern __shared__ char smg[];
    u32 sb = smem_u32(smg);
    const int N = EMB;

    int tid = threadIdx.x;
    int wid = tid / 32, lid = tid % 32;
    int wm = wid / 4, wn = wid % 4;        // warp grid 2 x 4
    int mat = mat_base + (blockIdx.x >> 4);
    int bm = blockIdx.y * 128, bn = (blockIdx.x & 15) * 128;

    const __nv_bfloat16* Bh = BhAll + (size_t)mat * EMB * EMB;
    const __nv_bfloat16* Bl = BlAll + (size_t)mat * EMB * EMB;
    const float* bias = (mat == 0) ? b0 : (mat == 1) ? b1 : (mat == 2) ? b2 : b3;

    float acc[4][4][4];
#pragma unroll
    for (int mt = 0; mt < 4; mt++)
#pragma unroll
        for (int nt = 0; nt < 4; nt++)
#pragma unroll
            for (int e = 0; e < 4; e++) acc[mt][nt][e] = 0.f;

    int a_r = (lid & 15);
    int a_h = (lid >> 4);
    int b_n = ((lid >> 4) << 3) + (lid & 7);
    int b_h = ((lid >> 3) & 1);

    int l_row[2], l_ch[2];
#pragma unroll
    for (int cc = 0; cc < 2; cc++) {
        int c = tid + cc * 256;
        l_row[cc] = c >> 2;
        l_ch[cc] = c & 3;
    }

#define GEMM_ISSUE(stage, k0)                                                  \
    do {                                                                       \
        u32 base_ = sb + (stage) * GSTG;                                       \
        _Pragma("unroll")                                                      \
        for (int cc = 0; cc < 2; cc++) {                                       \
            int row = l_row[cc], ch = l_ch[cc];                                \
            u32 so = SWZ64((u32)(row * 64 + ch * 16));                         \
            size_t ga = (size_t)(bm + row) * K + (k0) + ch * 8;                \
            size_t gb = (size_t)(bn + row) * K + (k0) + ch * 8;                \
            cp16(base_ + so, Ah + ga);                                         \
            cp16(base_ + 8192 + so, Al + ga);                                  \
            cp16(base_ + 16384 + so, Bh + gb);                                 \
            cp16(base_ + 24576 + so, Bl + gb);                                 \
        }                                                                      \
        CP_COMMIT();                                                           \
    } while (0)

    int niter = K / BKC;
    GEMM_ISSUE(0, 0);
    GEMM_ISSUE(1, BKC);

    for (int it = 0; it < niter; it++) {
        if (it + 2 < niter) {
            int st = (it + 2) % 3;
            GEMM_ISSUE(st, (it + 2) * BKC);
            CP_WAIT(2);
        } else if (it + 1 < niter) {
            CP_WAIT(1);
        } else {
            CP_WAIT(0);
        }
        __syncthreads();

        u32 baseAh = sb + (it % 3) * GSTG;
        u32 baseAl = baseAh + 8192;
        u32 baseBh = baseAh + 16384;
        u32 baseBl = baseAh + 24576;

#pragma unroll
        for (int ks = 0; ks < 2; ks++) {
            u32 af[4][4], bhf[4][2], blf[4][2];
#pragma unroll
            for (int mt = 0; mt < 4; mt++) {
                int r = wm * 64 + mt * 16 + a_r;
                u32 addr = baseAh + SWZ64((u32)(r * 64 + (ks * 2 + a_h) * 16));
                ldsm_x4(af[mt][0], af[mt][1], af[mt][2], af[mt][3], addr);
            }
#pragma unroll
            for (int np = 0; np < 2; np++) {
                int n = wn * 32 + np * 16 + b_n;
                u32 off = SWZ64((u32)(n * 64 + (ks * 2 + b_h) * 16));
                ldsm_x4(bhf[np * 2][0], bhf[np * 2][1],
                        bhf[np * 2 + 1][0], bhf[np * 2 + 1][1], baseBh + off);
                ldsm_x4(blf[np * 2][0], blf[np * 2][1],
                        blf[np * 2 + 1][0], blf[np * 2 + 1][1], baseBl + off);
            }
#pragma unroll
            for (int mt = 0; mt < 4; mt++)
#pragma unroll
                for (int nt = 0; nt < 4; nt++)
                    mma_bf16(acc[mt][nt], af[mt], bhf[nt]);
#pragma unroll
            for (int mt = 0; mt < 4; mt++)
#pragma unroll
                for (int nt = 0; nt < 4; nt++)
                    mma_bf16(acc[mt][nt], af[mt], blf[nt]);
#pragma unroll
            for (int mt = 0; mt < 4; mt++) {
                int r = wm * 64 + mt * 16 + a_r;
                u32 addr = baseAl + SWZ64((u32)(r * 64 + (ks * 2 + a_h) * 16));
                ldsm_x4(af[mt][0], af[mt][1], af[mt][2], af[mt][3], addr);
            }
#pragma unroll
            for (int mt = 0; mt < 4; mt++)
#pragma unroll
                for (int nt = 0; nt < 4; nt++)
                    mma_bf16(acc[mt][nt], af[mt], bhf[nt]);
        }
        __syncthreads();
    }

    __nv_bfloat16* H = (mat == 0) ? H0 : (mat == 1) ? H1 : H2;
    __nv_bfloat16* L = (mat == 0) ? L0 : (mat == 1) ? L1 : L2;

    int rr = lid >> 2, cc2 = (lid & 3) * 2;
#pragma unroll
    for (int mt = 0; mt < 4; mt++) {
        int r0 = bm + wm * 64 + mt * 16 + rr;
#pragma unroll
        for (int nt = 0; nt < 4; nt++) {
            int col = bn + wn * 32 + nt * 8 + cc2;
            float bb0 = bias[col], bb1 = bias[col + 1];
            float v00 = acc[mt][nt][0] + bb0, v01 = acc[mt][nt][1] + bb1;
            float v10 = acc[mt][nt][2] + bb0, v11 = acc[mt][nt][3] + bb1;
            if (mat == 3) {
                *(float2*)&C[(size_t)r0 * N + col] = make_float2(v00, v01);
                *(float2*)&C[(size_t)(r0 + 8) * N + col] = make_float2(v10, v11);
            } else {
                u32 hi, lo;
                pack_hl(v00, v01, hi, lo);
                *(u32*)&H[(size_t)r0 * N + col] = hi;
                *(u32*)&L[(size_t)r0 * N + col] = lo;
                pack_hl(v10, v11, hi, lo);
                *(u32*)&H[(size_t)(r0 + 8) * N + col] = hi;
                *(u32*)&L[(size_t)(r0 + 8) * N + col] = lo;
            }
        }
    }
}

// ---------------------------------------------------------------------------
// Tensor-core causal flash attention (bf16 hi/lo, fp32 softmax),
// cp.async 2-stage K/V pipeline, V via ldmatrix.trans (no V^T pass).
// __launch_bounds__(256, 2): cap regs at 128 so TWO CTAs fit the 64K-reg
// file (round-10 profile: 130 regs -> 1 CTA/SM, occ 12.5%, tensor 52%).
// RoPE mathematically eliminated (head-only rotation; q.k invariant).
// CTA: 128 q rows, 8 warps (warp = 16 q rows x full 64-col kv tile).
// ---------------------------------------------------------------------------
#define ABQ 128
#define ABK 64
#define OQH 0
#define OQL 16384
#define AKV 32768
#define ASTG 32768
#define ASMEM (AKV + 2 * ASTG)

__global__ __launch_bounds__(256, 2)
void flash_attn_tc(const __nv_bfloat16* __restrict__ qh_,
                   const __nv_bfloat16* __restrict__ ql_,
                   const __nv_bfloat16* __restrict__ kh_,
                   const __nv_bfloat16* __restrict__ kl_,
                   const __nv_bfloat16* __restrict__ vh_,
                   const __nv_bfloat16* __restrict__ vl_,
                   __nv_bfloat16* __restrict__ aoh,
                   __nv_bfloat16* __restrict__ aol)
{
    extern __shared__ char smc[];
    u32 sb = smem_u32(smc);
    int tid = threadIdx.x, wid = tid / 32, lid = tid % 32;
    int qb = gridDim.x - 1 - blockIdx.x;   // longest work first
    int h = blockIdx.y, b = blockIdx.z;
    int q0 = qb * ABQ;
    int warp_row = q0 + wid * 16;

    // Load Q tile (128x64 hi/lo), SW128 rows
#pragma unroll
    for (int i = 0; i < 4; i++) {
        int c = tid + i * 256;
        int r = c >> 3, ch = c & 7;
        u32 so = SWZ128((u32)(r * 128 + ch * 16));
        size_t g = (size_t)(b * SEQ + q0 + r) * EMB + h * HD + ch * 8;
        *(uint4*)(smc + OQH + so) = *(const uint4*)(qh_ + g);
        *(uint4*)(smc + OQL + so) = *(const uint4*)(ql_ + g);
    }

    int v_r[2], v_ch[2];
#pragma unroll
    for (int i = 0; i < 2; i++) {
        int c = tid + i * 256;
        v_r[i] = c >> 3;
        v_ch[i] = c & 7;
    }

// K and V use the SAME row-major [kv][d] addressing
#define ATTN_ISSUE(stage, kb)                                                  \
    do {                                                                       \
        u32 base_ = sb + AKV + (stage) * ASTG;                                 \
        _Pragma("unroll")                                                      \
        for (int i = 0; i < 2; i++) {                                          \
            int r = v_r[i], ch = v_ch[i];                                      \
            u32 so = SWZ128((u32)(r * 128 + ch * 16));                         \
            size_t gk = (size_t)(b * SEQ + (kb) * ABK + r) * EMB + h * HD + ch * 8; \
            cp16(base_ + so, kh_ + gk);                                        \
            cp16(base_ + 8192 + so, kl_ + gk);                                 \
            cp16(base_ + 16384 + so, vh_ + gk);                                \
            cp16(base_ + 24576 + so, vl_ + gk);                                \
        }                                                                      \
        CP_COMMIT();                                                           \
    } while (0)

    float m_i[2], l_i[2], o[8][4];
    m_i[0] = m_i[1] = -INFINITY;
    l_i[0] = l_i[1] = 0.f;
#pragma unroll
    for (int nt = 0; nt < 8; nt++)
#pragma unroll
        for (int e = 0; e < 4; e++) o[nt][e] = 0.f;

    const float scale = 0.125f;  // 1/sqrt(64)
    int r1 = lid >> 2;
    int a_r = lid & 15, a_h = lid >> 4;
    int b_n = ((lid >> 4) << 3) + (lid & 7), b_h = (lid >> 3) & 1;
    // trans-ldmatrix lane decomposition for V (rows = kv, cols = d)
    int t_r16 = (lid & 7) + ((lid >> 3) & 1) * 8;   // kv offset within 16
    int t_cb  = ((lid >> 4) & 1) * 16;              // d byte offset (8 cols)

    int nkb = 2 * qb + 2;
    ATTN_ISSUE(0, 0);

    for (int kb = 0; kb < nkb; kb++) {
        if (kb + 1 < nkb) {
            ATTN_ISSUE((kb + 1) & 1, kb + 1);
            CP_WAIT(1);
        } else {
            CP_WAIT(0);
        }
        __syncthreads();

        if (kb * ABK <= warp_row + 15) {   // not fully masked
            u32 bk = sb + AKV + (kb & 1) * ASTG;
            u32 okh = bk, okl = bk + 8192, ovh = bk + 16384, ovl = bk + 24576;

            // ---- S = Q K^T (hi/lo, 3 passes) ----
            float s[8][4];
#pragma unroll
            for (int nt = 0; nt < 8; nt++)
#pragma unroll
                for (int e = 0; e < 4; e++) s[nt][e] = 0.f;

#pragma unroll
            for (int kc = 0; kc < 4; kc++) {
                u32 af[4], bhf[8][2], blf[8][2];
                u32 arow = (u32)((wid * 16 + a_r) * 128 + (kc * 2 + a_h) * 16);
                ldsm_x4(af[0], af[1], af[2], af[3], sb + OQH + SWZ128(arow));
#pragma unroll
                for (int g = 0; g < 4; g++) {
                    int n = g * 16 + b_n;
                    u32 off = SWZ128((u32)(n * 128 + (kc * 2 + b_h) * 16));
                    ldsm_x4(bhf[g * 2][0], bhf[g * 2][1],
                            bhf[g * 2 + 1][0], bhf[g * 2 + 1][1], okh + off);
                    ldsm_x4(blf[g * 2][0], blf[g * 2][1],
                            blf[g * 2 + 1][0], blf[g * 2 + 1][1], okl + off);
                }
#pragma unroll
                for (int nt = 0; nt < 8; nt++) mma_bf16(s[nt], af, bhf[nt]);
#pragma unroll
                for (int nt = 0; nt < 8; nt++) mma_bf16(s[nt], af, blf[nt]);
                ldsm_x4(af[0], af[1], af[2], af[3], sb + OQL + SWZ128(arow));
#pragma unroll
                for (int nt = 0; nt < 8; nt++) mma_bf16(s[nt], af, bhf[nt]);
            }

            // ---- scale + causal mask ----
            bool needmask = (kb * ABK + ABK - 1 > warp_row);
#pragma unroll
            for (int nt = 0; nt < 8; nt++) {
#pragma unroll
                for (int e = 0; e < 4; e++) {
                    s[nt][e] *= scale;
                    if (needmask) {
                        int row = warp_row + r1 + ((e >> 1) << 3);
                        int col = kb * ABK + nt * 8 + (lid & 3) * 2 + (e & 1);
                        if (col > row) s[nt][e] = -INFINITY;
                    }
                }
            }

            // ---- online softmax (rows r1, r1+8) ----
#pragma unroll
            for (int half = 0; half < 2; half++) {
                float mx = -INFINITY;
#pragma unroll
                for (int nt = 0; nt < 8; nt++)
                    mx = fmaxf(mx, fmaxf(s[nt][half * 2], s[nt][half * 2 + 1]));
                mx = fmaxf(mx, __shfl_xor_sync(0xffffffffu, mx, 1));
                mx = fmaxf(mx, __shfl_xor_sync(0xffffffffu, mx, 2));
                float m_new = fmaxf(m_i[half], mx);
                float corr = __expf(m_i[half] - m_new);
                m_i[half] = m_new;
                float rs = 0.f;
#pragma unroll
                for (int nt = 0; nt < 8; nt++) {
                    float p0 = __expf(s[nt][half * 2] - m_new);
                    float p1 = __expf(s[nt][half * 2 + 1] - m_new);
                    s[nt][half * 2] = p0;
                    s[nt][half * 2 + 1] = p1;
                    rs += p0 + p1;
                }
                rs += __shfl_xor_sync(0xffffffffu, rs, 1);
                rs += __shfl_xor_sync(0xffffffffu, rs, 2);
                l_i[half] = l_i[half] * corr + rs;
#pragma unroll
                for (int nt = 0; nt < 8; nt++) {
                    o[nt][half * 2] *= corr;
                    o[nt][half * 2 + 1] *= corr;
                }
            }

            // ---- O += P V (hi/lo, 3 passes); V fragments via ldmatrix.trans
            //      from row-major [kv][d] tile ----
#pragma unroll
            for (int kc = 0; kc < 4; kc++) {
                u32 ph[4], pl[4];
                pack_hl(s[2 * kc][0], s[2 * kc][1], ph[0], pl[0]);
                pack_hl(s[2 * kc][2], s[2 * kc][3], ph[1], pl[1]);
                pack_hl(s[2 * kc + 1][0], s[2 * kc + 1][1], ph[2], pl[2]);
                pack_hl(s[2 * kc + 1][2], s[2 * kc + 1][3], ph[3], pl[3]);

                u32 bvh[8][2], bvl[8][2];
                u32 trow = (u32)((kc * 16 + t_r16) * 128);
#pragma unroll
                for (int g = 0; g < 4; g++) {
                    u32 off = SWZ128(trow + g * 32 + t_cb);
                    ldsm_x4t(bvh[g * 2][0], bvh[g * 2][1],
                             bvh[g * 2 + 1][0], bvh[g * 2 + 1][1], ovh + off);
                    ldsm_x4t(bvl[g * 2][0], bvl[g * 2][1],
                             bvl[g * 2 + 1][0], bvl[g * 2 + 1][1], ovl + off);
                }
#pragma unroll
                for (int nt = 0; nt < 8; nt++) mma_bf16(o[nt], ph, bvh[nt]);
#pragma unroll
                for (int nt = 0; nt < 8; nt++) mma_bf16(o[nt], ph, bvl[nt]);
#pragma unroll
                for (int nt = 0; nt < 8; nt++) mma_bf16(o[nt], pl, bvh[nt]);
            }
        }
        __syncthreads();
    }

    // ---- epilogue: normalize, split to hi/lo bf16, store ----
#pragma unroll
    for (int half = 0; half < 2; half++) {
        float inv = 1.f / l_i[half];
        int row = warp_row + r1 + half * 8;
        size_t base = (size_t)(b * SEQ + row) * EMB + h * HD;
#pragma unroll
        for (int nt = 0; nt < 8; nt++) {
            int col = nt * 8 + (lid & 3) * 2;
            float v0 = o[nt][half * 2] * inv;
            float v1 = o[nt][half * 2 + 1] * inv;
            u32 hi, lo;
            pack_hl(v0, v1, hi, lo);
            *(u32*)&aoh[base + col] = hi;
            *(u32*)&aol[base + col] = lo;
        }
    }
}

// ---------------------------------------------------------------------------
// Launch
// ---------------------------------------------------------------------------
extern "C" void kernel_launch(void* const* d_in, const int* in_sizes, int n_in,
                              void* d_out, int out_size)
{
    const float* x  = (const float*)d_in[0];
    const float* Wq = (const float*)d_in[1];
    const float* bq = (const float*)d_in[2];
    const float* Wk = (const float*)d_in[3];
    const float* bk = (const float*)d_in[4];
    const float* Wv = (const float*)d_in[5];
    const float* bv = (const float*)d_in[6];
    const float* Wo = (const float*)d_in[7];
    const float* bo = (const float*)d_in[8];
    float* out = (float*)d_out;

    __nv_bfloat16 *ah, *al, *bh, *bl, *qh, *ql, *kh, *kl, *vh, *vl;
    cudaGetSymbolAddress((void**)&ah, g_ah);
    cudaGetSymbolAddress((void**)&al, g_al);
    cudaGetSymbolAddress((void**)&bh, g_bh);
    cudaGetSymbolAddress((void**)&bl, g_bl);
    cudaGetSymbolAddress((void**)&qh, g_qh);
    cudaGetSymbolAddress((void**)&ql, g_ql);
    cudaGetSymbolAddress((void**)&kh, g_kh);
    cudaGetSymbolAddress((void**)&kl, g_kl);
    cudaGetSymbolAddress((void**)&vh, g_vh);
    cudaGetSymbolAddress((void**)&vl, g_vl);

    cudaFuncSetAttribute(gemm_mma,
                         cudaFuncAttributeMaxDynamicSharedMemorySize, GSMEM);
    cudaFuncSetAttribute(flash_attn_tc,
                         cudaFuncAttributeMaxDynamicSharedMemorySize, ASMEM);

    dim3 ct(32, 8);
    dim3 cg4(EMB / 32, EMB / 32, 4);
    int n4 = MROWS * EMB / 4;
    dim3 qkvgrid(3 * EMB / 128, MROWS / 128);   // (48, 32): fused Q,K,V
    dim3 ogrid(EMB / 128, MROWS / 128);         // (16, 32): out proj
    dim3 agrid(SEQ / ABQ, NH, BSZ);             // (16, 32, 2)

    // split x; convert all 4 weights
    conv_rows<<<(n4 + 255) / 256, 256>>>(x, ah, al, n4);
    conv_T4<<<cg4, ct>>>(Wq, Wk, Wv, Wo, bh, bl);

    // fused QKV projection -> bf16 hi/lo
    gemm_mma<<<qkvgrid, 256, GSMEM>>>(ah, al, bh, bl, bq, bk, bv, bo,
                                      qh, ql, kh, kl, vh, vl, NULL, 0,
                                      MROWS, EMB);

    // attention -> hi/lo into ah/al; V read directly (ldmatrix.trans)
    flash_attn_tc<<<agrid, 256, ASMEM>>>(qh, ql, kh, kl, vh, vl, ah, al);

    // output projection (mat 3, fp32 out)
    gemm_mma<<<ogrid, 256, GSMEM>>>(ah, al, bh, bl, bq, bk, bv, bo,
                                    qh, ql, kh, kl, vh, vl, out, 3,
                                    MROWS, EMB);
}

// round 12
// speedup vs baseline: 1.1528x; 1.0150x over previous
#include <cuda_runtime.h>
#include <cuda_bf16.h>
#include <cstdint>
#include <math.h>

typedef unsigned int u32;
typedef unsigned long long u64;
typedef unsigned short u16;

#define BSZ 2
#define SEQ 2048
#define EMB 2048
#define NH 32
#define HD 64
#define MROWS (BSZ*SEQ)

// ---------------------------------------------------------------------------
// Scratch (device globals: allocation-free per harness rules)
// ---------------------------------------------------------------------------
__device__ __align__(16) __nv_bfloat16 g_ah[(size_t)MROWS * EMB];
__device__ __align__(16) __nv_bfloat16 g_al[(size_t)MROWS * EMB];
__device__ __align__(16) __nv_bfloat16 g_bh[(size_t)4 * EMB * EMB];  // W^T hi x4
__device__ __align__(16) __nv_bfloat16 g_bl[(size_t)4 * EMB * EMB];  // W^T lo x4
__device__ __align__(16) __nv_bfloat16 g_qh[(size_t)MROWS * EMB];
__device__ __align__(16) __nv_bfloat16 g_ql[(size_t)MROWS * EMB];
__device__ __align__(16) __nv_bfloat16 g_kh[(size_t)MROWS * EMB];
__device__ __align__(16) __nv_bfloat16 g_kl[(size_t)MROWS * EMB];
__device__ __align__(16) __nv_bfloat16 g_vh[(size_t)MROWS * EMB];
__device__ __align__(16) __nv_bfloat16 g_vl[(size_t)MROWS * EMB];

// ---------------------------------------------------------------------------
// Warp-MMA / cp.async helpers (baseline PTX: works on plain sm_103 target)
// ---------------------------------------------------------------------------
__device__ __forceinline__ u32 smem_u32(const void* p) {
    u32 a;
    asm("{ .reg .u64 t; cvta.to.shared.u64 t, %1; cvt.u32.u64 %0, t; }"
        : "=r"(a) : "l"(p));
    return a;
}
__device__ __forceinline__ void ldsm_x4(u32& r0, u32& r1, u32& r2, u32& r3,
                                        u32 addr) {
    asm volatile("ldmatrix.sync.aligned.m8n8.x4.shared.b16 {%0,%1,%2,%3}, [%4];"
                 : "=r"(r0), "=r"(r1), "=r"(r2), "=r"(r3) : "r"(addr));
}
__device__ __forceinline__ void ldsm_x4t(u32& r0, u32& r1, u32& r2, u32& r3,
                                         u32 addr) {
    asm volatile("ldmatrix.sync.aligned.m8n8.x4.trans.shared.b16 {%0,%1,%2,%3}, [%4];"
                 : "=r"(r0), "=r"(r1), "=r"(r2), "=r"(r3) : "r"(addr));
}
__device__ __forceinline__ void mma_bf16(float* d, const u32* a, const u32* b) {
    asm volatile(
        "mma.sync.aligned.m16n8k16.row.col.f32.bf16.bf16.f32 "
        "{%0,%1,%2,%3}, {%4,%5,%6,%7}, {%8,%9}, {%0,%1,%2,%3};"
        : "+f"(d[0]), "+f"(d[1]), "+f"(d[2]), "+f"(d[3])
        : "r"(a[0]), "r"(a[1]), "r"(a[2]), "r"(a[3]), "r"(b[0]), "r"(b[1]));
}
__device__ __forceinline__ void cp16(u32 dst, const void* src) {
    asm volatile("cp.async.cg.shared.global [%0], [%1], 16;"
                 :: "r"(dst), "l"(src) : "memory");
}
#define CP_COMMIT() asm volatile("cp.async.commit_group;" ::: "memory")
#define CP_WAIT(n)  asm volatile("cp.async.wait_group %0;" :: "n"(n) : "memory")

// raw exp2 (single MUFU; inputs pre-scaled to base-2 domain)
__device__ __forceinline__ float ex2(float x) {
    float y;
    asm("ex2.approx.f32 %0, %1;" : "=f"(y) : "f"(x));
    return y;
}

// pack two fp32 -> bf16x2 (lo = x0), plus bf16x2 of the residuals
__device__ __forceinline__ void pack_hl(float x0, float x1, u32& hi, u32& lo) {
    asm("cvt.rn.bf16x2.f32 %0, %1, %2;" : "=r"(hi) : "f"(x1), "f"(x0));
    float h0 = __uint_as_float(hi << 16);
    float h1 = __uint_as_float(hi & 0xFFFF0000u);
    float r0 = x0 - h0, r1 = x1 - h1;
    asm("cvt.rn.bf16x2.f32 %0, %1, %2;" : "=r"(lo) : "f"(r1), "f"(r0));
}
#define SWZ64(o)  ((o) ^ (((o) >> 3) & 0x30))
#define SWZ128(o) ((o) ^ (((o) >> 3) & 0x70))

// ---------------------------------------------------------------------------
// Fused conversion: z=0..3 -> W_z^T hi/lo; z=4,5 -> x row-split hi/lo
// ---------------------------------------------------------------------------
__global__ void conv_all(const float* __restrict__ W0, const float* __restrict__ W1,
                         const float* __restrict__ W2, const float* __restrict__ W3,
                         const float* __restrict__ X,
                         __nv_bfloat16* __restrict__ Th,
                         __nv_bfloat16* __restrict__ Tl,
                         __nv_bfloat16* __restrict__ XH,
                         __nv_bfloat16* __restrict__ XL)
{
    int z = blockIdx.z;
    if (z >= 4) {
        // x split: 1M float4 per half, 4096 blocks x 256 threads
        int t = threadIdx.y * 32 + threadIdx.x;
        size_t i = ((size_t)(z - 4) * 4096 + blockIdx.y * 64 + blockIdx.x) * 256 + t;
        float4 v = ((const float4*)X)[i];
        u32 h0, l0, h1, l1;
        pack_hl(v.x, v.y, h0, l0);
        pack_hl(v.z, v.w, h1, l1);
        ((uint2*)XH)[i] = make_uint2(h0, h1);
        ((uint2*)XL)[i] = make_uint2(l0, l1);
        return;
    }
    __shared__ float t[32][33];
    const float* W = (z == 0) ? W0 : (z == 1) ? W1 : (z == 2) ? W2 : W3;
    size_t zo = (size_t)z * EMB * EMB;
    int n0 = blockIdx.x * 32, k0 = blockIdx.y * 32;
    int x = threadIdx.x, y = threadIdx.y;  // 32 x 8
#pragma unroll
    for (int r = 0; r < 32; r += 8)
        t[y + r][x] = W[(size_t)(k0 + y + r) * EMB + n0 + x];
    __syncthreads();
#pragma unroll
    for (int r = 0; r < 32; r += 8) {
        float v = t[x][y + r];
        __nv_bfloat16 h = __float2bfloat16(v);
        size_t o = zo + (size_t)(n0 + y + r) * EMB + k0 + x;
        Th[o] = h;
        Tl[o] = __float2bfloat16(v - __bfloat162float(h));
    }
}

// ---------------------------------------------------------------------------
// Tensor-core GEMM via mma.sync (bf16 hi/lo split, fp32 accumulate),
// cp.async 3-stage pipeline, SINGLE sync per iteration (issue moved after
// the barrier; 3-stage ring keeps CP_WAIT(1) sufficient for the live stage).
// 128x128 tile, 256 threads, 2 CTAs/SM (proven best shape).
// mats 0,1,2 -> bf16 hi/lo (Q,K,V); mat 3 -> fp32 C.
// Stage layout (32 KB): AH 0, AL 8192, BH 16384, BL 24576.
// ---------------------------------------------------------------------------
#define BKC 32
#define GSTG 32768
#define GSMEM (3 * GSTG)

__global__ __launch_bounds__(256, 2)
void gemm_mma(const __nv_bfloat16* __restrict__ Ah,
              const __nv_bfloat16* __restrict__ Al,
              const __nv_bfloat16* __restrict__ BhAll,
              const __nv_bfloat16* __restrict__ BlAll,
              const float* __restrict__ b0, const float* __restrict__ b1,
              const float* __restrict__ b2, const float* __restrict__ b3,
              __nv_bfloat16* __restrict__ H0, __nv_bfloat16* __restrict__ L0,
              __nv_bfloat16* __restrict__ H1, __nv_bfloat16* __restrict__ L1,
              __nv_bfloat16* __restrict__ H2, __nv_bfloat16* __restrict__ L2,
              float* __restrict__ C, int mat_base, int M, int K)
{
    extern __shared__ char smg[];
    u32 sb = smem_u32(smg);
    const int N = EMB;

    int tid = threadIdx.x;
    int wid = tid / 32, lid = tid % 32;
    int wm = wid / 4, wn = wid % 4;        // warp grid 2 x 4
    int mat = mat_base + (blockIdx.x >> 4);
    int bm = blockIdx.y * 128, bn = (blockIdx.x & 15) * 128;

    const __nv_bfloat16* Bh = BhAll + (size_t)mat * EMB * EMB;
    const __nv_bfloat16* Bl = BlAll + (size_t)mat * EMB * EMB;
    const float* bias = (mat == 0) ? b0 : (mat == 1) ? b1 : (mat == 2) ? b2 : b3;

    float acc[4][4][4];
#pragma unroll
    for (int mt = 0; mt < 4; mt++)
#pragma unroll
        for (int nt = 0; nt < 4; nt++)
#pragma unroll
            for (int e = 0; e < 4; e++) acc[mt][nt][e] = 0.f;

    int a_r = (lid & 15);
    int a_h = (lid >> 4);
    int b_n = ((lid >> 4) << 3) + (lid & 7);
    int b_h = ((lid >> 3) & 1);

    int l_row[2], l_ch[2];
#pragma unroll
    for (int cc = 0; cc < 2; cc++) {
        int c = tid + cc * 256;
        l_row[cc] = c >> 2;
        l_ch[cc] = c & 3;
    }

#define GEMM_ISSUE(stage, k0)                                                  \
    do {                                                                       \
        u32 base_ = sb + (stage) * GSTG;                                       \
        _Pragma("unroll")                                                      \
        for (int cc = 0; cc < 2; cc++) {                                       \
            int row = l_row[cc], ch = l_ch[cc];                                \
            u32 so = SWZ64((u32)(row * 64 + ch * 16));                         \
            size_t ga = (size_t)(bm + row) * K + (k0) + ch * 8;                \
            size_t gb = (size_t)(bn + row) * K + (k0) + ch * 8;                \
            cp16(base_ + so, Ah + ga);                                         \
            cp16(base_ + 8192 + so, Al + ga);                                  \
            cp16(base_ + 16384 + so, Bh + gb);                                 \
            cp16(base_ + 24576 + so, Bl + gb);                                 \
        }                                                                      \
        CP_COMMIT();                                                           \
    } while (0)

    int niter = K / BKC;
    GEMM_ISSUE(0, 0);
    GEMM_ISSUE(1, BKC);

    for (int it = 0; it < niter; it++) {
        if (it + 1 < niter) {
            CP_WAIT(1);            // stage `it` complete (newest pending: it+1)
        } else {
            CP_WAIT(0);
        }
        __syncthreads();           // all warps done with stage it-1's compute
        if (it + 2 < niter)
            GEMM_ISSUE((it + 2) % 3, (it + 2) * BKC);  // overwrites stage it-1

        u32 baseAh = sb + (it % 3) * GSTG;
        u32 baseAl = baseAh + 8192;
        u32 baseBh = baseAh + 16384;
        u32 baseBl = baseAh + 24576;

#pragma unroll
        for (int ks = 0; ks < 2; ks++) {
            u32 af[4][4], bhf[4][2], blf[4][2];
#pragma unroll
            for (int mt = 0; mt < 4; mt++) {
                int r = wm * 64 + mt * 16 + a_r;
                u32 addr = baseAh + SWZ64((u32)(r * 64 + (ks * 2 + a_h) * 16));
                ldsm_x4(af[mt][0], af[mt][1], af[mt][2], af[mt][3], addr);
            }
#pragma unroll
            for (int np = 0; np < 2; np++) {
                int n = wn * 32 + np * 16 + b_n;
                u32 off = SWZ64((u32)(n * 64 + (ks * 2 + b_h) * 16));
                ldsm_x4(bhf[np * 2][0], bhf[np * 2][1],
                        bhf[np * 2 + 1][0], bhf[np * 2 + 1][1], baseBh + off);
                ldsm_x4(blf[np * 2][0], blf[np * 2][1],
                        blf[np * 2 + 1][0], blf[np * 2 + 1][1], baseBl + off);
            }
#pragma unroll
            for (int mt = 0; mt < 4; mt++)
#pragma unroll
                for (int nt = 0; nt < 4; nt++)
                    mma_bf16(acc[mt][nt], af[mt], bhf[nt]);
#pragma unroll
            for (int mt = 0; mt < 4; mt++)
#pragma unroll
                for (int nt = 0; nt < 4; nt++)
                    mma_bf16(acc[mt][nt], af[mt], blf[nt]);
#pragma unroll
            for (int mt = 0; mt < 4; mt++) {
                int r = wm * 64 + mt * 16 + a_r;
                u32 addr = baseAl + SWZ64((u32)(r * 64 + (ks * 2 + a_h) * 16));
                ldsm_x4(af[mt][0], af[mt][1], af[mt][2], af[mt][3], addr);
            }
#pragma unroll
            for (int mt = 0; mt < 4; mt++)
#pragma unroll
                for (int nt = 0; nt < 4; nt++)
                    mma_bf16(acc[mt][nt], af[mt], bhf[nt]);
        }
    }

    __nv_bfloat16* H = (mat == 0) ? H0 : (mat == 1) ? H1 : H2;
    __nv_bfloat16* L = (mat == 0) ? L0 : (mat == 1) ? L1 : L2;

    int rr = lid >> 2, cc2 = (lid & 3) * 2;
#pragma unroll
    for (int mt = 0; mt < 4; mt++) {
        int r0 = bm + wm * 64 + mt * 16 + rr;
#pragma unroll
        for (int nt = 0; nt < 4; nt++) {
            int col = bn + wn * 32 + nt * 8 + cc2;
            float bb0 = bias[col], bb1 = bias[col + 1];
            float v00 = acc[mt][nt][0] + bb0, v01 = acc[mt][nt][1] + bb1;
            float v10 = acc[mt][nt][2] + bb0, v11 = acc[mt][nt][3] + bb1;
            if (mat == 3) {
                *(float2*)&C[(size_t)r0 * N + col] = make_float2(v00, v01);
                *(float2*)&C[(size_t)(r0 + 8) * N + col] = make_float2(v10, v11);
            } else {
                u32 hi, lo;
                pack_hl(v00, v01, hi, lo);
                *(u32*)&H[(size_t)r0 * N + col] = hi;
                *(u32*)&L[(size_t)r0 * N + col] = lo;
                pack_hl(v10, v11, hi, lo);
                *(u32*)&H[(size_t)(r0 + 8) * N + col] = hi;
                *(u32*)&L[(size_t)(r0 + 8) * N + col] = lo;
            }
        }
    }
}

// ---------------------------------------------------------------------------
// Tensor-core causal flash attention (bf16 hi/lo, fp32 softmax in BASE-2
// domain: score scale pre-folds log2e so softmax uses raw ex2.approx),
// cp.async 2-stage K/V pipeline, V via ldmatrix.trans (no V^T pass).
// __launch_bounds__(256, 2): 128 regs -> 2 CTAs/SM.
// RoPE mathematically eliminated (head-only rotation; q.k invariant).
// CTA: 128 q rows, 8 warps (warp = 16 q rows x full 64-col kv tile).
// ---------------------------------------------------------------------------
#define ABQ 128
#define ABK 64
#define OQH 0
#define OQL 16384
#define AKV 32768
#define ASTG 32768
#define ASMEM (AKV + 2 * ASTG)

__global__ __launch_bounds__(256, 2)
void flash_attn_tc(const __nv_bfloat16* __restrict__ qh_,
                   const __nv_bfloat16* __restrict__ ql_,
                   const __nv_bfloat16* __restrict__ kh_,
                   const __nv_bfloat16* __restrict__ kl_,
                   const __nv_bfloat16* __restrict__ vh_,
                   const __nv_bfloat16* __restrict__ vl_,
                   __nv_bfloat16* __restrict__ aoh,
                   __nv_bfloat16* __restrict__ aol)
{
    extern __shared__ char smc[];
    u32 sb = smem_u32(smc);
    int tid = threadIdx.x, wid = tid / 32, lid = tid % 32;
    int qb = gridDim.x - 1 - blockIdx.x;   // longest work first
    int h = blockIdx.y, b = blockIdx.z;
    int q0 = qb * ABQ;
    int warp_row = q0 + wid * 16;

    // Load Q tile (128x64 hi/lo), SW128 rows
#pragma unroll
    for (int i = 0; i < 4; i++) {
        int c = tid + i * 256;
        int r = c >> 3, ch = c & 7;
        u32 so = SWZ128((u32)(r * 128 + ch * 16));
        size_t g = (size_t)(b * SEQ + q0 + r) * EMB + h * HD + ch * 8;
        *(uint4*)(smc + OQH + so) = *(const uint4*)(qh_ + g);
        *(uint4*)(smc + OQL + so) = *(const uint4*)(ql_ + g);
    }

    int v_r[2], v_ch[2];
#pragma unroll
    for (int i = 0; i < 2; i++) {
        int c = tid + i * 256;
        v_r[i] = c >> 3;
        v_ch[i] = c & 7;
    }

// K and V use the SAME row-major [kv][d] addressing
#define ATTN_ISSUE(stage, kb)                                                  \
    do {                                                                       \
        u32 base_ = sb + AKV + (stage) * ASTG;                                 \
        _Pragma("unroll")                                                      \
        for (int i = 0; i < 2; i++) {                                          \
            int r = v_r[i], ch = v_ch[i];                                      \
            u32 so = SWZ128((u32)(r * 128 + ch * 16));                         \
            size_t gk = (size_t)(b * SEQ + (kb) * ABK + r) * EMB + h * HD + ch * 8; \
            cp16(base_ + so, kh_ + gk);                                        \
            cp16(base_ + 8192 + so, kl_ + gk);                                 \
            cp16(base_ + 16384 + so, vh_ + gk);                                \
            cp16(base_ + 24576 + so, vl_ + gk);                                \
        }                                                                      \
        CP_COMMIT();                                                           \
    } while (0)

    float m_i[2], l_i[2], o[8][4];
    m_i[0] = m_i[1] = -INFINITY;
    l_i[0] = l_i[1] = 0.f;
#pragma unroll
    for (int nt = 0; nt < 8; nt++)
#pragma unroll
        for (int e = 0; e < 4; e++) o[nt][e] = 0.f;

    // base-2 domain: fold log2(e) into the 1/sqrt(64) scale
    const float scale2 = 0.125f * 1.4426950408889634f;
    int r1 = lid >> 2;
    int a_r = lid & 15, a_h = lid >> 4;
    int b_n = ((lid >> 4) << 3) + (lid & 7), b_h = (lid >> 3) & 1;
    // trans-ldmatrix lane decomposition for V (rows = kv, cols = d)
    int t_r16 = (lid & 7) + ((lid >> 3) & 1) * 8;   // kv offset within 16
    int t_cb  = ((lid >> 4) & 1) * 16;              // d byte offset (8 cols)

    int nkb = 2 * qb + 2;
    ATTN_ISSUE(0, 0);

    for (int kb = 0; kb < nkb; kb++) {
        if (kb + 1 < nkb) {
            ATTN_ISSUE((kb + 1) & 1, kb + 1);
            CP_WAIT(1);
        } else {
            CP_WAIT(0);
        }
        __syncthreads();

        if (kb * ABK <= warp_row + 15) {   // not fully masked
            u32 bk = sb + AKV + (kb & 1) * ASTG;
            u32 okh = bk, okl = bk + 8192, ovh = bk + 16384, ovl = bk + 24576;

            // ---- S = Q K^T (hi/lo, 3 passes) ----
            float s[8][4];
#pragma unroll
            for (int nt = 0; nt < 8; nt++)
#pragma unroll
                for (int e = 0; e < 4; e++) s[nt][e] = 0.f;

#pragma unroll
            for (int kc = 0; kc < 4; kc++) {
                u32 af[4], bhf[8][2], blf[8][2];
                u32 arow = (u32)((wid * 16 + a_r) * 128 + (kc * 2 + a_h) * 16);
                ldsm_x4(af[0], af[1], af[2], af[3], sb + OQH + SWZ128(arow));
#pragma unroll
                for (int g = 0; g < 4; g++) {
                    int n = g * 16 + b_n;
                    u32 off = SWZ128((u32)(n * 128 + (kc * 2 + b_h) * 16));
                    ldsm_x4(bhf[g * 2][0], bhf[g * 2][1],
                            bhf[g * 2 + 1][0], bhf[g * 2 + 1][1], okh + off);
                    ldsm_x4(blf[g * 2][0], blf[g * 2][1],
                            blf[g * 2 + 1][0], blf[g * 2 + 1][1], okl + off);
                }
#pragma unroll
                for (int nt = 0; nt < 8; nt++) mma_bf16(s[nt], af, bhf[nt]);
#pragma unroll
                for (int nt = 0; nt < 8; nt++) mma_bf16(s[nt], af, blf[nt]);
                ldsm_x4(af[0], af[1], af[2], af[3], sb + OQL + SWZ128(arow));
#pragma unroll
                for (int nt = 0; nt < 8; nt++) mma_bf16(s[nt], af, bhf[nt]);
            }

            // ---- scale (base-2) + causal mask ----
            bool needmask = (kb * ABK + ABK - 1 > warp_row);
#pragma unroll
            for (int nt = 0; nt < 8; nt++) {
#pragma unroll
                for (int e = 0; e < 4; e++) {
                    s[nt][e] *= scale2;
                    if (needmask) {
                        int row = warp_row + r1 + ((e >> 1) << 3);
                        int col = kb * ABK + nt * 8 + (lid & 3) * 2 + (e & 1);
                        if (col > row) s[nt][e] = -INFINITY;
                    }
                }
            }

            // ---- online softmax in base-2 (rows r1, r1+8) ----
#pragma unroll
            for (int half = 0; half < 2; half++) {
                float mx = -INFINITY;
#pragma unroll
                for (int nt = 0; nt < 8; nt++)
                    mx = fmaxf(mx, fmaxf(s[nt][half * 2], s[nt][half * 2 + 1]));
                mx = fmaxf(mx, __shfl_xor_sync(0xffffffffu, mx, 1));
                mx = fmaxf(mx, __shfl_xor_sync(0xffffffffu, mx, 2));
                float m_new = fmaxf(m_i[half], mx);
                float corr = ex2(m_i[half] - m_new);
                m_i[half] = m_new;
                float rs = 0.f;
#pragma unroll
                for (int nt = 0; nt < 8; nt++) {
                    float p0 = ex2(s[nt][half * 2] - m_new);
                    float p1 = ex2(s[nt][half * 2 + 1] - m_new);
                    s[nt][half * 2] = p0;
                    s[nt][half * 2 + 1] = p1;
                    rs += p0 + p1;
                }
                rs += __shfl_xor_sync(0xffffffffu, rs, 1);
                rs += __shfl_xor_sync(0xffffffffu, rs, 2);
                l_i[half] = l_i[half] * corr + rs;
#pragma unroll
                for (int nt = 0; nt < 8; nt++) {
                    o[nt][half * 2] *= corr;
                    o[nt][half * 2 + 1] *= corr;
                }
            }

            // ---- O += P V (hi/lo, 3 passes); V fragments via ldmatrix.trans
            //      from row-major [kv][d] tile ----
#pragma unroll
            for (int kc = 0; kc < 4; kc++) {
                u32 ph[4], pl[4];
                pack_hl(s[2 * kc][0], s[2 * kc][1], ph[0], pl[0]);
                pack_hl(s[2 * kc][2], s[2 * kc][3], ph[1], pl[1]);
                pack_hl(s[2 * kc + 1][0], s[2 * kc + 1][1], ph[2], pl[2]);
                pack_hl(s[2 * kc + 1][2], s[2 * kc + 1][3], ph[3], pl[3]);

                u32 bvh[8][2], bvl[8][2];
                u32 trow = (u32)((kc * 16 + t_r16) * 128);
#pragma unroll
                for (int g = 0; g < 4; g++) {
                    u32 off = SWZ128(trow + g * 32 + t_cb);
                    ldsm_x4t(bvh[g * 2][0], bvh[g * 2][1],
                             bvh[g * 2 + 1][0], bvh[g * 2 + 1][1], ovh + off);
                    ldsm_x4t(bvl[g * 2][0], bvl[g * 2][1],
                             bvl[g * 2 + 1][0], bvl[g * 2 + 1][1], ovl + off);
                }
#pragma unroll
                for (int nt = 0; nt < 8; nt++) mma_bf16(o[nt], ph, bvh[nt]);
#pragma unroll
                for (int nt = 0; nt < 8; nt++) mma_bf16(o[nt], ph, bvl[nt]);
#pragma unroll
                for (int nt = 0; nt < 8; nt++) mma_bf16(o[nt], pl, bvh[nt]);
            }
        }
        __syncthreads();
    }

    // ---- epilogue: normalize, split to hi/lo bf16, store ----
#pragma unroll
    for (int half = 0; half < 2; half++) {
        float inv = 1.f / l_i[half];
        int row = warp_row + r1 + half * 8;
        size_t base = (size_t)(b * SEQ + row) * EMB + h * HD;
#pragma unroll
        for (int nt = 0; nt < 8; nt++) {
            int col = nt * 8 + (lid & 3) * 2;
            float v0 = o[nt][half * 2] * inv;
            float v1 = o[nt][half * 2 + 1] * inv;
            u32 hi, lo;
            pack_hl(v0, v1, hi, lo);
            *(u32*)&aoh[base + col] = hi;
            *(u32*)&aol[base + col] = lo;
        }
    }
}

// ---------------------------------------------------------------------------
// Launch
// ---------------------------------------------------------------------------
extern "C" void kernel_launch(void* const* d_in, const int* in_sizes, int n_in,
                              void* d_out, int out_size)
{
    const float* x  = (const float*)d_in[0];
    const float* Wq = (const float*)d_in[1];
    const float* bq = (const float*)d_in[2];
    const float* Wk = (const float*)d_in[3];
    const float* bk = (const float*)d_in[4];
    const float* Wv = (const float*)d_in[5];
    const float* bv = (const float*)d_in[6];
    const float* Wo = (const float*)d_in[7];
    const float* bo = (const float*)d_in[8];
    float* out = (float*)d_out;

    __nv_bfloat16 *ah, *al, *bh, *bl, *qh, *ql, *kh, *kl, *vh, *vl;
    cudaGetSymbolAddress((void**)&ah, g_ah);
    cudaGetSymbolAddress((void**)&al, g_al);
    cudaGetSymbolAddress((void**)&bh, g_bh);
    cudaGetSymbolAddress((void**)&bl, g_bl);
    cudaGetSymbolAddress((void**)&qh, g_qh);
    cudaGetSymbolAddress((void**)&ql, g_ql);
    cudaGetSymbolAddress((void**)&kh, g_kh);
    cudaGetSymbolAddress((void**)&kl, g_kl);
    cudaGetSymbolAddress((void**)&vh, g_vh);
    cudaGetSymbolAddress((void**)&vl, g_vl);

    cudaFuncSetAttribute(gemm_mma,
                         cudaFuncAttributeMaxDynamicSharedMemorySize, GSMEM);
    cudaFuncSetAttribute(flash_attn_tc,
                         cudaFuncAttributeMaxDynamicSharedMemorySize, ASMEM);

    dim3 ct(32, 8);
    dim3 cg6(EMB / 32, EMB / 32, 6);            // 4 weights + 2 x-halves
    dim3 qkvgrid(3 * EMB / 128, MROWS / 128);   // (48, 32): fused Q,K,V
    dim3 ogrid(EMB / 128, MROWS / 128);         // (16, 32): out proj
    dim3 agrid(SEQ / ABQ, NH, BSZ);             // (16, 32, 2)

    // one fused conversion launch: W^T hi/lo x4 + x split hi/lo
    conv_all<<<cg6, ct>>>(Wq, Wk, Wv, Wo, x, bh, bl, ah, al);

    // fused QKV projection -> bf16 hi/lo
    gemm_mma<<<qkvgrid, 256, GSMEM>>>(ah, al, bh, bl, bq, bk, bv, bo,
                                      qh, ql, kh, kl, vh, vl, NULL, 0,
                                      MROWS, EMB);

    // attention -> hi/lo into ah/al; V read directly (ldmatrix.trans)
    flash_attn_tc<<<agrid, 256, ASMEM>>>(qh, ql, kh, kl, vh, vl, ah, al);

    // output projection (mat 3, fp32 out)
    gemm_mma<<<ogrid, 256, GSMEM>>>(ah, al, bh, bl, bq, bk, bv, bo,
                                    qh, ql, kh, kl, vh, vl, out, 3,
                                    MROWS, EMB);
}

// round 13
// speedup vs baseline: 1.4007x; 1.2150x over previous
#include <cuda_runtime.h>
#include <cuda_bf16.h>
#include <cuda_fp16.h>
#include <cstdint>
#include <math.h>

typedef unsigned int u32;
typedef unsigned long long u64;
typedef unsigned short u16;

#define BSZ 2
#define SEQ 2048
#define EMB 2048
#define NH 32
#define HD 64
#define MROWS (BSZ*SEQ)
#define RSC 64.0f          // residual scale (2^6)
#define IRSC 0.015625f     // 1/64

// ---------------------------------------------------------------------------
// Scratch (device globals: allocation-free per harness rules)
// g_af/g_as: fp16 A operand (x, later attention-out) + /64 copy
// g_bh/g_bl: fp16 W^T hi + (residual*64), x4 weights
// q/k/v: bf16 hi/lo (attention kernel unchanged)
// ---------------------------------------------------------------------------
__device__ __align__(16) u16 g_af[(size_t)MROWS * EMB];
__device__ __align__(16) u16 g_as[(size_t)MROWS * EMB];
__device__ __align__(16) u16 g_bh[(size_t)4 * EMB * EMB];
__device__ __align__(16) u16 g_bl[(size_t)4 * EMB * EMB];
__device__ __align__(16) __nv_bfloat16 g_qh[(size_t)MROWS * EMB];
__device__ __align__(16) __nv_bfloat16 g_ql[(size_t)MROWS * EMB];
__device__ __align__(16) __nv_bfloat16 g_kh[(size_t)MROWS * EMB];
__device__ __align__(16) __nv_bfloat16 g_kl[(size_t)MROWS * EMB];
__device__ __align__(16) __nv_bfloat16 g_vh[(size_t)MROWS * EMB];
__device__ __align__(16) __nv_bfloat16 g_vl[(size_t)MROWS * EMB];

// ---------------------------------------------------------------------------
// Warp-MMA / cp.async helpers (baseline PTX: works on plain sm_103 target)
// ---------------------------------------------------------------------------
__device__ __forceinline__ u32 smem_u32(const void* p) {
    u32 a;
    asm("{ .reg .u64 t; cvta.to.shared.u64 t, %1; cvt.u32.u64 %0, t; }"
        : "=r"(a) : "l"(p));
    return a;
}
__device__ __forceinline__ void ldsm_x4(u32& r0, u32& r1, u32& r2, u32& r3,
                                        u32 addr) {
    asm volatile("ldmatrix.sync.aligned.m8n8.x4.shared.b16 {%0,%1,%2,%3}, [%4];"
                 : "=r"(r0), "=r"(r1), "=r"(r2), "=r"(r3) : "r"(addr));
}
__device__ __forceinline__ void ldsm_x4t(u32& r0, u32& r1, u32& r2, u32& r3,
                                         u32 addr) {
    asm volatile("ldmatrix.sync.aligned.m8n8.x4.trans.shared.b16 {%0,%1,%2,%3}, [%4];"
                 : "=r"(r0), "=r"(r1), "=r"(r2), "=r"(r3) : "r"(addr));
}
__device__ __forceinline__ void mma_bf16(float* d, const u32* a, const u32* b) {
    asm volatile(
        "mma.sync.aligned.m16n8k16.row.col.f32.bf16.bf16.f32 "
        "{%0,%1,%2,%3}, {%4,%5,%6,%7}, {%8,%9}, {%0,%1,%2,%3};"
        : "+f"(d[0]), "+f"(d[1]), "+f"(d[2]), "+f"(d[3])
        : "r"(a[0]), "r"(a[1]), "r"(a[2]), "r"(a[3]), "r"(b[0]), "r"(b[1]));
}
__device__ __forceinline__ void mma_f16(float* d, const u32* a, const u32* b) {
    asm volatile(
        "mma.sync.aligned.m16n8k16.row.col.f32.f16.f16.f32 "
        "{%0,%1,%2,%3}, {%4,%5,%6,%7}, {%8,%9}, {%0,%1,%2,%3};"
        : "+f"(d[0]), "+f"(d[1]), "+f"(d[2]), "+f"(d[3])
        : "r"(a[0]), "r"(a[1]), "r"(a[2]), "r"(a[3]), "r"(b[0]), "r"(b[1]));
}
__device__ __forceinline__ void cp16(u32 dst, const void* src) {
    asm volatile("cp.async.cg.shared.global [%0], [%1], 16;"
                 :: "r"(dst), "l"(src) : "memory");
}
#define CP_COMMIT() asm volatile("cp.async.commit_group;" ::: "memory")
#define CP_WAIT(n)  asm volatile("cp.async.wait_group %0;" :: "n"(n) : "memory")

// raw exp2 (single MUFU; inputs pre-scaled to base-2 domain)
__device__ __forceinline__ float ex2(float x) {
    float y;
    asm("ex2.approx.f32 %0, %1;" : "=f"(y) : "f"(x));
    return y;
}

// pack two fp32 -> bf16x2 + bf16x2 residuals (attention path)
__device__ __forceinline__ void pack_hl(float x0, float x1, u32& hi, u32& lo) {
    asm("cvt.rn.bf16x2.f32 %0, %1, %2;" : "=r"(hi) : "f"(x1), "f"(x0));
    float h0 = __uint_as_float(hi << 16);
    float h1 = __uint_as_float(hi & 0xFFFF0000u);
    float r0 = x0 - h0, r1 = x1 - h1;
    asm("cvt.rn.bf16x2.f32 %0, %1, %2;" : "=r"(lo) : "f"(r1), "f"(r0));
}
// pack two fp32 -> fp16x2 and fp16x2 of (x/64)  (GEMM A-operand path)
__device__ __forceinline__ void pack_fs(float x0, float x1, u32& f, u32& s) {
    __half2 hf = __float22half2_rn(make_float2(x0, x1));
    __half2 hs = __float22half2_rn(make_float2(x0 * IRSC, x1 * IRSC));
    f = *(u32*)&hf;
    s = *(u32*)&hs;
}
#define SWZ64(o)  ((o) ^ (((o) >> 3) & 0x30))
#define SWZ128(o) ((o) ^ (((o) >> 3) & 0x70))

// ---------------------------------------------------------------------------
// Fused conversion:
//   z=0..3 -> W_z^T: fp16 hi + fp16(residual*64)
//   z=4,5  -> x: fp16 single + fp16(x/64)
// ---------------------------------------------------------------------------
__global__ void conv_all(const float* __restrict__ W0, const float* __restrict__ W1,
                         const float* __restrict__ W2, const float* __restrict__ W3,
                         const float* __restrict__ X,
                         u16* __restrict__ Th, u16* __restrict__ Tl,
                         u16* __restrict__ XF, u16* __restrict__ XS)
{
    int z = blockIdx.z;
    if (z >= 4) {
        int t = threadIdx.y * 32 + threadIdx.x;
        size_t i = ((size_t)(z - 4) * 4096 + blockIdx.y * 64 + blockIdx.x) * 256 + t;
        float4 v = ((const float4*)X)[i];
        u32 f0, s0, f1, s1;
        pack_fs(v.x, v.y, f0, s0);
        pack_fs(v.z, v.w, f1, s1);
        ((uint2*)XF)[i] = make_uint2(f0, f1);
        ((uint2*)XS)[i] = make_uint2(s0, s1);
        return;
    }
    __shared__ float t[32][33];
    const float* W = (z == 0) ? W0 : (z == 1) ? W1 : (z == 2) ? W2 : W3;
    size_t zo = (size_t)z * EMB * EMB;
    int n0 = blockIdx.x * 32, k0 = blockIdx.y * 32;
    int x = threadIdx.x, y = threadIdx.y;  // 32 x 8
#pragma unroll
    for (int r = 0; r < 32; r += 8)
        t[y + r][x] = W[(size_t)(k0 + y + r) * EMB + n0 + x];
    __syncthreads();
#pragma unroll
    for (int r = 0; r < 32; r += 8) {
        float v = t[x][y + r];
        __half h = __float2half_rn(v);
        float res = (v - __half2float(h)) * RSC;
        __half l = __float2half_rn(res);
        size_t o = zo + (size_t)(n0 + y + r) * EMB + k0 + x;
        Th[o] = *(u16*)&h;
        Tl[o] = *(u16*)&l;
    }
}

// ---------------------------------------------------------------------------
// Tensor-core GEMM, fp16 2-pass scaled-residual:
//   D = Af * Bh + (A/64) * (Bres*64)   (exactly A_f16 * W to ~22 bits on W)
// cp.async 3-stage pipeline, single sync/iter. 128x128, 256 thr, 2 CTAs/SM.
// mats 0,1,2 -> bf16 hi/lo (Q,K,V for attention); mat 3 -> fp32 C.
// Stage layout (32 KB): AF 0, AS 8192, BH 16384, BL 24576.
// ---------------------------------------------------------------------------
#define BKC 32
#define GSTG 32768
#define GSMEM (3 * GSTG)

__global__ __launch_bounds__(256, 2)
void gemm_mma(const u16* __restrict__ Af,
              const u16* __restrict__ As,
              const u16* __restrict__ BhAll,
              const u16* __restrict__ BlAll,
              const float* __restrict__ b0, const float* __restrict__ b1,
              const float* __restrict__ b2, const float* __restrict__ b3,
              __nv_bfloat16* __restrict__ H0, __nv_bfloat16* __restrict__ L0,
              __nv_bfloat16* __restrict__ H1, __nv_bfloat16* __restrict__ L1,
              __nv_bfloat16* __restrict__ H2, __nv_bfloat16* __restrict__ L2,
              float* __restrict__ C, int mat_base, int M, int K)
{
    extern __shared__ char smg[];
    u32 sb = smem_u32(smg);
    const int N = EMB;

    int tid = threadIdx.x;
    int wid = tid / 32, lid = tid % 32;
    int wm = wid / 4, wn = wid % 4;        // warp grid 2 x 4
    int mat = mat_base + (blockIdx.x >> 4);
    int bm = blockIdx.y * 128, bn = (blockIdx.x & 15) * 128;

    const u16* Bh = BhAll + (size_t)mat * EMB * EMB;
    const u16* Bl = BlAll + (size_t)mat * EMB * EMB;
    const float* bias = (mat == 0) ? b0 : (mat == 1) ? b1 : (mat == 2) ? b2 : b3;

    float acc[4][4][4];
#pragma unroll
    for (int mt = 0; mt < 4; mt++)
#pragma unroll
        for (int nt = 0; nt < 4; nt++)
#pragma unroll
            for (int e = 0; e < 4; e++) acc[mt][nt][e] = 0.f;

    int a_r = (lid & 15);
    int a_h = (lid >> 4);
    int b_n = ((lid >> 4) << 3) + (lid & 7);
    int b_h = ((lid >> 3) & 1);

    int l_row[2], l_ch[2];
#pragma unroll
    for (int cc = 0; cc < 2; cc++) {
        int c = tid + cc * 256;
        l_row[cc] = c >> 2;
        l_ch[cc] = c & 3;
    }

#define GEMM_ISSUE(stage, k0)                                                  \
    do {                                                                       \
        u32 base_ = sb + (stage) * GSTG;                                       \
        _Pragma("unroll")                                                      \
        for (int cc = 0; cc < 2; cc++) {                                       \
            int row = l_row[cc], ch = l_ch[cc];                                \
            u32 so = SWZ64((u32)(row * 64 + ch * 16));                         \
            size_t ga = (size_t)(bm + row) * K + (k0) + ch * 8;                \
            size_t gb = (size_t)(bn + row) * K + (k0) + ch * 8;                \
            cp16(base_ + so, Af + ga);                                         \
            cp16(base_ + 8192 + so, As + ga);                                  \
            cp16(base_ + 16384 + so, Bh + gb);                                 \
            cp16(base_ + 24576 + so, Bl + gb);                                 \
        }                                                                      \
        CP_COMMIT();                                                           \
    } while (0)

    int niter = K / BKC;
    GEMM_ISSUE(0, 0);
    GEMM_ISSUE(1, BKC);

    for (int it = 0; it < niter; it++) {
        if (it + 1 < niter) {
            CP_WAIT(1);
        } else {
            CP_WAIT(0);
        }
        __syncthreads();
        if (it + 2 < niter)
            GEMM_ISSUE((it + 2) % 3, (it + 2) * BKC);

        u32 baseAf = sb + (it % 3) * GSTG;
        u32 baseAs = baseAf + 8192;
        u32 baseBh = baseAf + 16384;
        u32 baseBl = baseAf + 24576;

#pragma unroll
        for (int ks = 0; ks < 2; ks++) {
            u32 af[4][4], bhf[4][2], blf[4][2];
#pragma unroll
            for (int mt = 0; mt < 4; mt++) {
                int r = wm * 64 + mt * 16 + a_r;
                u32 addr = baseAf + SWZ64((u32)(r * 64 + (ks * 2 + a_h) * 16));
                ldsm_x4(af[mt][0], af[mt][1], af[mt][2], af[mt][3], addr);
            }
#pragma unroll
            for (int np = 0; np < 2; np++) {
                int n = wn * 32 + np * 16 + b_n;
                u32 off = SWZ64((u32)(n * 64 + (ks * 2 + b_h) * 16));
                ldsm_x4(bhf[np * 2][0], bhf[np * 2][1],
                        bhf[np * 2 + 1][0], bhf[np * 2 + 1][1], baseBh + off);
                ldsm_x4(blf[np * 2][0], blf[np * 2][1],
                        blf[np * 2 + 1][0], blf[np * 2 + 1][1], baseBl + off);
            }
            // pass 1: Af * Bh
#pragma unroll
            for (int mt = 0; mt < 4; mt++)
#pragma unroll
                for (int nt = 0; nt < 4; nt++)
                    mma_f16(acc[mt][nt], af[mt], bhf[nt]);
            // reload A-scaled into af, pass 2: (A/64) * (Bres*64)
#pragma unroll
            for (int mt = 0; mt < 4; mt++) {
                int r = wm * 64 + mt * 16 + a_r;
                u32 addr = baseAs + SWZ64((u32)(r * 64 + (ks * 2 + a_h) * 16));
                ldsm_x4(af[mt][0], af[mt][1], af[mt][2], af[mt][3], addr);
            }
#pragma unroll
            for (int mt = 0; mt < 4; mt++)
#pragma unroll
                for (int nt = 0; nt < 4; nt++)
                    mma_f16(acc[mt][nt], af[mt], blf[nt]);
        }
    }

    __nv_bfloat16* H = (mat == 0) ? H0 : (mat == 1) ? H1 : H2;
    __nv_bfloat16* L = (mat == 0) ? L0 : (mat == 1) ? L1 : L2;

    int rr = lid >> 2, cc2 = (lid & 3) * 2;
#pragma unroll
    for (int mt = 0; mt < 4; mt++) {
        int r0 = bm + wm * 64 + mt * 16 + rr;
#pragma unroll
        for (int nt = 0; nt < 4; nt++) {
            int col = bn + wn * 32 + nt * 8 + cc2;
            float bb0 = bias[col], bb1 = bias[col + 1];
            float v00 = acc[mt][nt][0] + bb0, v01 = acc[mt][nt][1] + bb1;
            float v10 = acc[mt][nt][2] + bb0, v11 = acc[mt][nt][3] + bb1;
            if (mat == 3) {
                *(float2*)&C[(size_t)r0 * N + col] = make_float2(v00, v01);
                *(float2*)&C[(size_t)(r0 + 8) * N + col] = make_float2(v10, v11);
            } else {
                u32 hi, lo;
                pack_hl(v00, v01, hi, lo);
                *(u32*)&H[(size_t)r0 * N + col] = hi;
                *(u32*)&L[(size_t)r0 * N + col] = lo;
                pack_hl(v10, v11, hi, lo);
                *(u32*)&H[(size_t)(r0 + 8) * N + col] = hi;
                *(u32*)&L[(size_t)(r0 + 8) * N + col] = lo;
            }
        }
    }
}

// ---------------------------------------------------------------------------
// Tensor-core causal flash attention (bf16 hi/lo 3-pass, fp32 base-2 softmax),
// cp.async 2-stage K/V pipeline, V via ldmatrix.trans.
// Epilogue now emits fp16 single + fp16/64 (A-operands for the out-proj).
// RoPE mathematically eliminated (head-only rotation; q.k invariant).
// ---------------------------------------------------------------------------
#define ABQ 128
#define ABK 64
#define OQH 0
#define OQL 16384
#define AKV 32768
#define ASTG 32768
#define ASMEM (AKV + 2 * ASTG)

__global__ __launch_bounds__(256, 2)
void flash_attn_tc(const __nv_bfloat16* __restrict__ qh_,
                   const __nv_bfloat16* __restrict__ ql_,
                   const __nv_bfloat16* __restrict__ kh_,
                   const __nv_bfloat16* __restrict__ kl_,
                   const __nv_bfloat16* __restrict__ vh_,
                   const __nv_bfloat16* __restrict__ vl_,
                   u16* __restrict__ aof, u16* __restrict__ aos)
{
    extern __shared__ char smc[];
    u32 sb = smem_u32(smc);
    int tid = threadIdx.x, wid = tid / 32, lid = tid % 32;
    int qb = gridDim.x - 1 - blockIdx.x;   // longest work first
    int h = blockIdx.y, b = blockIdx.z;
    int q0 = qb * ABQ;
    int warp_row = q0 + wid * 16;

#pragma unroll
    for (int i = 0; i < 4; i++) {
        int c = tid + i * 256;
        int r = c >> 3, ch = c & 7;
        u32 so = SWZ128((u32)(r * 128 + ch * 16));
        size_t g = (size_t)(b * SEQ + q0 + r) * EMB + h * HD + ch * 8;
        *(uint4*)(smc + OQH + so) = *(const uint4*)(qh_ + g);
        *(uint4*)(smc + OQL + so) = *(const uint4*)(ql_ + g);
    }

    int v_r[2], v_ch[2];
#pragma unroll
    for (int i = 0; i < 2; i++) {
        int c = tid + i * 256;
        v_r[i] = c >> 3;
        v_ch[i] = c & 7;
    }

#define ATTN_ISSUE(stage, kb)                                                  \
    do {                                                                       \
        u32 base_ = sb + AKV + (stage) * ASTG;                                 \
        _Pragma("unroll")                                                      \
        for (int i = 0; i < 2; i++) {                                          \
            int r = v_r[i], ch = v_ch[i];                                      \
            u32 so = SWZ128((u32)(r * 128 + ch * 16));                         \
            size_t gk = (size_t)(b * SEQ + (kb) * ABK + r) * EMB + h * HD + ch * 8; \
            cp16(base_ + so, kh_ + gk);                                        \
            cp16(base_ + 8192 + so, kl_ + gk);                                 \
            cp16(base_ + 16384 + so, vh_ + gk);                                \
            cp16(base_ + 24576 + so, vl_ + gk);                                \
        }                                                                      \
        CP_COMMIT();                                                           \
    } while (0)

    float m_i[2], l_i[2], o[8][4];
    m_i[0] = m_i[1] = -INFINITY;
    l_i[0] = l_i[1] = 0.f;
#pragma unroll
    for (int nt = 0; nt < 8; nt++)
#pragma unroll
        for (int e = 0; e < 4; e++) o[nt][e] = 0.f;

    const float scale2 = 0.125f * 1.4426950408889634f;  // base-2 softmax
    int r1 = lid >> 2;
    int a_r = lid & 15, a_h = lid >> 4;
    int b_n = ((lid >> 4) << 3) + (lid & 7), b_h = (lid >> 3) & 1;
    int t_r16 = (lid & 7) + ((lid >> 3) & 1) * 8;
    int t_cb  = ((lid >> 4) & 1) * 16;

    int nkb = 2 * qb + 2;
    ATTN_ISSUE(0, 0);

    for (int kb = 0; kb < nkb; kb++) {
        if (kb + 1 < nkb) {
            ATTN_ISSUE((kb + 1) & 1, kb + 1);
            CP_WAIT(1);
        } else {
            CP_WAIT(0);
        }
        __syncthreads();

        if (kb * ABK <= warp_row + 15) {
            u32 bk = sb + AKV + (kb & 1) * ASTG;
            u32 okh = bk, okl = bk + 8192, ovh = bk + 16384, ovl = bk + 24576;

            float s[8][4];
#pragma unroll
            for (int nt = 0; nt < 8; nt++)
#pragma unroll
                for (int e = 0; e < 4; e++) s[nt][e] = 0.f;

#pragma unroll
            for (int kc = 0; kc < 4; kc++) {
                u32 af[4], bhf[8][2], blf[8][2];
                u32 arow = (u32)((wid * 16 + a_r) * 128 + (kc * 2 + a_h) * 16);
                ldsm_x4(af[0], af[1], af[2], af[3], sb + OQH + SWZ128(arow));
#pragma unroll
                for (int g = 0; g < 4; g++) {
                    int n = g * 16 + b_n;
                    u32 off = SWZ128((u32)(n * 128 + (kc * 2 + b_h) * 16));
                    ldsm_x4(bhf[g * 2][0], bhf[g * 2][1],
                            bhf[g * 2 + 1][0], bhf[g * 2 + 1][1], okh + off);
                    ldsm_x4(blf[g * 2][0], blf[g * 2][1],
                            blf[g * 2 + 1][0], blf[g * 2 + 1][1], okl + off);
                }
#pragma unroll
                for (int nt = 0; nt < 8; nt++) mma_bf16(s[nt], af, bhf[nt]);
#pragma unroll
                for (int nt = 0; nt < 8; nt++) mma_bf16(s[nt], af, blf[nt]);
                ldsm_x4(af[0], af[1], af[2], af[3], sb + OQL + SWZ128(arow));
#pragma unroll
                for (int nt = 0; nt < 8; nt++) mma_bf16(s[nt], af, bhf[nt]);
            }

            bool needmask = (kb * ABK + ABK - 1 > warp_row);
#pragma unroll
            for (int nt = 0; nt < 8; nt++) {
#pragma unroll
                for (int e = 0; e < 4; e++) {
                    s[nt][e] *= scale2;
                    if (needmask) {
                        int row = warp_row + r1 + ((e >> 1) << 3);
                        int col = kb * ABK + nt * 8 + (lid & 3) * 2 + (e & 1);
                        if (col > row) s[nt][e] = -INFINITY;
                    }
                }
            }

#pragma unroll
            for (int half = 0; half < 2; half++) {
                float mx = -INFINITY;
#pragma unroll
                for (int nt = 0; nt < 8; nt++)
                    mx = fmaxf(mx, fmaxf(s[nt][half * 2], s[nt][half * 2 + 1]));
                mx = fmaxf(mx, __shfl_xor_sync(0xffffffffu, mx, 1));
                mx = fmaxf(mx, __shfl_xor_sync(0xffffffffu, mx, 2));
                float m_new = fmaxf(m_i[half], mx);
                float corr = ex2(m_i[half] - m_new);
                m_i[half] = m_new;
                float rs = 0.f;
#pragma unroll
                for (int nt = 0; nt < 8; nt++) {
                    float p0 = ex2(s[nt][half * 2] - m_new);
                    float p1 = ex2(s[nt][half * 2 + 1] - m_new);
                    s[nt][half * 2] = p0;
                    s[nt][half * 2 + 1] = p1;
                    rs += p0 + p1;
                }
                rs += __shfl_xor_sync(0xffffffffu, rs, 1);
                rs += __shfl_xor_sync(0xffffffffu, rs, 2);
                l_i[half] = l_i[half] * corr + rs;
#pragma unroll
                for (int nt = 0; nt < 8; nt++) {
                    o[nt][half * 2] *= corr;
                    o[nt][half * 2 + 1] *= corr;
                }
            }

#pragma unroll
            for (int kc = 0; kc < 4; kc++) {
                u32 ph[4], pl[4];
                pack_hl(s[2 * kc][0], s[2 * kc][1], ph[0], pl[0]);
                pack_hl(s[2 * kc][2], s[2 * kc][3], ph[1], pl[1]);
                pack_hl(s[2 * kc + 1][0], s[2 * kc + 1][1], ph[2], pl[2]);
                pack_hl(s[2 * kc + 1][2], s[2 * kc + 1][3], ph[3], pl[3]);

                u32 bvh[8][2], bvl[8][2];
                u32 trow = (u32)((kc * 16 + t_r16) * 128);
#pragma unroll
                for (int g = 0; g < 4; g++) {
                    u32 off = SWZ128(trow + g * 32 + t_cb);
                    ldsm_x4t(bvh[g * 2][0], bvh[g * 2][1],
                             bvh[g * 2 + 1][0], bvh[g * 2 + 1][1], ovh + off);
                    ldsm_x4t(bvl[g * 2][0], bvl[g * 2][1],
                             bvl[g * 2 + 1][0], bvl[g * 2 + 1][1], ovl + off);
                }
#pragma unroll
                for (int nt = 0; nt < 8; nt++) mma_bf16(o[nt], ph, bvh[nt]);
#pragma unroll
                for (int nt = 0; nt < 8; nt++) mma_bf16(o[nt], ph, bvl[nt]);
#pragma unroll
                for (int nt = 0; nt < 8; nt++) mma_bf16(o[nt], pl, bvh[nt]);
            }
        }
        __syncthreads();
    }

    // ---- epilogue: normalize, emit fp16 single + fp16/64 for out-proj ----
#pragma unroll
    for (int half = 0; half < 2; half++) {
        float inv = 1.f / l_i[half];
        int row = warp_row + r1 + half * 8;
        size_t base = (size_t)(b * SEQ + row) * EMB + h * HD;
#pragma unroll
        for (int nt = 0; nt < 8; nt++) {
            int col = nt * 8 + (lid & 3) * 2;
            float v0 = o[nt][half * 2] * inv;
            float v1 = o[nt][half * 2 + 1] * inv;
            u32 f, sreg;
            pack_fs(v0, v1, f, sreg);
            *(u32*)&aof[base + col] = f;
            *(u32*)&aos[base + col] = sreg;
        }
    }
}

// ---------------------------------------------------------------------------
// Launch
// ---------------------------------------------------------------------------
extern "C" void kernel_launch(void* const* d_in, const int* in_sizes, int n_in,
                              void* d_out, int out_size)
{
    const float* x  = (const float*)d_in[0];
    const float* Wq = (const float*)d_in[1];
    const float* bq = (const float*)d_in[2];
    const float* Wk = (const float*)d_in[3];
    const float* bk = (const float*)d_in[4];
    const float* Wv = (const float*)d_in[5];
    const float* bv = (const float*)d_in[6];
    const float* Wo = (const float*)d_in[7];
    const float* bo = (const float*)d_in[8];
    float* out = (float*)d_out;

    u16 *af, *as, *bh, *bl;
    __nv_bfloat16 *qh, *ql, *kh, *kl, *vh, *vl;
    cudaGetSymbolAddress((void**)&af, g_af);
    cudaGetSymbolAddress((void**)&as, g_as);
    cudaGetSymbolAddress((void**)&bh, g_bh);
    cudaGetSymbolAddress((void**)&bl, g_bl);
    cudaGetSymbolAddress((void**)&qh, g_qh);
    cudaGetSymbolAddress((void**)&ql, g_ql);
    cudaGetSymbolAddress((void**)&kh, g_kh);
    cudaGetSymbolAddress((void**)&kl, g_kl);
    cudaGetSymbolAddress((void**)&vh, g_vh);
    cudaGetSymbolAddress((void**)&vl, g_vl);

    cudaFuncSetAttribute(gemm_mma,
                         cudaFuncAttributeMaxDynamicSharedMemorySize, GSMEM);
    cudaFuncSetAttribute(flash_attn_tc,
                         cudaFuncAttributeMaxDynamicSharedMemorySize, ASMEM);

    dim3 ct(32, 8);
    dim3 cg6(EMB / 32, EMB / 32, 6);            // 4 weights + 2 x-halves
    dim3 qkvgrid(3 * EMB / 128, MROWS / 128);   // (48, 32): fused Q,K,V
    dim3 ogrid(EMB / 128, MROWS / 128);         // (16, 32): out proj
    dim3 agrid(SEQ / ABQ, NH, BSZ);             // (16, 32, 2)

    // one fused conversion launch: W^T fp16 hi/lo*64 x4 + x fp16 + x/64
    conv_all<<<cg6, ct>>>(Wq, Wk, Wv, Wo, x, bh, bl, af, as);

    // fused QKV projection (fp16 2-pass) -> bf16 hi/lo for attention
    gemm_mma<<<qkvgrid, 256, GSMEM>>>(af, as, bh, bl, bq, bk, bv, bo,
                                      qh, ql, kh, kl, vh, vl, NULL, 0,
                                      MROWS, EMB);

    // attention (bf16 3-pass) -> fp16 single + fp16/64 into af/as
    flash_attn_tc<<<agrid, 256, ASMEM>>>(qh, ql, kh, kl, vh, vl, af, as);

    // output projection (fp16 2-pass, mat 3, fp32 out)
    gemm_mma<<<ogrid, 256, GSMEM>>>(af, as, bh, bl, bq, bk, bv, bo,
                                    qh, ql, kh, kl, vh, vl, out, 3,
                                    MROWS, EMB);
}

// round 14
// speedup vs baseline: 1.5027x; 1.0728x over previous
#include <cuda_runtime.h>
#include <cuda_bf16.h>
#include <cuda_fp16.h>
#include <cstdint>
#include <math.h>

typedef unsigned int u32;
typedef unsigned long long u64;
typedef unsigned short u16;

#define BSZ 2
#define SEQ 2048
#define EMB 2048
#define NH 32
#define HD 64
#define MROWS (BSZ*SEQ)
#define RSC 64.0f          // residual scale (2^6)
#define IRSC 0.015625f     // 1/64

// ---------------------------------------------------------------------------
// Scratch (device globals: allocation-free per harness rules)
// g_af/g_as: fp16 A operand (x, later attention-out) + /64 copy
// g_bh/g_bl: fp16 W^T hi + (residual*64), x4 weights
// q: fp16 + fp16/64 (A-side); k,v: fp16 hi + res*64 (B-side)
// ---------------------------------------------------------------------------
__device__ __align__(16) u16 g_af[(size_t)MROWS * EMB];
__device__ __align__(16) u16 g_as[(size_t)MROWS * EMB];
__device__ __align__(16) u16 g_bh[(size_t)4 * EMB * EMB];
__device__ __align__(16) u16 g_bl[(size_t)4 * EMB * EMB];
__device__ __align__(16) u16 g_qf[(size_t)MROWS * EMB];
__device__ __align__(16) u16 g_qs[(size_t)MROWS * EMB];
__device__ __align__(16) u16 g_kf[(size_t)MROWS * EMB];
__device__ __align__(16) u16 g_ks[(size_t)MROWS * EMB];
__device__ __align__(16) u16 g_vf[(size_t)MROWS * EMB];
__device__ __align__(16) u16 g_vs[(size_t)MROWS * EMB];

// ---------------------------------------------------------------------------
// Warp-MMA / cp.async helpers (baseline PTX: works on plain sm_103 target)
// ---------------------------------------------------------------------------
__device__ __forceinline__ u32 smem_u32(const void* p) {
    u32 a;
    asm("{ .reg .u64 t; cvta.to.shared.u64 t, %1; cvt.u32.u64 %0, t; }"
        : "=r"(a) : "l"(p));
    return a;
}
__device__ __forceinline__ void ldsm_x4(u32& r0, u32& r1, u32& r2, u32& r3,
                                        u32 addr) {
    asm volatile("ldmatrix.sync.aligned.m8n8.x4.shared.b16 {%0,%1,%2,%3}, [%4];"
                 : "=r"(r0), "=r"(r1), "=r"(r2), "=r"(r3) : "r"(addr));
}
__device__ __forceinline__ void ldsm_x4t(u32& r0, u32& r1, u32& r2, u32& r3,
                                         u32 addr) {
    asm volatile("ldmatrix.sync.aligned.m8n8.x4.trans.shared.b16 {%0,%1,%2,%3}, [%4];"
                 : "=r"(r0), "=r"(r1), "=r"(r2), "=r"(r3) : "r"(addr));
}
__device__ __forceinline__ void mma_f16(float* d, const u32* a, const u32* b) {
    asm volatile(
        "mma.sync.aligned.m16n8k16.row.col.f32.f16.f16.f32 "
        "{%0,%1,%2,%3}, {%4,%5,%6,%7}, {%8,%9}, {%0,%1,%2,%3};"
        : "+f"(d[0]), "+f"(d[1]), "+f"(d[2]), "+f"(d[3])
        : "r"(a[0]), "r"(a[1]), "r"(a[2]), "r"(a[3]), "r"(b[0]), "r"(b[1]));
}
__device__ __forceinline__ void cp16(u32 dst, const void* src) {
    asm volatile("cp.async.cg.shared.global [%0], [%1], 16;"
                 :: "r"(dst), "l"(src) : "memory");
}
#define CP_COMMIT() asm volatile("cp.async.commit_group;" ::: "memory")
#define CP_WAIT(n)  asm volatile("cp.async.wait_group %0;" :: "n"(n) : "memory")

// raw exp2 (single MUFU; inputs pre-scaled to base-2 domain)
__device__ __forceinline__ float ex2(float x) {
    float y;
    asm("ex2.approx.f32 %0, %1;" : "=f"(y) : "f"(x));
    return y;
}

// pack two fp32 -> fp16x2 and fp16x2 of (x/64)   (A-side operands)
__device__ __forceinline__ void pack_fs(float x0, float x1, u32& f, u32& s) {
    __half2 hf = __float22half2_rn(make_float2(x0, x1));
    __half2 hs = __float22half2_rn(make_float2(x0 * IRSC, x1 * IRSC));
    f = *(u32*)&hf;
    s = *(u32*)&hs;
}
// pack two fp32 -> fp16x2 hi and fp16x2 of (residual*64)   (B-side operands)
__device__ __forceinline__ void pack_hr(float x0, float x1, u32& h, u32& r) {
    __half2 hh = __float22half2_rn(make_float2(x0, x1));
    float r0 = (x0 - __half2float(__low2half(hh))) * RSC;
    float r1 = (x1 - __half2float(__high2half(hh))) * RSC;
    __half2 hr = __float22half2_rn(make_float2(r0, r1));
    h = *(u32*)&hh;
    r = *(u32*)&hr;
}
#define SWZ64(o)  ((o) ^ (((o) >> 3) & 0x30))
#define SWZ128(o) ((o) ^ (((o) >> 3) & 0x70))

// ---------------------------------------------------------------------------
// Fused conversion:
//   z=0..3 -> W_z^T: fp16 hi + fp16(residual*64)
//   z=4,5  -> x: fp16 single + fp16(x/64)
// ---------------------------------------------------------------------------
__global__ void conv_all(const float* __restrict__ W0, const float* __restrict__ W1,
                         const float* __restrict__ W2, const float* __restrict__ W3,
                         const float* __restrict__ X,
                         u16* __restrict__ Th, u16* __restrict__ Tl,
                         u16* __restrict__ XF, u16* __restrict__ XS)
{
    int z = blockIdx.z;
    if (z >= 4) {
        int t = threadIdx.y * 32 + threadIdx.x;
        size_t i = ((size_t)(z - 4) * 4096 + blockIdx.y * 64 + blockIdx.x) * 256 + t;
        float4 v = ((const float4*)X)[i];
        u32 f0, s0, f1, s1;
        pack_fs(v.x, v.y, f0, s0);
        pack_fs(v.z, v.w, f1, s1);
        ((uint2*)XF)[i] = make_uint2(f0, f1);
        ((uint2*)XS)[i] = make_uint2(s0, s1);
        return;
    }
    __shared__ float t[32][33];
    const float* W = (z == 0) ? W0 : (z == 1) ? W1 : (z == 2) ? W2 : W3;
    size_t zo = (size_t)z * EMB * EMB;
    int n0 = blockIdx.x * 32, k0 = blockIdx.y * 32;
    int x = threadIdx.x, y = threadIdx.y;  // 32 x 8
#pragma unroll
    for (int r = 0; r < 32; r += 8)
        t[y + r][x] = W[(size_t)(k0 + y + r) * EMB + n0 + x];
    __syncthreads();
#pragma unroll
    for (int r = 0; r < 32; r += 8) {
        float v = t[x][y + r];
        __half h = __float2half_rn(v);
        float res = (v - __half2float(h)) * RSC;
        __half l = __float2half_rn(res);
        size_t o = zo + (size_t)(n0 + y + r) * EMB + k0 + x;
        Th[o] = *(u16*)&h;
        Tl[o] = *(u16*)&l;
    }
}

// ---------------------------------------------------------------------------
// Tensor-core GEMM, fp16 2-pass scaled-residual:
//   D = Af * Bh + (A/64) * (Bres*64)
// cp.async 3-stage pipeline, single sync/iter. 128x128, 256 thr, 2 CTAs/SM.
// mat 0 -> Q as (fp16, fp16/64); mats 1,2 -> K,V as (fp16 hi, res*64);
// mat 3 -> fp32 C.
// Stage layout (32 KB): AF 0, AS 8192, BH 16384, BL 24576.
// ---------------------------------------------------------------------------
#define BKC 32
#define GSTG 32768
#define GSMEM (3 * GSTG)

__global__ __launch_bounds__(256, 2)
void gemm_mma(const u16* __restrict__ Af,
              const u16* __restrict__ As,
              const u16* __restrict__ BhAll,
              const u16* __restrict__ BlAll,
              const float* __restrict__ b0, const float* __restrict__ b1,
              const float* __restrict__ b2, const float* __restrict__ b3,
              u16* __restrict__ H0, u16* __restrict__ L0,
              u16* __restrict__ H1, u16* __restrict__ L1,
              u16* __restrict__ H2, u16* __restrict__ L2,
              float* __restrict__ C, int mat_base, int M, int K)
{
    extern __shared__ char smg[];
    u32 sb = smem_u32(smg);
    const int N = EMB;

    int tid = threadIdx.x;
    int wid = tid / 32, lid = tid % 32;
    int wm = wid / 4, wn = wid % 4;        // warp grid 2 x 4
    int mat = mat_base + (blockIdx.x >> 4);
    int bm = blockIdx.y * 128, bn = (blockIdx.x & 15) * 128;

    const u16* Bh = BhAll + (size_t)mat * EMB * EMB;
    const u16* Bl = BlAll + (size_t)mat * EMB * EMB;
    const float* bias = (mat == 0) ? b0 : (mat == 1) ? b1 : (mat == 2) ? b2 : b3;

    float acc[4][4][4];
#pragma unroll
    for (int mt = 0; mt < 4; mt++)
#pragma unroll
        for (int nt = 0; nt < 4; nt++)
#pragma unroll
            for (int e = 0; e < 4; e++) acc[mt][nt][e] = 0.f;

    int a_r = (lid & 15);
    int a_h = (lid >> 4);
    int b_n = ((lid >> 4) << 3) + (lid & 7);
    int b_h = ((lid >> 3) & 1);

    int l_row[2], l_ch[2];
#pragma unroll
    for (int cc = 0; cc < 2; cc++) {
        int c = tid + cc * 256;
        l_row[cc] = c >> 2;
        l_ch[cc] = c & 3;
    }

#define GEMM_ISSUE(stage, k0)                                                  \
    do {                                                                       \
        u32 base_ = sb + (stage) * GSTG;                                       \
        _Pragma("unroll")                                                      \
        for (int cc = 0; cc < 2; cc++) {                                       \
            int row = l_row[cc], ch = l_ch[cc];                                \
            u32 so = SWZ64((u32)(row * 64 + ch * 16));                         \
            size_t ga = (size_t)(bm + row) * K + (k0) + ch * 8;                \
            size_t gb = (size_t)(bn + row) * K + (k0) + ch * 8;                \
            cp16(base_ + so, Af + ga);                                         \
            cp16(base_ + 8192 + so, As + ga);                                  \
            cp16(base_ + 16384 + so, Bh + gb);                                 \
            cp16(base_ + 24576 + so, Bl + gb);                                 \
        }                                                                      \
        CP_COMMIT();                                                           \
    } while (0)

    int niter = K / BKC;
    GEMM_ISSUE(0, 0);
    GEMM_ISSUE(1, BKC);

    for (int it = 0; it < niter; it++) {
        if (it + 1 < niter) {
            CP_WAIT(1);
        } else {
            CP_WAIT(0);
        }
        __syncthreads();
        if (it + 2 < niter)
            GEMM_ISSUE((it + 2) % 3, (it + 2) * BKC);

        u32 baseAf = sb + (it % 3) * GSTG;
        u32 baseAs = baseAf + 8192;
        u32 baseBh = baseAf + 16384;
        u32 baseBl = baseAf + 24576;

#pragma unroll
        for (int ks = 0; ks < 2; ks++) {
            u32 af[4][4], bhf[4][2], blf[4][2];
#pragma unroll
            for (int mt = 0; mt < 4; mt++) {
                int r = wm * 64 + mt * 16 + a_r;
                u32 addr = baseAf + SWZ64((u32)(r * 64 + (ks * 2 + a_h) * 16));
                ldsm_x4(af[mt][0], af[mt][1], af[mt][2], af[mt][3], addr);
            }
#pragma unroll
            for (int np = 0; np < 2; np++) {
                int n = wn * 32 + np * 16 + b_n;
                u32 off = SWZ64((u32)(n * 64 + (ks * 2 + b_h) * 16));
                ldsm_x4(bhf[np * 2][0], bhf[np * 2][1],
                        bhf[np * 2 + 1][0], bhf[np * 2 + 1][1], baseBh + off);
                ldsm_x4(blf[np * 2][0], blf[np * 2][1],
                        blf[np * 2 + 1][0], blf[np * 2 + 1][1], baseBl + off);
            }
#pragma unroll
            for (int mt = 0; mt < 4; mt++)
#pragma unroll
                for (int nt = 0; nt < 4; nt++)
                    mma_f16(acc[mt][nt], af[mt], bhf[nt]);
#pragma unroll
            for (int mt = 0; mt < 4; mt++) {
                int r = wm * 64 + mt * 16 + a_r;
                u32 addr = baseAs + SWZ64((u32)(r * 64 + (ks * 2 + a_h) * 16));
                ldsm_x4(af[mt][0], af[mt][1], af[mt][2], af[mt][3], addr);
            }
#pragma unroll
            for (int mt = 0; mt < 4; mt++)
#pragma unroll
                for (int nt = 0; nt < 4; nt++)
                    mma_f16(acc[mt][nt], af[mt], blf[nt]);
        }
    }

    u16* H = (mat == 0) ? H0 : (mat == 1) ? H1 : H2;
    u16* L = (mat == 0) ? L0 : (mat == 1) ? L1 : L2;

    int rr = lid >> 2, cc2 = (lid & 3) * 2;
#pragma unroll
    for (int mt = 0; mt < 4; mt++) {
        int r0 = bm + wm * 64 + mt * 16 + rr;
#pragma unroll
        for (int nt = 0; nt < 4; nt++) {
            int col = bn + wn * 32 + nt * 8 + cc2;
            float bb0 = bias[col], bb1 = bias[col + 1];
            float v00 = acc[mt][nt][0] + bb0, v01 = acc[mt][nt][1] + bb1;
            float v10 = acc[mt][nt][2] + bb0, v11 = acc[mt][nt][3] + bb1;
            if (mat == 3) {
                *(float2*)&C[(size_t)r0 * N + col] = make_float2(v00, v01);
                *(float2*)&C[(size_t)(r0 + 8) * N + col] = make_float2(v10, v11);
            } else if (mat == 0) {
                // Q: A-side split (fp16, fp16/64)
                u32 f, sgl;
                pack_fs(v00, v01, f, sgl);
                *(u32*)&H[(size_t)r0 * N + col] = f;
                *(u32*)&L[(size_t)r0 * N + col] = sgl;
                pack_fs(v10, v11, f, sgl);
                *(u32*)&H[(size_t)(r0 + 8) * N + col] = f;
                *(u32*)&L[(size_t)(r0 + 8) * N + col] = sgl;
            } else {
                // K,V: B-side split (fp16 hi, residual*64)
                u32 hh, rr2;
                pack_hr(v00, v01, hh, rr2);
                *(u32*)&H[(size_t)r0 * N + col] = hh;
                *(u32*)&L[(size_t)r0 * N + col] = rr2;
                pack_hr(v10, v11, hh, rr2);
                *(u32*)&H[(size_t)(r0 + 8) * N + col] = hh;
                *(u32*)&L[(size_t)(r0 + 8) * N + col] = rr2;
            }
        }
    }
}

// ---------------------------------------------------------------------------
// Tensor-core causal flash attention, fp16 2-pass everywhere:
//   S = Qf*Khi + (Q/64)*(Kres*64)   (exact in K; Q fp16 rounding only)
//   O = Pf*Vhi + (P/64)*(Vres*64)   (exact in V; P fp16 rounding only)
// fp32 base-2 softmax, cp.async 2-stage K/V pipeline, V via ldmatrix.trans.
// __launch_bounds__(256, 2): 2 CTAs/SM. RoPE mathematically eliminated.
// ---------------------------------------------------------------------------
#define ABQ 128
#define ABK 64
#define OQF 0
#define OQS 16384
#define AKV 32768
#define ASTG 32768
#define ASMEM (AKV + 2 * ASTG)

__global__ __launch_bounds__(256, 2)
void flash_attn_tc(const u16* __restrict__ qf_,
                   const u16* __restrict__ qs_,
                   const u16* __restrict__ kf_,
                   const u16* __restrict__ ks_,
                   const u16* __restrict__ vf_,
                   const u16* __restrict__ vs_,
                   u16* __restrict__ aof, u16* __restrict__ aos)
{
    extern __shared__ char smc[];
    u32 sb = smem_u32(smc);
    int tid = threadIdx.x, wid = tid / 32, lid = tid % 32;
    int qb = gridDim.x - 1 - blockIdx.x;   // longest work first
    int h = blockIdx.y, b = blockIdx.z;
    int q0 = qb * ABQ;
    int warp_row = q0 + wid * 16;

#pragma unroll
    for (int i = 0; i < 4; i++) {
        int c = tid + i * 256;
        int r = c >> 3, ch = c & 7;
        u32 so = SWZ128((u32)(r * 128 + ch * 16));
        size_t g = (size_t)(b * SEQ + q0 + r) * EMB + h * HD + ch * 8;
        *(uint4*)(smc + OQF + so) = *(const uint4*)(qf_ + g);
        *(uint4*)(smc + OQS + so) = *(const uint4*)(qs_ + g);
    }

    int v_r[2], v_ch[2];
#pragma unroll
    for (int i = 0; i < 2; i++) {
        int c = tid + i * 256;
        v_r[i] = c >> 3;
        v_ch[i] = c & 7;
    }

#define ATTN_ISSUE(stage, kb)                                                  \
    do {                                                                       \
        u32 base_ = sb + AKV + (stage) * ASTG;                                 \
        _Pragma("unroll")                                                      \
        for (int i = 0; i < 2; i++) {                                          \
            int r = v_r[i], ch = v_ch[i];                                      \
            u32 so = SWZ128((u32)(r * 128 + ch * 16));                         \
            size_t gk = (size_t)(b * SEQ + (kb) * ABK + r) * EMB + h * HD + ch * 8; \
            cp16(base_ + so, kf_ + gk);                                        \
            cp16(base_ + 8192 + so, ks_ + gk);                                 \
            cp16(base_ + 16384 + so, vf_ + gk);                                \
            cp16(base_ + 24576 + so, vs_ + gk);                                \
        }                                                                      \
        CP_COMMIT();                                                           \
    } while (0)

    float m_i[2], l_i[2], o[8][4];
    m_i[0] = m_i[1] = -INFINITY;
    l_i[0] = l_i[1] = 0.f;
#pragma unroll
    for (int nt = 0; nt < 8; nt++)
#pragma unroll
        for (int e = 0; e < 4; e++) o[nt][e] = 0.f;

    const float scale2 = 0.125f * 1.4426950408889634f;  // base-2 softmax
    int r1 = lid >> 2;
    int a_r = lid & 15, a_h = lid >> 4;
    int b_n = ((lid >> 4) << 3) + (lid & 7), b_h = (lid >> 3) & 1;
    int t_r16 = (lid & 7) + ((lid >> 3) & 1) * 8;
    int t_cb  = ((lid >> 4) & 1) * 16;

    int nkb = 2 * qb + 2;
    ATTN_ISSUE(0, 0);

    for (int kb = 0; kb < nkb; kb++) {
        if (kb + 1 < nkb) {
            ATTN_ISSUE((kb + 1) & 1, kb + 1);
            CP_WAIT(1);
        } else {
            CP_WAIT(0);
        }
        __syncthreads();

        if (kb * ABK <= warp_row + 15) {
            u32 bk = sb + AKV + (kb & 1) * ASTG;
            u32 okf = bk, oks = bk + 8192, ovf = bk + 16384, ovs = bk + 24576;

            // ---- S = Q K^T (fp16 2-pass) ----
            float s[8][4];
#pragma unroll
            for (int nt = 0; nt < 8; nt++)
#pragma unroll
                for (int e = 0; e < 4; e++) s[nt][e] = 0.f;

#pragma unroll
            for (int kc = 0; kc < 4; kc++) {
                u32 af[4], bhf[8][2], blf[8][2];
                u32 arow = (u32)((wid * 16 + a_r) * 128 + (kc * 2 + a_h) * 16);
                ldsm_x4(af[0], af[1], af[2], af[3], sb + OQF + SWZ128(arow));
#pragma unroll
                for (int g = 0; g < 4; g++) {
                    int n = g * 16 + b_n;
                    u32 off = SWZ128((u32)(n * 128 + (kc * 2 + b_h) * 16));
                    ldsm_x4(bhf[g * 2][0], bhf[g * 2][1],
                            bhf[g * 2 + 1][0], bhf[g * 2 + 1][1], okf + off);
                    ldsm_x4(blf[g * 2][0], blf[g * 2][1],
                            blf[g * 2 + 1][0], blf[g * 2 + 1][1], oks + off);
                }
#pragma unroll
                for (int nt = 0; nt < 8; nt++) mma_f16(s[nt], af, bhf[nt]);
                ldsm_x4(af[0], af[1], af[2], af[3], sb + OQS + SWZ128(arow));
#pragma unroll
                for (int nt = 0; nt < 8; nt++) mma_f16(s[nt], af, blf[nt]);
            }

            // ---- scale (base-2) + causal mask ----
            bool needmask = (kb * ABK + ABK - 1 > warp_row);
#pragma unroll
            for (int nt = 0; nt < 8; nt++) {
#pragma unroll
                for (int e = 0; e < 4; e++) {
                    s[nt][e] *= scale2;
                    if (needmask) {
                        int row = warp_row + r1 + ((e >> 1) << 3);
                        int col = kb * ABK + nt * 8 + (lid & 3) * 2 + (e & 1);
                        if (col > row) s[nt][e] = -INFINITY;
                    }
                }
            }

            // ---- online softmax in base-2 (rows r1, r1+8) ----
#pragma unroll
            for (int half = 0; half < 2; half++) {
                float mx = -INFINITY;
#pragma unroll
                for (int nt = 0; nt < 8; nt++)
                    mx = fmaxf(mx, fmaxf(s[nt][half * 2], s[nt][half * 2 + 1]));
                mx = fmaxf(mx, __shfl_xor_sync(0xffffffffu, mx, 1));
                mx = fmaxf(mx, __shfl_xor_sync(0xffffffffu, mx, 2));
                float m_new = fmaxf(m_i[half], mx);
                float corr = ex2(m_i[half] - m_new);
                m_i[half] = m_new;
                float rs = 0.f;
#pragma unroll
                for (int nt = 0; nt < 8; nt++) {
                    float p0 = ex2(s[nt][half * 2] - m_new);
                    float p1 = ex2(s[nt][half * 2 + 1] - m_new);
                    s[nt][half * 2] = p0;
                    s[nt][half * 2 + 1] = p1;
                    rs += p0 + p1;
                }
                rs += __shfl_xor_sync(0xffffffffu, rs, 1);
                rs += __shfl_xor_sync(0xffffffffu, rs, 2);
                l_i[half] = l_i[half] * corr + rs;
#pragma unroll
                for (int nt = 0; nt < 8; nt++) {
                    o[nt][half * 2] *= corr;
                    o[nt][half * 2 + 1] *= corr;
                }
            }

            // ---- O += P V (fp16 2-pass); V fragments via ldmatrix.trans ----
#pragma unroll
            for (int kc = 0; kc < 4; kc++) {
                u32 pf[4], ps[4];
                pack_fs(s[2 * kc][0], s[2 * kc][1], pf[0], ps[0]);
                pack_fs(s[2 * kc][2], s[2 * kc][3], pf[1], ps[1]);
                pack_fs(s[2 * kc + 1][0], s[2 * kc + 1][1], pf[2], ps[2]);
                pack_fs(s[2 * kc + 1][2], s[2 * kc + 1][3], pf[3], ps[3]);

                u32 bvf[8][2], bvs[8][2];
                u32 trow = (u32)((kc * 16 + t_r16) * 128);
#pragma unroll
                for (int g = 0; g < 4; g++) {
                    u32 off = SWZ128(trow + g * 32 + t_cb);
                    ldsm_x4t(bvf[g * 2][0], bvf[g * 2][1],
                             bvf[g * 2 + 1][0], bvf[g * 2 + 1][1], ovf + off);
                    ldsm_x4t(bvs[g * 2][0], bvs[g * 2][1],
                             bvs[g * 2 + 1][0], bvs[g * 2 + 1][1], ovs + off);
                }
#pragma unroll
                for (int nt = 0; nt < 8; nt++) mma_f16(o[nt], pf, bvf[nt]);
#pragma unroll
                for (int nt = 0; nt < 8; nt++) mma_f16(o[nt], ps, bvs[nt]);
            }
        }
        __syncthreads();
    }

    // ---- epilogue: normalize, emit fp16 single + fp16/64 for out-proj ----
#pragma unroll
    for (int half = 0; half < 2; half++) {
        float inv = 1.f / l_i[half];
        int row = warp_row + r1 + half * 8;
        size_t base = (size_t)(b * SEQ + row) * EMB + h * HD;
#pragma unroll
        for (int nt = 0; nt < 8; nt++) {
            int col = nt * 8 + (lid & 3) * 2;
            float v0 = o[nt][half * 2] * inv;
            float v1 = o[nt][half * 2 + 1] * inv;
            u32 f, sreg;
            pack_fs(v0, v1, f, sreg);
            *(u32*)&aof[base + col] = f;
            *(u32*)&aos[base + col] = sreg;
        }
    }
}

// ---------------------------------------------------------------------------
// Launch
// ---------------------------------------------------------------------------
extern "C" void kernel_launch(void* const* d_in, const int* in_sizes, int n_in,
                              void* d_out, int out_size)
{
    const float* x  = (const float*)d_in[0];
    const float* Wq = (const float*)d_in[1];
    const float* bq = (const float*)d_in[2];
    const float* Wk = (const float*)d_in[3];
    const float* bk = (const float*)d_in[4];
    const float* Wv = (const float*)d_in[5];
    const float* bv = (const float*)d_in[6];
    const float* Wo = (const float*)d_in[7];
    const float* bo = (const float*)d_in[8];
    float* out = (float*)d_out;

    u16 *af, *as, *bh, *bl, *qf, *qs, *kf, *ks, *vf, *vs;
    cudaGetSymbolAddress((void**)&af, g_af);
    cudaGetSymbolAddress((void**)&as, g_as);
    cudaGetSymbolAddress((void**)&bh, g_bh);
    cudaGetSymbolAddress((void**)&bl, g_bl);
    cudaGetSymbolAddress((void**)&qf, g_qf);
    cudaGetSymbolAddress((void**)&qs, g_qs);
    cudaGetSymbolAddress((void**)&kf, g_kf);
    cudaGetSymbolAddress((void**)&ks, g_ks);
    cudaGetSymbolAddress((void**)&vf, g_vf);
    cudaGetSymbolAddress((void**)&vs, g_vs);

    cudaFuncSetAttribute(gemm_mma,
                         cudaFuncAttributeMaxDynamicSharedMemorySize, GSMEM);
    cudaFuncSetAttribute(flash_attn_tc,
                         cudaFuncAttributeMaxDynamicSharedMemorySize, ASMEM);

    dim3 ct(32, 8);
    dim3 cg6(EMB / 32, EMB / 32, 6);            // 4 weights + 2 x-halves
    dim3 qkvgrid(3 * EMB / 128, MROWS / 128);   // (48, 32): fused Q,K,V
    dim3 ogrid(EMB / 128, MROWS / 128);         // (16, 32): out proj
    dim3 agrid(SEQ / ABQ, NH, BSZ);             // (16, 32, 2)

    // one fused conversion launch
    conv_all<<<cg6, ct>>>(Wq, Wk, Wv, Wo, x, bh, bl, af, as);

    // fused QKV projection (fp16 2-pass)
    gemm_mma<<<qkvgrid, 256, GSMEM>>>(af, as, bh, bl, bq, bk, bv, bo,
                                      qf, qs, kf, ks, vf, vs, NULL, 0,
                                      MROWS, EMB);

    // attention (fp16 2-pass) -> fp16 single + fp16/64 into af/as
    flash_attn_tc<<<agrid, 256, ASMEM>>>(qf, qs, kf, ks, vf, vs, af, as);

    // output projection (fp16 2-pass, mat 3, fp32 out)
    gemm_mma<<<ogrid, 256, GSMEM>>>(af, as, bh, bl, bq, bk, bv, bo,
                                    qf, qs, kf, ks, vf, vs, out, 3,
                                    MROWS, EMB);
}

// round 15
// speedup vs baseline: 1.6032x; 1.0669x over previous
#include <cuda_runtime.h>
#include <cuda_bf16.h>
#include <cuda_fp16.h>
#include <cstdint>
#include <math.h>

typedef unsigned int u32;
typedef unsigned long long u64;
typedef unsigned short u16;

#define BSZ 2
#define SEQ 2048
#define EMB 2048
#define NH 32
#define HD 64
#define MROWS (BSZ*SEQ)
#define RSC 64.0f          // residual scale (2^6)
#define H2_ISC 0x24002400u // fp16x2 {2^-6, 2^-6}

// ---------------------------------------------------------------------------
// Scratch (device globals: allocation-free per harness rules)
// g_af: fp16 A operand (x, later attention-out); scaled copy derived in-reg
// g_bh/g_bl: fp16 W^T hi + (residual*64), x4 weights
// q: fp16 (A-side); k,v: fp16 hi + res*64 (B-side)
// ---------------------------------------------------------------------------
__device__ __align__(16) u16 g_af[(size_t)MROWS * EMB];
__device__ __align__(16) u16 g_bh[(size_t)4 * EMB * EMB];
__device__ __align__(16) u16 g_bl[(size_t)4 * EMB * EMB];
__device__ __align__(16) u16 g_qf[(size_t)MROWS * EMB];
__device__ __align__(16) u16 g_kf[(size_t)MROWS * EMB];
__device__ __align__(16) u16 g_ks[(size_t)MROWS * EMB];
__device__ __align__(16) u16 g_vf[(size_t)MROWS * EMB];
__device__ __align__(16) u16 g_vs[(size_t)MROWS * EMB];

// ---------------------------------------------------------------------------
// Warp-MMA / cp.async helpers (baseline PTX: works on plain sm_103 target)
// ---------------------------------------------------------------------------
__device__ __forceinline__ u32 smem_u32(const void* p) {
    u32 a;
    asm("{ .reg .u64 t; cvta.to.shared.u64 t, %1; cvt.u32.u64 %0, t; }"
        : "=r"(a) : "l"(p));
    return a;
}
__device__ __forceinline__ void ldsm_x4(u32& r0, u32& r1, u32& r2, u32& r3,
                                        u32 addr) {
    asm volatile("ldmatrix.sync.aligned.m8n8.x4.shared.b16 {%0,%1,%2,%3}, [%4];"
                 : "=r"(r0), "=r"(r1), "=r"(r2), "=r"(r3) : "r"(addr));
}
__device__ __forceinline__ void ldsm_x4t(u32& r0, u32& r1, u32& r2, u32& r3,
                                         u32 addr) {
    asm volatile("ldmatrix.sync.aligned.m8n8.x4.trans.shared.b16 {%0,%1,%2,%3}, [%4];"
                 : "=r"(r0), "=r"(r1), "=r"(r2), "=r"(r3) : "r"(addr));
}
__device__ __forceinline__ void mma_f16(float* d, const u32* a, const u32* b) {
    asm volatile(
        "mma.sync.aligned.m16n8k16.row.col.f32.f16.f16.f32 "
        "{%0,%1,%2,%3}, {%4,%5,%6,%7}, {%8,%9}, {%0,%1,%2,%3};"
        : "+f"(d[0]), "+f"(d[1]), "+f"(d[2]), "+f"(d[3])
        : "r"(a[0]), "r"(a[1]), "r"(a[2]), "r"(a[3]), "r"(b[0]), "r"(b[1]));
}
// exact in-register /64 of a packed fp16x2 (power-of-2 scale)
__device__ __forceinline__ u32 hscale(u32 v) {
    u32 r;
    asm("mul.rn.f16x2 %0, %1, %2;" : "=r"(r) : "r"(v), "r"(H2_ISC));
    return r;
}
__device__ __forceinline__ void cp16(u32 dst, const void* src) {
    asm volatile("cp.async.cg.shared.global [%0], [%1], 16;"
                 :: "r"(dst), "l"(src) : "memory");
}
#define CP_COMMIT() asm volatile("cp.async.commit_group;" ::: "memory")
#define CP_WAIT(n)  asm volatile("cp.async.wait_group %0;" :: "n"(n) : "memory")

__device__ __forceinline__ float ex2(float x) {
    float y;
    asm("ex2.approx.f32 %0, %1;" : "=f"(y) : "f"(x));
    return y;
}
// pack two fp32 -> fp16x2
__device__ __forceinline__ u32 pack_f(float x0, float x1) {
    __half2 hf = __float22half2_rn(make_float2(x0, x1));
    return *(u32*)&hf;
}
// pack two fp32 -> fp16x2 hi and fp16x2 of (residual*64)   (B-side operands)
__device__ __forceinline__ void pack_hr(float x0, float x1, u32& h, u32& r) {
    __half2 hh = __float22half2_rn(make_float2(x0, x1));
    float r0 = (x0 - __half2float(__low2half(hh))) * RSC;
    float r1 = (x1 - __half2float(__high2half(hh))) * RSC;
    __half2 hr = __float22half2_rn(make_float2(r0, r1));
    h = *(u32*)&hh;
    r = *(u32*)&hr;
}
#define SWZ64(o)  ((o) ^ (((o) >> 3) & 0x30))
#define SWZ128(o) ((o) ^ (((o) >> 3) & 0x70))

// ---------------------------------------------------------------------------
// Fused conversion: z=0..3 -> W_z^T fp16 hi + fp16(res*64); z=4,5 -> x fp16
// ---------------------------------------------------------------------------
__global__ void conv_all(const float* __restrict__ W0, const float* __restrict__ W1,
                         const float* __restrict__ W2, const float* __restrict__ W3,
                         const float* __restrict__ X,
                         u16* __restrict__ Th, u16* __restrict__ Tl,
                         u16* __restrict__ XF)
{
    int z = blockIdx.z;
    if (z >= 4) {
        int t = threadIdx.y * 32 + threadIdx.x;
        size_t i = ((size_t)(z - 4) * 4096 + blockIdx.y * 64 + blockIdx.x) * 256 + t;
        float4 v = ((const float4*)X)[i];
        ((uint2*)XF)[i] = make_uint2(pack_f(v.x, v.y), pack_f(v.z, v.w));
        return;
    }
    __shared__ float t[32][33];
    const float* W = (z == 0) ? W0 : (z == 1) ? W1 : (z == 2) ? W2 : W3;
    size_t zo = (size_t)z * EMB * EMB;
    int n0 = blockIdx.x * 32, k0 = blockIdx.y * 32;
    int x = threadIdx.x, y = threadIdx.y;  // 32 x 8
#pragma unroll
    for (int r = 0; r < 32; r += 8)
        t[y + r][x] = W[(size_t)(k0 + y + r) * EMB + n0 + x];
    __syncthreads();
#pragma unroll
    for (int r = 0; r < 32; r += 8) {
        float v = t[x][y + r];
        __half h = __float2half_rn(v);
        float res = (v - __half2float(h)) * RSC;
        __half l = __float2half_rn(res);
        size_t o = zo + (size_t)(n0 + y + r) * EMB + k0 + x;
        Th[o] = *(u16*)&h;
        Tl[o] = *(u16*)&l;
    }
}

// ---------------------------------------------------------------------------
// Tensor-core GEMM, fp16 2-pass scaled-residual with IN-REGISTER A scaling:
//   D = Af * Bh + (Af*2^-6) * (Bres*64)
// No As smem buffer: A-fragments halved -> 8 ldsm/ks, FLOP/B 10.7 -> 16.
// cp.async 3-stage pipeline, single sync/iter. 128x128, 256 thr, 2 CTAs/SM.
// mat 0 -> Q fp16; mats 1,2 -> K,V as (fp16 hi, res*64); mat 3 -> fp32 C.
// Stage layout (24 KB): AF 0, BH 8192, BL 16384.
// ---------------------------------------------------------------------------
#define BKC 32
#define GSTG 24576
#define GSMEM (3 * GSTG)

__global__ __launch_bounds__(256, 2)
void gemm_mma(const u16* __restrict__ Af,
              const u16* __restrict__ BhAll,
              const u16* __restrict__ BlAll,
              const float* __restrict__ b0, const float* __restrict__ b1,
              const float* __restrict__ b2, const float* __restrict__ b3,
              u16* __restrict__ H0,
              u16* __restrict__ H1, u16* __restrict__ L1,
              u16* __restrict__ H2, u16* __restrict__ L2,
              float* __restrict__ C, int mat_base, int M, int K)
{
    extern __shared__ char smg[];
    u32 sb = smem_u32(smg);
    const int N = EMB;

    int tid = threadIdx.x;
    int wid = tid / 32, lid = tid % 32;
    int wm = wid / 4, wn = wid % 4;        // warp grid 2 x 4
    int mat = mat_base + (blockIdx.x >> 4);
    int bm = blockIdx.y * 128, bn = (blockIdx.x & 15) * 128;

    const u16* Bh = BhAll + (size_t)mat * EMB * EMB;
    const u16* Bl = BlAll + (size_t)mat * EMB * EMB;
    const float* bias = (mat == 0) ? b0 : (mat == 1) ? b1 : (mat == 2) ? b2 : b3;

    float acc[4][4][4];
#pragma unroll
    for (int mt = 0; mt < 4; mt++)
#pragma unroll
        for (int nt = 0; nt < 4; nt++)
#pragma unroll
            for (int e = 0; e < 4; e++) acc[mt][nt][e] = 0.f;

    int a_r = (lid & 15);
    int a_h = (lid >> 4);
    int b_n = ((lid >> 4) << 3) + (lid & 7);
    int b_h = ((lid >> 3) & 1);

    int l_row[2], l_ch[2];
#pragma unroll
    for (int cc = 0; cc < 2; cc++) {
        int c = tid + cc * 256;
        l_row[cc] = c >> 2;
        l_ch[cc] = c & 3;
    }

#define GEMM_ISSUE(stage, k0)                                                  \
    do {                                                                       \
        u32 base_ = sb + (stage) * GSTG;                                       \
        _Pragma("unroll")                                                      \
        for (int cc = 0; cc < 2; cc++) {                                       \
            int row = l_row[cc], ch = l_ch[cc];                                \
            u32 so = SWZ64((u32)(row * 64 + ch * 16));                         \
            size_t ga = (size_t)(bm + row) * K + (k0) + ch * 8;                \
            size_t gb = (size_t)(bn + row) * K + (k0) + ch * 8;                \
            cp16(base_ + so, Af + ga);                                         \
            cp16(base_ + 8192 + so, Bh + gb);                                  \
            cp16(base_ + 16384 + so, Bl + gb);                                 \
        }                                                                      \
        CP_COMMIT();                                                           \
    } while (0)

    int niter = K / BKC;
    GEMM_ISSUE(0, 0);
    GEMM_ISSUE(1, BKC);

    for (int it = 0; it < niter; it++) {
        if (it + 1 < niter) {
            CP_WAIT(1);
        } else {
            CP_WAIT(0);
        }
        __syncthreads();
        if (it + 2 < niter)
            GEMM_ISSUE((it + 2) % 3, (it + 2) * BKC);

        u32 baseAf = sb + (it % 3) * GSTG;
        u32 baseBh = baseAf + 8192;
        u32 baseBl = baseAf + 16384;

#pragma unroll
        for (int ks = 0; ks < 2; ks++) {
            u32 af[4][4], bhf[4][2], blf[4][2];
#pragma unroll
            for (int mt = 0; mt < 4; mt++) {
                int r = wm * 64 + mt * 16 + a_r;
                u32 addr = baseAf + SWZ64((u32)(r * 64 + (ks * 2 + a_h) * 16));
                ldsm_x4(af[mt][0], af[mt][1], af[mt][2], af[mt][3], addr);
            }
#pragma unroll
            for (int np = 0; np < 2; np++) {
                int n = wn * 32 + np * 16 + b_n;
                u32 off = SWZ64((u32)(n * 64 + (ks * 2 + b_h) * 16));
                ldsm_x4(bhf[np * 2][0], bhf[np * 2][1],
                        bhf[np * 2 + 1][0], bhf[np * 2 + 1][1], baseBh + off);
                ldsm_x4(blf[np * 2][0], blf[np * 2][1],
                        blf[np * 2 + 1][0], blf[np * 2 + 1][1], baseBl + off);
            }
            // pass 1: Af * Bh
#pragma unroll
            for (int mt = 0; mt < 4; mt++)
#pragma unroll
                for (int nt = 0; nt < 4; nt++)
                    mma_f16(acc[mt][nt], af[mt], bhf[nt]);
            // exact in-register scale: af *= 2^-6, pass 2 with residuals
#pragma unroll
            for (int mt = 0; mt < 4; mt++)
#pragma unroll
                for (int r = 0; r < 4; r++)
                    af[mt][r] = hscale(af[mt][r]);
#pragma unroll
            for (int mt = 0; mt < 4; mt++)
#pragma unroll
                for (int nt = 0; nt < 4; nt++)
                    mma_f16(acc[mt][nt], af[mt], blf[nt]);
        }
    }

    int rr = lid >> 2, cc2 = (lid & 3) * 2;
#pragma unroll
    for (int mt = 0; mt < 4; mt++) {
        int r0 = bm + wm * 64 + mt * 16 + rr;
#pragma unroll
        for (int nt = 0; nt < 4; nt++) {
            int col = bn + wn * 32 + nt * 8 + cc2;
            float bb0 = bias[col], bb1 = bias[col + 1];
            float v00 = acc[mt][nt][0] + bb0, v01 = acc[mt][nt][1] + bb1;
            float v10 = acc[mt][nt][2] + bb0, v11 = acc[mt][nt][3] + bb1;
            if (mat == 3) {
                *(float2*)&C[(size_t)r0 * N + col] = make_float2(v00, v01);
                *(float2*)&C[(size_t)(r0 + 8) * N + col] = make_float2(v10, v11);
            } else if (mat == 0) {
                // Q: fp16 only (scaled copy derived in attention registers)
                *(u32*)&H0[(size_t)r0 * N + col] = pack_f(v00, v01);
                *(u32*)&H0[(size_t)(r0 + 8) * N + col] = pack_f(v10, v11);
            } else {
                u16* H = (mat == 1) ? H1 : H2;
                u16* L = (mat == 1) ? L1 : L2;
                u32 hh, rr2;
                pack_hr(v00, v01, hh, rr2);
                *(u32*)&H[(size_t)r0 * N + col] = hh;
                *(u32*)&L[(size_t)r0 * N + col] = rr2;
                pack_hr(v10, v11, hh, rr2);
                *(u32*)&H[(size_t)(r0 + 8) * N + col] = hh;
                *(u32*)&L[(size_t)(r0 + 8) * N + col] = rr2;
            }
        }
    }
}

// ---------------------------------------------------------------------------
// Tensor-core causal flash attention, fp16 2-pass with in-register scaling:
//   S = Qf*Khi + (Qf*2^-6)*(Kres*64);  O = Pf*Vhi + (Pf*2^-6)*(Vres*64)
// fp32 base-2 softmax, cp.async 2-stage K/V pipeline, V via ldmatrix.trans.
// Q smem halved (fp16 only). 2 CTAs/SM. RoPE mathematically eliminated.
// ---------------------------------------------------------------------------
#define ABQ 128
#define ABK 64
#define OQF 0
#define AKV 16384
#define ASTG 32768
#define ASMEM (AKV + 2 * ASTG)

__global__ __launch_bounds__(256, 2)
void flash_attn_tc(const u16* __restrict__ qf_,
                   const u16* __restrict__ kf_,
                   const u16* __restrict__ ks_,
                   const u16* __restrict__ vf_,
                   const u16* __restrict__ vs_,
                   u16* __restrict__ aof)
{
    extern __shared__ char smc[];
    u32 sb = smem_u32(smc);
    int tid = threadIdx.x, wid = tid / 32, lid = tid % 32;
    int qb = gridDim.x - 1 - blockIdx.x;   // longest work first
    int h = blockIdx.y, b = blockIdx.z;
    int q0 = qb * ABQ;
    int warp_row = q0 + wid * 16;

    // Load Q tile (128x64 fp16), SW128 rows
#pragma unroll
    for (int i = 0; i < 4; i++) {
        int c = tid + i * 256;
        int r = c >> 3, ch = c & 7;
        u32 so = SWZ128((u32)(r * 128 + ch * 16));
        size_t g = (size_t)(b * SEQ + q0 + r) * EMB + h * HD + ch * 8;
        *(uint4*)(smc + OQF + so) = *(const uint4*)(qf_ + g);
    }

    int v_r[2], v_ch[2];
#pragma unroll
    for (int i = 0; i < 2; i++) {
        int c = tid + i * 256;
        v_r[i] = c >> 3;
        v_ch[i] = c & 7;
    }

#define ATTN_ISSUE(stage, kb)                                                  \
    do {                                                                       \
        u32 base_ = sb + AKV + (stage) * ASTG;                                 \
        _Pragma("unroll")                                                      \
        for (int i = 0; i < 2; i++) {                                          \
            int r = v_r[i], ch = v_ch[i];                                      \
            u32 so = SWZ128((u32)(r * 128 + ch * 16));                         \
            size_t gk = (size_t)(b * SEQ + (kb) * ABK + r) * EMB + h * HD + ch * 8; \
            cp16(base_ + so, kf_ + gk);                                        \
            cp16(base_ + 8192 + so, ks_ + gk);                                 \
            cp16(base_ + 16384 + so, vf_ + gk);                                \
            cp16(base_ + 24576 + so, vs_ + gk);                                \
        }                                                                      \
        CP_COMMIT();                                                           \
    } while (0)

    float m_i[2], l_i[2], o[8][4];
    m_i[0] = m_i[1] = -INFINITY;
    l_i[0] = l_i[1] = 0.f;
#pragma unroll
    for (int nt = 0; nt < 8; nt++)
#pragma unroll
        for (int e = 0; e < 4; e++) o[nt][e] = 0.f;

    const float scale2 = 0.125f * 1.4426950408889634f;  // base-2 softmax
    int r1 = lid >> 2;
    int a_r = lid & 15, a_h = lid >> 4;
    int b_n = ((lid >> 4) << 3) + (lid & 7), b_h = (lid >> 3) & 1;
    int t_r16 = (lid & 7) + ((lid >> 3) & 1) * 8;
    int t_cb  = ((lid >> 4) & 1) * 16;

    int nkb = 2 * qb + 2;
    ATTN_ISSUE(0, 0);

    for (int kb = 0; kb < nkb; kb++) {
        if (kb + 1 < nkb) {
            ATTN_ISSUE((kb + 1) & 1, kb + 1);
            CP_WAIT(1);
        } else {
            CP_WAIT(0);
        }
        __syncthreads();

        if (kb * ABK <= warp_row + 15) {
            u32 bk = sb + AKV + (kb & 1) * ASTG;
            u32 okf = bk, oks = bk + 8192, ovf = bk + 16384, ovs = bk + 24576;

            // ---- S = Q K^T (fp16 2-pass, Q scaled in-register) ----
            float s[8][4];
#pragma unroll
            for (int nt = 0; nt < 8; nt++)
#pragma unroll
                for (int e = 0; e < 4; e++) s[nt][e] = 0.f;

#pragma unroll
            for (int kc = 0; kc < 4; kc++) {
                u32 af[4], bhf[8][2], blf[8][2];
                u32 arow = (u32)((wid * 16 + a_r) * 128 + (kc * 2 + a_h) * 16);
                ldsm_x4(af[0], af[1], af[2], af[3], sb + OQF + SWZ128(arow));
#pragma unroll
                for (int g = 0; g < 4; g++) {
                    int n = g * 16 + b_n;
                    u32 off = SWZ128((u32)(n * 128 + (kc * 2 + b_h) * 16));
                    ldsm_x4(bhf[g * 2][0], bhf[g * 2][1],
                            bhf[g * 2 + 1][0], bhf[g * 2 + 1][1], okf + off);
                    ldsm_x4(blf[g * 2][0], blf[g * 2][1],
                            blf[g * 2 + 1][0], blf[g * 2 + 1][1], oks + off);
                }
#pragma unroll
                for (int nt = 0; nt < 8; nt++) mma_f16(s[nt], af, bhf[nt]);
#pragma unroll
                for (int r = 0; r < 4; r++) af[r] = hscale(af[r]);
#pragma unroll
                for (int nt = 0; nt < 8; nt++) mma_f16(s[nt], af, blf[nt]);
            }

            // ---- scale (base-2) + causal mask ----
            bool needmask = (kb * ABK + ABK - 1 > warp_row);
#pragma unroll
            for (int nt = 0; nt < 8; nt++) {
#pragma unroll
                for (int e = 0; e < 4; e++) {
                    s[nt][e] *= scale2;
                    if (needmask) {
                        int row = warp_row + r1 + ((e >> 1) << 3);
                        int col = kb * ABK + nt * 8 + (lid & 3) * 2 + (e & 1);
                        if (col > row) s[nt][e] = -INFINITY;
                    }
                }
            }

            // ---- online softmax in base-2 (rows r1, r1+8) ----
#pragma unroll
            for (int half = 0; half < 2; half++) {
                float mx = -INFINITY;
#pragma unroll
                for (int nt = 0; nt < 8; nt++)
                    mx = fmaxf(mx, fmaxf(s[nt][half * 2], s[nt][half * 2 + 1]));
                mx = fmaxf(mx, __shfl_xor_sync(0xffffffffu, mx, 1));
                mx = fmaxf(mx, __shfl_xor_sync(0xffffffffu, mx, 2));
                float m_new = fmaxf(m_i[half], mx);
                float corr = ex2(m_i[half] - m_new);
                m_i[half] = m_new;
                float rs = 0.f;
#pragma unroll
                for (int nt = 0; nt < 8; nt++) {
                    float p0 = ex2(s[nt][half * 2] - m_new);
                    float p1 = ex2(s[nt][half * 2 + 1] - m_new);
                    s[nt][half * 2] = p0;
                    s[nt][half * 2 + 1] = p1;
                    rs += p0 + p1;
                }
                rs += __shfl_xor_sync(0xffffffffu, rs, 1);
                rs += __shfl_xor_sync(0xffffffffu, rs, 2);
                l_i[half] = l_i[half] * corr + rs;
#pragma unroll
                for (int nt = 0; nt < 8; nt++) {
                    o[nt][half * 2] *= corr;
                    o[nt][half * 2 + 1] *= corr;
                }
            }

            // ---- O += P V (fp16 2-pass, P scaled in-register) ----
#pragma unroll
            for (int kc = 0; kc < 4; kc++) {
                u32 pf[4];
                pf[0] = pack_f(s[2 * kc][0], s[2 * kc][1]);
                pf[1] = pack_f(s[2 * kc][2], s[2 * kc][3]);
                pf[2] = pack_f(s[2 * kc + 1][0], s[2 * kc + 1][1]);
                pf[3] = pack_f(s[2 * kc + 1][2], s[2 * kc + 1][3]);

                u32 bvf[8][2], bvs[8][2];
                u32 trow = (u32)((kc * 16 + t_r16) * 128);
#pragma unroll
                for (int g = 0; g < 4; g++) {
                    u32 off = SWZ128(trow + g * 32 + t_cb);
                    ldsm_x4t(bvf[g * 2][0], bvf[g * 2][1],
                             bvf[g * 2 + 1][0], bvf[g * 2 + 1][1], ovf + off);
                    ldsm_x4t(bvs[g * 2][0], bvs[g * 2][1],
                             bvs[g * 2 + 1][0], bvs[g * 2 + 1][1], ovs + off);
                }
#pragma unroll
                for (int nt = 0; nt < 8; nt++) mma_f16(o[nt], pf, bvf[nt]);
#pragma unroll
                for (int r = 0; r < 4; r++) pf[r] = hscale(pf[r]);
#pragma unroll
                for (int nt = 0; nt < 8; nt++) mma_f16(o[nt], pf, bvs[nt]);
            }
        }
        __syncthreads();
    }

    // ---- epilogue: normalize, emit fp16 for out-proj ----
#pragma unroll
    for (int half = 0; half < 2; half++) {
        float inv = 1.f / l_i[half];
        int row = warp_row + r1 + half * 8;
        size_t base = (size_t)(b * SEQ + row) * EMB + h * HD;
#pragma unroll
        for (int nt = 0; nt < 8; nt++) {
            int col = nt * 8 + (lid & 3) * 2;
            float v0 = o[nt][half * 2] * inv;
            float v1 = o[nt][half * 2 + 1] * inv;
            *(u32*)&aof[base + col] = pack_f(v0, v1);
        }
    }
}

// ---------------------------------------------------------------------------
// Launch
// ---------------------------------------------------------------------------
extern "C" void kernel_launch(void* const* d_in, const int* in_sizes, int n_in,
                              void* d_out, int out_size)
{
    const float* x  = (const float*)d_in[0];
    const float* Wq = (const float*)d_in[1];
    const float* bq = (const float*)d_in[2];
    const float* Wk = (const float*)d_in[3];
    const float* bk = (const float*)d_in[4];
    const float* Wv = (const float*)d_in[5];
    const float* bv = (const float*)d_in[6];
    const float* Wo = (const float*)d_in[7];
    const float* bo = (const float*)d_in[8];
    float* out = (float*)d_out;

    u16 *af, *bh, *bl, *qf, *kf, *ks, *vf, *vs;
    cudaGetSymbolAddress((void**)&af, g_af);
    cudaGetSymbolAddress((void**)&bh, g_bh);
    cudaGetSymbolAddress((void**)&bl, g_bl);
    cudaGetSymbolAddress((void**)&qf, g_qf);
    cudaGetSymbolAddress((void**)&kf, g_kf);
    cudaGetSymbolAddress((void**)&ks, g_ks);
    cudaGetSymbolAddress((void**)&vf, g_vf);
    cudaGetSymbolAddress((void**)&vs, g_vs);

    cudaFuncSetAttribute(gemm_mma,
                         cudaFuncAttributeMaxDynamicSharedMemorySize, GSMEM);
    cudaFuncSetAttribute(flash_attn_tc,
                         cudaFuncAttributeMaxDynamicSharedMemorySize, ASMEM);

    dim3 ct(32, 8);
    dim3 cg6(EMB / 32, EMB / 32, 6);            // 4 weights + 2 x-halves
    dim3 qkvgrid(3 * EMB / 128, MROWS / 128);   // (48, 32): fused Q,K,V
    dim3 ogrid(EMB / 128, MROWS / 128);         // (16, 32): out proj
    dim3 agrid(SEQ / ABQ, NH, BSZ);             // (16, 32, 2)

    // one fused conversion launch
    conv_all<<<cg6, ct>>>(Wq, Wk, Wv, Wo, x, bh, bl, af);

    // fused QKV projection (fp16 2-pass, in-register A scaling)
    gemm_mma<<<qkvgrid, 256, GSMEM>>>(af, bh, bl, bq, bk, bv, bo,
                                      qf, kf, ks, vf, vs, NULL, 0,
                                      MROWS, EMB);

    // attention (fp16 2-pass) -> fp16 into af
    flash_attn_tc<<<agrid, 256, ASMEM>>>(qf, kf, ks, vf, vs, af);

    // output projection (mat 3, fp32 out)
    gemm_mma<<<ogrid, 256, GSMEM>>>(af, bh, bl, bq, bk, bv, bo,
                                    qf, kf, ks, vf, vs, out, 3,
                                    MROWS, EMB);
}

// round 16
// speedup vs baseline: 1.7893x; 1.1161x over previous
#include <cuda_runtime.h>
#include <cuda_bf16.h>
#include <cuda_fp16.h>
#include <cstdint>
#include <math.h>

typedef unsigned int u32;
typedef unsigned long long u64;
typedef unsigned short u16;

#define BSZ 2
#define SEQ 2048
#define EMB 2048
#define NH 32
#define HD 64
#define MROWS (BSZ*SEQ)
#define RSC 64.0f          // residual scale (2^6)
#define H2_ISC 0x24002400u // fp16x2 {2^-6, 2^-6}

// ---------------------------------------------------------------------------
// Scratch (device globals: allocation-free per harness rules)
// g_af: fp16 A operand (x, later attention-out)
// g_bh/g_bl: fp16 W^T hi + (residual*64), x4 weights
// q: fp16 (A-side); k: fp16 hi + res*64 (B-side); v: fp16 single-pass
// ---------------------------------------------------------------------------
__device__ __align__(16) u16 g_af[(size_t)MROWS * EMB];
__device__ __align__(16) u16 g_bh[(size_t)4 * EMB * EMB];
__device__ __align__(16) u16 g_bl[(size_t)4 * EMB * EMB];
__device__ __align__(16) u16 g_qf[(size_t)MROWS * EMB];
__device__ __align__(16) u16 g_kf[(size_t)MROWS * EMB];
__device__ __align__(16) u16 g_ks[(size_t)MROWS * EMB];
__device__ __align__(16) u16 g_vf[(size_t)MROWS * EMB];

// ---------------------------------------------------------------------------
// Warp-MMA / cp.async helpers (baseline PTX: works on plain sm_103 target)
// ---------------------------------------------------------------------------
__device__ __forceinline__ u32 smem_u32(const void* p) {
    u32 a;
    asm("{ .reg .u64 t; cvta.to.shared.u64 t, %1; cvt.u32.u64 %0, t; }"
        : "=r"(a) : "l"(p));
    return a;
}
__device__ __forceinline__ void ldsm_x4(u32& r0, u32& r1, u32& r2, u32& r3,
                                        u32 addr) {
    asm volatile("ldmatrix.sync.aligned.m8n8.x4.shared.b16 {%0,%1,%2,%3}, [%4];"
                 : "=r"(r0), "=r"(r1), "=r"(r2), "=r"(r3) : "r"(addr));
}
__device__ __forceinline__ void ldsm_x4t(u32& r0, u32& r1, u32& r2, u32& r3,
                                         u32 addr) {
    asm volatile("ldmatrix.sync.aligned.m8n8.x4.trans.shared.b16 {%0,%1,%2,%3}, [%4];"
                 : "=r"(r0), "=r"(r1), "=r"(r2), "=r"(r3) : "r"(addr));
}
__device__ __forceinline__ void mma_f16(float* d, const u32* a, const u32* b) {
    asm volatile(
        "mma.sync.aligned.m16n8k16.row.col.f32.f16.f16.f32 "
        "{%0,%1,%2,%3}, {%4,%5,%6,%7}, {%8,%9}, {%0,%1,%2,%3};"
        : "+f"(d[0]), "+f"(d[1]), "+f"(d[2]), "+f"(d[3])
        : "r"(a[0]), "r"(a[1]), "r"(a[2]), "r"(a[3]), "r"(b[0]), "r"(b[1]));
}
// exact in-register /64 of a packed fp16x2 (power-of-2 scale)
__device__ __forceinline__ u32 hscale(u32 v) {
    u32 r;
    asm("mul.rn.f16x2 %0, %1, %2;" : "=r"(r) : "r"(v), "r"(H2_ISC));
    return r;
}
__device__ __forceinline__ void cp16(u32 dst, const void* src) {
    asm volatile("cp.async.cg.shared.global [%0], [%1], 16;"
                 :: "r"(dst), "l"(src) : "memory");
}
#define CP_COMMIT() asm volatile("cp.async.commit_group;" ::: "memory")
#define CP_WAIT(n)  asm volatile("cp.async.wait_group %0;" :: "n"(n) : "memory")

__device__ __forceinline__ float ex2(float x) {
    float y;
    asm("ex2.approx.f32 %0, %1;" : "=f"(y) : "f"(x));
    return y;
}
// pack two fp32 -> fp16x2
__device__ __forceinline__ u32 pack_f(float x0, float x1) {
    __half2 hf = __float22half2_rn(make_float2(x0, x1));
    return *(u32*)&hf;
}
// pack two fp32 -> fp16x2 hi and fp16x2 of (residual*64)   (B-side operands)
__device__ __forceinline__ void pack_hr(float x0, float x1, u32& h, u32& r) {
    __half2 hh = __float22half2_rn(make_float2(x0, x1));
    float r0 = (x0 - __half2float(__low2half(hh))) * RSC;
    float r1 = (x1 - __half2float(__high2half(hh))) * RSC;
    __half2 hr = __float22half2_rn(make_float2(r0, r1));
    h = *(u32*)&hh;
    r = *(u32*)&hr;
}
#define SWZ64(o)  ((o) ^ (((o) >> 3) & 0x30))
#define SWZ128(o) ((o) ^ (((o) >> 3) & 0x70))

// ---------------------------------------------------------------------------
// Fused conversion: z=0..3 -> W_z^T fp16 hi + fp16(res*64); z=4,5 -> x fp16
// ---------------------------------------------------------------------------
__global__ void conv_all(const float* __restrict__ W0, const float* __restrict__ W1,
                         const float* __restrict__ W2, const float* __restrict__ W3,
                         const float* __restrict__ X,
                         u16* __restrict__ Th, u16* __restrict__ Tl,
                         u16* __restrict__ XF)
{
    int z = blockIdx.z;
    if (z >= 4) {
        int t = threadIdx.y * 32 + threadIdx.x;
        size_t i = ((size_t)(z - 4) * 4096 + blockIdx.y * 64 + blockIdx.x) * 256 + t;
        float4 v = ((const float4*)X)[i];
        ((uint2*)XF)[i] = make_uint2(pack_f(v.x, v.y), pack_f(v.z, v.w));
        return;
    }
    __shared__ float t[32][33];
    const float* W = (z == 0) ? W0 : (z == 1) ? W1 : (z == 2) ? W2 : W3;
    size_t zo = (size_t)z * EMB * EMB;
    int n0 = blockIdx.x * 32, k0 = blockIdx.y * 32;
    int x = threadIdx.x, y = threadIdx.y;  // 32 x 8
#pragma unroll
    for (int r = 0; r < 32; r += 8)
        t[y + r][x] = W[(size_t)(k0 + y + r) * EMB + n0 + x];
    __syncthreads();
#pragma unroll
    for (int r = 0; r < 32; r += 8) {
        float v = t[x][y + r];
        __half h = __float2half_rn(v);
        float res = (v - __half2float(h)) * RSC;
        __half l = __float2half_rn(res);
        size_t o = zo + (size_t)(n0 + y + r) * EMB + k0 + x;
        Th[o] = *(u16*)&h;
        Tl[o] = *(u16*)&l;
    }
}

// ---------------------------------------------------------------------------
// Tensor-core GEMM, fp16 scaled-residual with IN-REGISTER A scaling:
//   D = Af * Bh + (Af*2^-6) * (Bres*64)       (two_pass mats)
//   D = Af * Bh                               (mat 2 = V, single-pass)
// cp.async 3-stage pipeline, single sync/iter. 128x128, 256 thr, 2 CTAs/SM.
// mat 0 -> Q fp16; mat 1 -> K (fp16 hi, res*64); mat 2 -> V fp16 only;
// mat 3 -> fp32 C.
// Stage layout (24 KB): AF 0, BH 8192, BL 16384.
// ---------------------------------------------------------------------------
#define BKC 32
#define GSTG 24576
#define GSMEM (3 * GSTG)

__global__ __launch_bounds__(256, 2)
void gemm_mma(const u16* __restrict__ Af,
              const u16* __restrict__ BhAll,
              const u16* __restrict__ BlAll,
              const float* __restrict__ b0, const float* __restrict__ b1,
              const float* __restrict__ b2, const float* __restrict__ b3,
              u16* __restrict__ H0,
              u16* __restrict__ H1, u16* __restrict__ L1,
              u16* __restrict__ H2,
              float* __restrict__ C, int mat_base, int M, int K)
{
    extern __shared__ char smg[];
    u32 sb = smem_u32(smg);
    const int N = EMB;

    int tid = threadIdx.x;
    int wid = tid / 32, lid = tid % 32;
    int wm = wid / 4, wn = wid % 4;        // warp grid 2 x 4
    int mat = mat_base + (blockIdx.x >> 4);
    int bm = blockIdx.y * 128, bn = (blockIdx.x & 15) * 128;
    bool twop = (mat != 2);                // V is single-pass

    const u16* Bh = BhAll + (size_t)mat * EMB * EMB;
    const u16* Bl = BlAll + (size_t)mat * EMB * EMB;
    const float* bias = (mat == 0) ? b0 : (mat == 1) ? b1 : (mat == 2) ? b2 : b3;

    float acc[4][4][4];
#pragma unroll
    for (int mt = 0; mt < 4; mt++)
#pragma unroll
        for (int nt = 0; nt < 4; nt++)
#pragma unroll
            for (int e = 0; e < 4; e++) acc[mt][nt][e] = 0.f;

    int a_r = (lid & 15);
    int a_h = (lid >> 4);
    int b_n = ((lid >> 4) << 3) + (lid & 7);
    int b_h = ((lid >> 3) & 1);

    int l_row[2], l_ch[2];
#pragma unroll
    for (int cc = 0; cc < 2; cc++) {
        int c = tid + cc * 256;
        l_row[cc] = c >> 2;
        l_ch[cc] = c & 3;
    }

#define GEMM_ISSUE(stage, k0)                                                  \
    do {                                                                       \
        u32 base_ = sb + (stage) * GSTG;                                       \
        _Pragma("unroll")                                                      \
        for (int cc = 0; cc < 2; cc++) {                                       \
            int row = l_row[cc], ch = l_ch[cc];                                \
            u32 so = SWZ64((u32)(row * 64 + ch * 16));                         \
            size_t ga = (size_t)(bm + row) * K + (k0) + ch * 8;                \
            size_t gb = (size_t)(bn + row) * K + (k0) + ch * 8;                \
            cp16(base_ + so, Af + ga);                                         \
            cp16(base_ + 8192 + so, Bh + gb);                                  \
            if (twop) cp16(base_ + 16384 + so, Bl + gb);                       \
        }                                                                      \
        CP_COMMIT();                                                           \
    } while (0)

    int niter = K / BKC;
    GEMM_ISSUE(0, 0);
    GEMM_ISSUE(1, BKC);

    for (int it = 0; it < niter; it++) {
        if (it + 1 < niter) {
            CP_WAIT(1);
        } else {
            CP_WAIT(0);
        }
        __syncthreads();
        if (it + 2 < niter)
            GEMM_ISSUE((it + 2) % 3, (it + 2) * BKC);

        u32 baseAf = sb + (it % 3) * GSTG;
        u32 baseBh = baseAf + 8192;
        u32 baseBl = baseAf + 16384;

#pragma unroll
        for (int ks = 0; ks < 2; ks++) {
            u32 af[4][4], bhf[4][2];
#pragma unroll
            for (int mt = 0; mt < 4; mt++) {
                int r = wm * 64 + mt * 16 + a_r;
                u32 addr = baseAf + SWZ64((u32)(r * 64 + (ks * 2 + a_h) * 16));
                ldsm_x4(af[mt][0], af[mt][1], af[mt][2], af[mt][3], addr);
            }
#pragma unroll
            for (int np = 0; np < 2; np++) {
                int n = wn * 32 + np * 16 + b_n;
                u32 off = SWZ64((u32)(n * 64 + (ks * 2 + b_h) * 16));
                ldsm_x4(bhf[np * 2][0], bhf[np * 2][1],
                        bhf[np * 2 + 1][0], bhf[np * 2 + 1][1], baseBh + off);
            }
            // pass 1: Af * Bh
#pragma unroll
            for (int mt = 0; mt < 4; mt++)
#pragma unroll
                for (int nt = 0; nt < 4; nt++)
                    mma_f16(acc[mt][nt], af[mt], bhf[nt]);
            // pass 2 (residual) only for two-pass mats
            if (twop) {
                u32 blf[4][2];
#pragma unroll
                for (int np = 0; np < 2; np++) {
                    int n = wn * 32 + np * 16 + b_n;
                    u32 off = SWZ64((u32)(n * 64 + (ks * 2 + b_h) * 16));
                    ldsm_x4(blf[np * 2][0], blf[np * 2][1],
                            blf[np * 2 + 1][0], blf[np * 2 + 1][1], baseBl + off);
                }
#pragma unroll
                for (int mt = 0; mt < 4; mt++)
#pragma unroll
                    for (int r = 0; r < 4; r++)
                        af[mt][r] = hscale(af[mt][r]);
#pragma unroll
                for (int mt = 0; mt < 4; mt++)
#pragma unroll
                    for (int nt = 0; nt < 4; nt++)
                        mma_f16(acc[mt][nt], af[mt], blf[nt]);
            }
        }
    }

    int rr = lid >> 2, cc2 = (lid & 3) * 2;
#pragma unroll
    for (int mt = 0; mt < 4; mt++) {
        int r0 = bm + wm * 64 + mt * 16 + rr;
#pragma unroll
        for (int nt = 0; nt < 4; nt++) {
            int col = bn + wn * 32 + nt * 8 + cc2;
            float bb0 = bias[col], bb1 = bias[col + 1];
            float v00 = acc[mt][nt][0] + bb0, v01 = acc[mt][nt][1] + bb1;
            float v10 = acc[mt][nt][2] + bb0, v11 = acc[mt][nt][3] + bb1;
            if (mat == 3) {
                *(float2*)&C[(size_t)r0 * N + col] = make_float2(v00, v01);
                *(float2*)&C[(size_t)(r0 + 8) * N + col] = make_float2(v10, v11);
            } else if (mat == 0) {
                *(u32*)&H0[(size_t)r0 * N + col] = pack_f(v00, v01);
                *(u32*)&H0[(size_t)(r0 + 8) * N + col] = pack_f(v10, v11);
            } else if (mat == 2) {
                *(u32*)&H2[(size_t)r0 * N + col] = pack_f(v00, v01);
                *(u32*)&H2[(size_t)(r0 + 8) * N + col] = pack_f(v10, v11);
            } else {
                u32 hh, rr2;
                pack_hr(v00, v01, hh, rr2);
                *(u32*)&H1[(size_t)r0 * N + col] = hh;
                *(u32*)&L1[(size_t)r0 * N + col] = rr2;
                pack_hr(v10, v11, hh, rr2);
                *(u32*)&H1[(size_t)(r0 + 8) * N + col] = hh;
                *(u32*)&L1[(size_t)(r0 + 8) * N + col] = rr2;
            }
        }
    }
}

// ---------------------------------------------------------------------------
// Tensor-core causal flash attention:
//   S = Qf*Khi + (Qf*2^-6)*(Kres*64)   (scores 2-pass: accuracy-critical)
//   O = Pf*Vf                          (V single-pass: linear, benign error)
// fp32 base-2 softmax, cp.async 2-stage K/V pipeline, V via ldmatrix.trans.
// Stage 24 KB (KF, KS, VF). 2 CTAs/SM. RoPE mathematically eliminated.
// ---------------------------------------------------------------------------
#define ABQ 128
#define ABK 64
#define OQF 0
#define AKV 16384
#define ASTG 24576
#define ASMEM (AKV + 2 * ASTG)

__global__ __launch_bounds__(256, 2)
void flash_attn_tc(const u16* __restrict__ qf_,
                   const u16* __restrict__ kf_,
                   const u16* __restrict__ ks_,
                   const u16* __restrict__ vf_,
                   u16* __restrict__ aof)
{
    extern __shared__ char smc[];
    u32 sb = smem_u32(smc);
    int tid = threadIdx.x, wid = tid / 32, lid = tid % 32;
    int qb = gridDim.x - 1 - blockIdx.x;   // longest work first
    int h = blockIdx.y, b = blockIdx.z;
    int q0 = qb * ABQ;
    int warp_row = q0 + wid * 16;

    // Load Q tile (128x64 fp16), SW128 rows
#pragma unroll
    for (int i = 0; i < 4; i++) {
        int c = tid + i * 256;
        int r = c >> 3, ch = c & 7;
        u32 so = SWZ128((u32)(r * 128 + ch * 16));
        size_t g = (size_t)(b * SEQ + q0 + r) * EMB + h * HD + ch * 8;
        *(uint4*)(smc + OQF + so) = *(const uint4*)(qf_ + g);
    }

    int v_r[2], v_ch[2];
#pragma unroll
    for (int i = 0; i < 2; i++) {
        int c = tid + i * 256;
        v_r[i] = c >> 3;
        v_ch[i] = c & 7;
    }

#define ATTN_ISSUE(stage, kb)                                                  \
    do {                                                                       \
        u32 base_ = sb + AKV + (stage) * ASTG;                                 \
        _Pragma("unroll")                                                      \
        for (int i = 0; i < 2; i++) {                                          \
            int r = v_r[i], ch = v_ch[i];                                      \
            u32 so = SWZ128((u32)(r * 128 + ch * 16));                         \
            size_t gk = (size_t)(b * SEQ + (kb) * ABK + r) * EMB + h * HD + ch * 8; \
            cp16(base_ + so, kf_ + gk);                                        \
            cp16(base_ + 8192 + so, ks_ + gk);                                 \
            cp16(base_ + 16384 + so, vf_ + gk);                                \
        }                                                                      \
        CP_COMMIT();                                                           \
    } while (0)

    float m_i[2], l_i[2], o[8][4];
    m_i[0] = m_i[1] = -INFINITY;
    l_i[0] = l_i[1] = 0.f;
#pragma unroll
    for (int nt = 0; nt < 8; nt++)
#pragma unroll
        for (int e = 0; e < 4; e++) o[nt][e] = 0.f;

    const float scale2 = 0.125f * 1.4426950408889634f;  // base-2 softmax
    int r1 = lid >> 2;
    int a_r = lid & 15, a_h = lid >> 4;
    int b_n = ((lid >> 4) << 3) + (lid & 7), b_h = (lid >> 3) & 1;
    int t_r16 = (lid & 7) + ((lid >> 3) & 1) * 8;
    int t_cb  = ((lid >> 4) & 1) * 16;

    int nkb = 2 * qb + 2;
    ATTN_ISSUE(0, 0);

    for (int kb = 0; kb < nkb; kb++) {
        if (kb + 1 < nkb) {
            ATTN_ISSUE((kb + 1) & 1, kb + 1);
            CP_WAIT(1);
        } else {
            CP_WAIT(0);
        }
        __syncthreads();

        if (kb * ABK <= warp_row + 15) {
            u32 bk = sb + AKV + (kb & 1) * ASTG;
            u32 okf = bk, oks = bk + 8192, ovf = bk + 16384;

            // ---- S = Q K^T (fp16 2-pass, Q scaled in-register) ----
            float s[8][4];
#pragma unroll
            for (int nt = 0; nt < 8; nt++)
#pragma unroll
                for (int e = 0; e < 4; e++) s[nt][e] = 0.f;

#pragma unroll
            for (int kc = 0; kc < 4; kc++) {
                u32 af[4], bhf[8][2], blf[8][2];
                u32 arow = (u32)((wid * 16 + a_r) * 128 + (kc * 2 + a_h) * 16);
                ldsm_x4(af[0], af[1], af[2], af[3], sb + OQF + SWZ128(arow));
#pragma unroll
                for (int g = 0; g < 4; g++) {
                    int n = g * 16 + b_n;
                    u32 off = SWZ128((u32)(n * 128 + (kc * 2 + b_h) * 16));
                    ldsm_x4(bhf[g * 2][0], bhf[g * 2][1],
                            bhf[g * 2 + 1][0], bhf[g * 2 + 1][1], okf + off);
                    ldsm_x4(blf[g * 2][0], blf[g * 2][1],
                            blf[g * 2 + 1][0], blf[g * 2 + 1][1], oks + off);
                }
#pragma unroll
                for (int nt = 0; nt < 8; nt++) mma_f16(s[nt], af, bhf[nt]);
#pragma unroll
                for (int r = 0; r < 4; r++) af[r] = hscale(af[r]);
#pragma unroll
                for (int nt = 0; nt < 8; nt++) mma_f16(s[nt], af, blf[nt]);
            }

            // ---- scale (base-2) + causal mask ----
            bool needmask = (kb * ABK + ABK - 1 > warp_row);
#pragma unroll
            for (int nt = 0; nt < 8; nt++) {
#pragma unroll
                for (int e = 0; e < 4; e++) {
                    s[nt][e] *= scale2;
                    if (needmask) {
                        int row = warp_row + r1 + ((e >> 1) << 3);
                        int col = kb * ABK + nt * 8 + (lid & 3) * 2 + (e & 1);
                        if (col > row) s[nt][e] = -INFINITY;
                    }
                }
            }

            // ---- online softmax in base-2 (rows r1, r1+8) ----
#pragma unroll
            for (int half = 0; half < 2; half++) {
                float mx = -INFINITY;
#pragma unroll
                for (int nt = 0; nt < 8; nt++)
                    mx = fmaxf(mx, fmaxf(s[nt][half * 2], s[nt][half * 2 + 1]));
                mx = fmaxf(mx, __shfl_xor_sync(0xffffffffu, mx, 1));
                mx = fmaxf(mx, __shfl_xor_sync(0xffffffffu, mx, 2));
                float m_new = fmaxf(m_i[half], mx);
                float corr = ex2(m_i[half] - m_new);
                m_i[half] = m_new;
                float rs = 0.f;
#pragma unroll
                for (int nt = 0; nt < 8; nt++) {
                    float p0 = ex2(s[nt][half * 2] - m_new);
                    float p1 = ex2(s[nt][half * 2 + 1] - m_new);
                    s[nt][half * 2] = p0;
                    s[nt][half * 2 + 1] = p1;
                    rs += p0 + p1;
                }
                rs += __shfl_xor_sync(0xffffffffu, rs, 1);
                rs += __shfl_xor_sync(0xffffffffu, rs, 2);
                l_i[half] = l_i[half] * corr + rs;
#pragma unroll
                for (int nt = 0; nt < 8; nt++) {
                    o[nt][half * 2] *= corr;
                    o[nt][half * 2 + 1] *= corr;
                }
            }

            // ---- O += P V (fp16 single-pass, V via ldmatrix.trans) ----
#pragma unroll
            for (int kc = 0; kc < 4; kc++) {
                u32 pf[4];
                pf[0] = pack_f(s[2 * kc][0], s[2 * kc][1]);
                pf[1] = pack_f(s[2 * kc][2], s[2 * kc][3]);
                pf[2] = pack_f(s[2 * kc + 1][0], s[2 * kc + 1][1]);
                pf[3] = pack_f(s[2 * kc + 1][2], s[2 * kc + 1][3]);

                u32 bvf[8][2];
                u32 trow = (u32)((kc * 16 + t_r16) * 128);
#pragma unroll
                for (int g = 0; g < 4; g++) {
                    u32 off = SWZ128(trow + g * 32 + t_cb);
                    ldsm_x4t(bvf[g * 2][0], bvf[g * 2][1],
                             bvf[g * 2 + 1][0], bvf[g * 2 + 1][1], ovf + off);
                }
#pragma unroll
                for (int nt = 0; nt < 8; nt++) mma_f16(o[nt], pf, bvf[nt]);
            }
        }
        __syncthreads();
    }

    // ---- epilogue: normalize, emit fp16 for out-proj ----
#pragma unroll
    for (int half = 0; half < 2; half++) {
        float inv = 1.f / l_i[half];
        int row = warp_row + r1 + half * 8;
        size_t base = (size_t)(b * SEQ + row) * EMB + h * HD;
#pragma unroll
        for (int nt = 0; nt < 8; nt++) {
            int col = nt * 8 + (lid & 3) * 2;
            float v0 = o[nt][half * 2] * inv;
            float v1 = o[nt][half * 2 + 1] * inv;
            *(u32*)&aof[base + col] = pack_f(v0, v1);
        }
    }
}

// ---------------------------------------------------------------------------
// Launch
// ---------------------------------------------------------------------------
extern "C" void kernel_launch(void* const* d_in, const int* in_sizes, int n_in,
                              void* d_out, int out_size)
{
    const float* x  = (const float*)d_in[0];
    const float* Wq = (const float*)d_in[1];
    const float* bq = (const float*)d_in[2];
    const float* Wk = (const float*)d_in[3];
    const float* bk = (const float*)d_in[4];
    const float* Wv = (const float*)d_in[5];
    const float* bv = (const float*)d_in[6];
    const float* Wo = (const float*)d_in[7];
    const float* bo = (const float*)d_in[8];
    float* out = (float*)d_out;

    u16 *af, *bh, *bl, *qf, *kf, *ks, *vf;
    cudaGetSymbolAddress((void**)&af, g_af);
    cudaGetSymbolAddress((void**)&bh, g_bh);
    cudaGetSymbolAddress((void**)&bl, g_bl);
    cudaGetSymbolAddress((void**)&qf, g_qf);
    cudaGetSymbolAddress((void**)&kf, g_kf);
    cudaGetSymbolAddress((void**)&ks, g_ks);
    cudaGetSymbolAddress((void**)&vf, g_vf);

    cudaFuncSetAttribute(gemm_mma,
                         cudaFuncAttributeMaxDynamicSharedMemorySize, GSMEM);
    cudaFuncSetAttribute(flash_attn_tc,
                         cudaFuncAttributeMaxDynamicSharedMemorySize, ASMEM);

    dim3 ct(32, 8);
    dim3 cg6(EMB / 32, EMB / 32, 6);            // 4 weights + 2 x-halves
    dim3 qkvgrid(3 * EMB / 128, MROWS / 128);   // (48, 32): fused Q,K,V
    dim3 ogrid(EMB / 128, MROWS / 128);         // (16, 32): out proj
    dim3 agrid(SEQ / ABQ, NH, BSZ);             // (16, 32, 2)

    // one fused conversion launch
    conv_all<<<cg6, ct>>>(Wq, Wk, Wv, Wo, x, bh, bl, af);

    // fused QKV projection (Q,K 2-pass; V single-pass)
    gemm_mma<<<qkvgrid, 256, GSMEM>>>(af, bh, bl, bq, bk, bv, bo,
                                      qf, kf, ks, vf, NULL, 0,
                                      MROWS, EMB);

    // attention (QK 2-pass, PV single-pass) -> fp16 into af
    flash_attn_tc<<<agrid, 256, ASMEM>>>(qf, kf, ks, vf, af);

    // output projection (2-pass, mat 3, fp32 out)
    gemm_mma<<<ogrid, 256, GSMEM>>>(af, bh, bl, bq, bk, bv, bo,
                                    qf, kf, ks, vf, out, 3,
                                    MROWS, EMB);
}

// round 17
// speedup vs baseline: 2.6196x; 1.4641x over previous
#include <cuda_runtime.h>
#include <cuda_bf16.h>
#include <cuda_fp16.h>
#include <cstdint>
#include <math.h>

typedef unsigned int u32;
typedef unsigned long long u64;
typedef unsigned short u16;

#define BSZ 2
#define SEQ 2048
#define EMB 2048
#define NH 32
#define HD 64
#define MROWS (BSZ*SEQ)

// ---------------------------------------------------------------------------
// Scratch (device globals: allocation-free per harness rules)
// All operands plain fp16 (full single-pass; error budget 7.6e-4 < 1e-3,
// calibrated: each dropped residual adds 2.8e-4 in quadrature).
// ---------------------------------------------------------------------------
__device__ __align__(16) u16 g_af[(size_t)MROWS * EMB];
__device__ __align__(16) u16 g_bh[(size_t)4 * EMB * EMB];
__device__ __align__(16) u16 g_qf[(size_t)MROWS * EMB];
__device__ __align__(16) u16 g_kf[(size_t)MROWS * EMB];
__device__ __align__(16) u16 g_vf[(size_t)MROWS * EMB];

// ---------------------------------------------------------------------------
// Warp-MMA / cp.async helpers (baseline PTX: works on plain sm_103 target)
// ---------------------------------------------------------------------------
__device__ __forceinline__ u32 smem_u32(const void* p) {
    u32 a;
    asm("{ .reg .u64 t; cvta.to.shared.u64 t, %1; cvt.u32.u64 %0, t; }"
        : "=r"(a) : "l"(p));
    return a;
}
__device__ __forceinline__ void ldsm_x4(u32& r0, u32& r1, u32& r2, u32& r3,
                                        u32 addr) {
    asm volatile("ldmatrix.sync.aligned.m8n8.x4.shared.b16 {%0,%1,%2,%3}, [%4];"
                 : "=r"(r0), "=r"(r1), "=r"(r2), "=r"(r3) : "r"(addr));
}
__device__ __forceinline__ void ldsm_x4t(u32& r0, u32& r1, u32& r2, u32& r3,
                                         u32 addr) {
    asm volatile("ldmatrix.sync.aligned.m8n8.x4.trans.shared.b16 {%0,%1,%2,%3}, [%4];"
                 : "=r"(r0), "=r"(r1), "=r"(r2), "=r"(r3) : "r"(addr));
}
__device__ __forceinline__ void mma_f16(float* d, const u32* a, const u32* b) {
    asm volatile(
        "mma.sync.aligned.m16n8k16.row.col.f32.f16.f16.f32 "
        "{%0,%1,%2,%3}, {%4,%5,%6,%7}, {%8,%9}, {%0,%1,%2,%3};"
        : "+f"(d[0]), "+f"(d[1]), "+f"(d[2]), "+f"(d[3])
        : "r"(a[0]), "r"(a[1]), "r"(a[2]), "r"(a[3]), "r"(b[0]), "r"(b[1]));
}
__device__ __forceinline__ void cp16(u32 dst, const void* src) {
    asm volatile("cp.async.cg.shared.global [%0], [%1], 16;"
                 :: "r"(dst), "l"(src) : "memory");
}
#define CP_COMMIT() asm volatile("cp.async.commit_group;" ::: "memory")
#define CP_WAIT(n)  asm volatile("cp.async.wait_group %0;" :: "n"(n) : "memory")

__device__ __forceinline__ float ex2(float x) {
    float y;
    asm("ex2.approx.f32 %0, %1;" : "=f"(y) : "f"(x));
    return y;
}
__device__ __forceinline__ u32 pack_f(float x0, float x1) {
    __half2 hf = __float22half2_rn(make_float2(x0, x1));
    return *(u32*)&hf;
}
#define SWZ64(o)  ((o) ^ (((o) >> 3) & 0x30))
#define SWZ128(o) ((o) ^ (((o) >> 3) & 0x70))

// ---------------------------------------------------------------------------
// Fused conversion: z=0..3 -> W_z^T fp16; z=4,5 -> x fp16
// ---------------------------------------------------------------------------
__global__ void conv_all(const float* __restrict__ W0, const float* __restrict__ W1,
                         const float* __restrict__ W2, const float* __restrict__ W3,
                         const float* __restrict__ X,
                         u16* __restrict__ Th, u16* __restrict__ XF)
{
    int z = blockIdx.z;
    if (z >= 4) {
        int t = threadIdx.y * 32 + threadIdx.x;
        size_t i = ((size_t)(z - 4) * 4096 + blockIdx.y * 64 + blockIdx.x) * 256 + t;
        float4 v = ((const float4*)X)[i];
        ((uint2*)XF)[i] = make_uint2(pack_f(v.x, v.y), pack_f(v.z, v.w));
        return;
    }
    __shared__ float t[32][33];
    const float* W = (z == 0) ? W0 : (z == 1) ? W1 : (z == 2) ? W2 : W3;
    size_t zo = (size_t)z * EMB * EMB;
    int n0 = blockIdx.x * 32, k0 = blockIdx.y * 32;
    int x = threadIdx.x, y = threadIdx.y;  // 32 x 8
#pragma unroll
    for (int r = 0; r < 32; r += 8)
        t[y + r][x] = W[(size_t)(k0 + y + r) * EMB + n0 + x];
    __syncthreads();
#pragma unroll
    for (int r = 0; r < 32; r += 8) {
        float v = t[x][y + r];
        __half h = __float2half_rn(v);
        size_t o = zo + (size_t)(n0 + y + r) * EMB + k0 + x;
        Th[o] = *(u16*)&h;
    }
}

// ---------------------------------------------------------------------------
// Tensor-core GEMM, single-pass fp16: D = Af * Bh.
// cp.async 3-stage pipeline, single sync/iter. 128x128, 256 thr, 2 CTAs/SM.
// mats 0,1,2 -> fp16 Q/K/V; mat 3 -> fp32 C.
// Stage layout (16 KB): AF 0, BH 8192.
// ---------------------------------------------------------------------------
#define BKC 32
#define GSTG 16384
#define GSMEM (3 * GSTG)

__global__ __launch_bounds__(256, 2)
void gemm_mma(const u16* __restrict__ Af,
              const u16* __restrict__ BhAll,
              const float* __restrict__ b0, const float* __restrict__ b1,
              const float* __restrict__ b2, const float* __restrict__ b3,
              u16* __restrict__ H0, u16* __restrict__ H1,
              u16* __restrict__ H2,
              float* __restrict__ C, int mat_base, int M, int K)
{
    extern __shared__ char smg[];
    u32 sb = smem_u32(smg);
    const int N = EMB;

    int tid = threadIdx.x;
    int wid = tid / 32, lid = tid % 32;
    int wm = wid / 4, wn = wid % 4;        // warp grid 2 x 4
    int mat = mat_base + (blockIdx.x >> 4);
    int bm = blockIdx.y * 128, bn = (blockIdx.x & 15) * 128;

    const u16* Bh = BhAll + (size_t)mat * EMB * EMB;
    const float* bias = (mat == 0) ? b0 : (mat == 1) ? b1 : (mat == 2) ? b2 : b3;

    float acc[4][4][4];
#pragma unroll
    for (int mt = 0; mt < 4; mt++)
#pragma unroll
        for (int nt = 0; nt < 4; nt++)
#pragma unroll
            for (int e = 0; e < 4; e++) acc[mt][nt][e] = 0.f;

    int a_r = (lid & 15);
    int a_h = (lid >> 4);
    int b_n = ((lid >> 4) << 3) + (lid & 7);
    int b_h = ((lid >> 3) & 1);

    int l_row[2], l_ch[2];
#pragma unroll
    for (int cc = 0; cc < 2; cc++) {
        int c = tid + cc * 256;
        l_row[cc] = c >> 2;
        l_ch[cc] = c & 3;
    }

#define GEMM_ISSUE(stage, k0)                                                  \
    do {                                                                       \
        u32 base_ = sb + (stage) * GSTG;                                       \
        _Pragma("unroll")                                                      \
        for (int cc = 0; cc < 2; cc++) {                                       \
            int row = l_row[cc], ch = l_ch[cc];                                \
            u32 so = SWZ64((u32)(row * 64 + ch * 16));                         \
            size_t ga = (size_t)(bm + row) * K + (k0) + ch * 8;                \
            size_t gb = (size_t)(bn + row) * K + (k0) + ch * 8;                \
            cp16(base_ + so, Af + ga);                                         \
            cp16(base_ + 8192 + so, Bh + gb);                                  \
        }                                                                      \
        CP_COMMIT();                                                           \
    } while (0)

    int niter = K / BKC;
    GEMM_ISSUE(0, 0);
    GEMM_ISSUE(1, BKC);

    for (int it = 0; it < niter; it++) {
        if (it + 1 < niter) {
            CP_WAIT(1);
        } else {
            CP_WAIT(0);
        }
        __syncthreads();
        if (it + 2 < niter)
            GEMM_ISSUE((it + 2) % 3, (it + 2) * BKC);

        u32 baseAf = sb + (it % 3) * GSTG;
        u32 baseBh = baseAf + 8192;

#pragma unroll
        for (int ks = 0; ks < 2; ks++) {
            u32 af[4][4], bhf[4][2];
#pragma unroll
            for (int mt = 0; mt < 4; mt++) {
                int r = wm * 64 + mt * 16 + a_r;
                u32 addr = baseAf + SWZ64((u32)(r * 64 + (ks * 2 + a_h) * 16));
                ldsm_x4(af[mt][0], af[mt][1], af[mt][2], af[mt][3], addr);
            }
#pragma unroll
            for (int np = 0; np < 2; np++) {
                int n = wn * 32 + np * 16 + b_n;
                u32 off = SWZ64((u32)(n * 64 + (ks * 2 + b_h) * 16));
                ldsm_x4(bhf[np * 2][0], bhf[np * 2][1],
                        bhf[np * 2 + 1][0], bhf[np * 2 + 1][1], baseBh + off);
            }
#pragma unroll
            for (int mt = 0; mt < 4; mt++)
#pragma unroll
                for (int nt = 0; nt < 4; nt++)
                    mma_f16(acc[mt][nt], af[mt], bhf[nt]);
        }
    }

    int rr = lid >> 2, cc2 = (lid & 3) * 2;
#pragma unroll
    for (int mt = 0; mt < 4; mt++) {
        int r0 = bm + wm * 64 + mt * 16 + rr;
#pragma unroll
        for (int nt = 0; nt < 4; nt++) {
            int col = bn + wn * 32 + nt * 8 + cc2;
            float bb0 = bias[col], bb1 = bias[col + 1];
            float v00 = acc[mt][nt][0] + bb0, v01 = acc[mt][nt][1] + bb1;
            float v10 = acc[mt][nt][2] + bb0, v11 = acc[mt][nt][3] + bb1;
            if (mat == 3) {
                *(float2*)&C[(size_t)r0 * N + col] = make_float2(v00, v01);
                *(float2*)&C[(size_t)(r0 + 8) * N + col] = make_float2(v10, v11);
            } else {
                u16* H = (mat == 0) ? H0 : (mat == 1) ? H1 : H2;
                *(u32*)&H[(size_t)r0 * N + col] = pack_f(v00, v01);
                *(u32*)&H[(size_t)(r0 + 8) * N + col] = pack_f(v10, v11);
            }
        }
    }
}

// ---------------------------------------------------------------------------
// Tensor-core causal flash attention, single-pass fp16:
//   S = Qf*Kf;  O = Pf*Vf    (fp32 accumulate + fp32 base-2 softmax)
// cp.async 2-stage K/V pipeline, V via ldmatrix.trans.
// Stage 16 KB (KF, VF). 2 CTAs/SM. RoPE mathematically eliminated
// (reference rotation depends only on head index -> q.k invariant).
// ---------------------------------------------------------------------------
#define ABQ 128
#define ABK 64
#define OQF 0
#define AKV 16384
#define ASTG 16384
#define ASMEM (AKV + 2 * ASTG)

__global__ __launch_bounds__(256, 2)
void flash_attn_tc(const u16* __restrict__ qf_,
                   const u16* __restrict__ kf_,
                   const u16* __restrict__ vf_,
                   u16* __restrict__ aof)
{
    extern __shared__ char smc[];
    u32 sb = smem_u32(smc);
    int tid = threadIdx.x, wid = tid / 32, lid = tid % 32;
    int qb = gridDim.x - 1 - blockIdx.x;   // longest work first
    int h = blockIdx.y, b = blockIdx.z;
    int q0 = qb * ABQ;
    int warp_row = q0 + wid * 16;

    // Load Q tile (128x64 fp16), SW128 rows
#pragma unroll
    for (int i = 0; i < 4; i++) {
        int c = tid + i * 256;
        int r = c >> 3, ch = c & 7;
        u32 so = SWZ128((u32)(r * 128 + ch * 16));
        size_t g = (size_t)(b * SEQ + q0 + r) * EMB + h * HD + ch * 8;
        *(uint4*)(smc + OQF + so) = *(const uint4*)(qf_ + g);
    }

    int v_r[2], v_ch[2];
#pragma unroll
    for (int i = 0; i < 2; i++) {
        int c = tid + i * 256;
        v_r[i] = c >> 3;
        v_ch[i] = c & 7;
    }

#define ATTN_ISSUE(stage, kb)                                                  \
    do {                                                                       \
        u32 base_ = sb + AKV + (stage) * ASTG;                                 \
        _Pragma("unroll")                                                      \
        for (int i = 0; i < 2; i++) {                                          \
            int r = v_r[i], ch = v_ch[i];                                      \
            u32 so = SWZ128((u32)(r * 128 + ch * 16));                         \
            size_t gk = (size_t)(b * SEQ + (kb) * ABK + r) * EMB + h * HD + ch * 8; \
            cp16(base_ + so, kf_ + gk);                                        \
            cp16(base_ + 8192 + so, vf_ + gk);                                 \
        }                                                                      \
        CP_COMMIT();                                                           \
    } while (0)

    float m_i[2], l_i[2], o[8][4];
    m_i[0] = m_i[1] = -INFINITY;
    l_i[0] = l_i[1] = 0.f;
#pragma unroll
    for (int nt = 0; nt < 8; nt++)
#pragma unroll
        for (int e = 0; e < 4; e++) o[nt][e] = 0.f;

    const float scale2 = 0.125f * 1.4426950408889634f;  // base-2 softmax
    int r1 = lid >> 2;
    int a_r = lid & 15, a_h = lid >> 4;
    int b_n = ((lid >> 4) << 3) + (lid & 7), b_h = (lid >> 3) & 1;
    int t_r16 = (lid & 7) + ((lid >> 3) & 1) * 8;
    int t_cb  = ((lid >> 4) & 1) * 16;

    int nkb = 2 * qb + 2;
    ATTN_ISSUE(0, 0);

    for (int kb = 0; kb < nkb; kb++) {
        if (kb + 1 < nkb) {
            ATTN_ISSUE((kb + 1) & 1, kb + 1);
            CP_WAIT(1);
        } else {
            CP_WAIT(0);
        }
        __syncthreads();

        if (kb * ABK <= warp_row + 15) {
            u32 bk = sb + AKV + (kb & 1) * ASTG;
            u32 okf = bk, ovf = bk + 8192;

            // ---- S = Q K^T (fp16 single-pass) ----
            float s[8][4];
#pragma unroll
            for (int nt = 0; nt < 8; nt++)
#pragma unroll
                for (int e = 0; e < 4; e++) s[nt][e] = 0.f;

#pragma unroll
            for (int kc = 0; kc < 4; kc++) {
                u32 af[4], bhf[8][2];
                u32 arow = (u32)((wid * 16 + a_r) * 128 + (kc * 2 + a_h) * 16);
                ldsm_x4(af[0], af[1], af[2], af[3], sb + OQF + SWZ128(arow));
#pragma unroll
                for (int g = 0; g < 4; g++) {
                    int n = g * 16 + b_n;
                    u32 off = SWZ128((u32)(n * 128 + (kc * 2 + b_h) * 16));
                    ldsm_x4(bhf[g * 2][0], bhf[g * 2][1],
                            bhf[g * 2 + 1][0], bhf[g * 2 + 1][1], okf + off);
                }
#pragma unroll
                for (int nt = 0; nt < 8; nt++) mma_f16(s[nt], af, bhf[nt]);
            }

            // ---- scale (base-2) + causal mask ----
            bool needmask = (kb * ABK + ABK - 1 > warp_row);
#pragma unroll
            for (int nt = 0; nt < 8; nt++) {
#pragma unroll
                for (int e = 0; e < 4; e++) {
                    s[nt][e] *= scale2;
                    if (needmask) {
                        int row = warp_row + r1 + ((e >> 1) << 3);
                        int col = kb * ABK + nt * 8 + (lid & 3) * 2 + (e & 1);
                        if (col > row) s[nt][e] = -INFINITY;
                    }
                }
            }

            // ---- online softmax in base-2 (rows r1, r1+8) ----
#pragma unroll
            for (int half = 0; half < 2; half++) {
                float mx = -INFINITY;
#pragma unroll
                for (int nt = 0; nt < 8; nt++)
                    mx = fmaxf(mx, fmaxf(s[nt][half * 2], s[nt][half * 2 + 1]));
                mx = fmaxf(mx, __shfl_xor_sync(0xffffffffu, mx, 1));
                mx = fmaxf(mx, __shfl_xor_sync(0xffffffffu, mx, 2));
                float m_new = fmaxf(m_i[half], mx);
                float corr = ex2(m_i[half] - m_new);
                m_i[half] = m_new;
                float rs = 0.f;
#pragma unroll
                for (int nt = 0; nt < 8; nt++) {
                    float p0 = ex2(s[nt][half * 2] - m_new);
                    float p1 = ex2(s[nt][half * 2 + 1] - m_new);
                    s[nt][half * 2] = p0;
                    s[nt][half * 2 + 1] = p1;
                    rs += p0 + p1;
                }
                rs += __shfl_xor_sync(0xffffffffu, rs, 1);
                rs += __shfl_xor_sync(0xffffffffu, rs, 2);
                l_i[half] = l_i[half] * corr + rs;
#pragma unroll
                for (int nt = 0; nt < 8; nt++) {
                    o[nt][half * 2] *= corr;
                    o[nt][half * 2 + 1] *= corr;
                }
            }

            // ---- O += P V (fp16 single-pass, V via ldmatrix.trans) ----
#pragma unroll
            for (int kc = 0; kc < 4; kc++) {
                u32 pf[4];
                pf[0] = pack_f(s[2 * kc][0], s[2 * kc][1]);
                pf[1] = pack_f(s[2 * kc][2], s[2 * kc][3]);
                pf[2] = pack_f(s[2 * kc + 1][0], s[2 * kc + 1][1]);
                pf[3] = pack_f(s[2 * kc + 1][2], s[2 * kc + 1][3]);

                u32 bvf[8][2];
                u32 trow = (u32)((kc * 16 + t_r16) * 128);
#pragma unroll
                for (int g = 0; g < 4; g++) {
                    u32 off = SWZ128(trow + g * 32 + t_cb);
                    ldsm_x4t(bvf[g * 2][0], bvf[g * 2][1],
                             bvf[g * 2 + 1][0], bvf[g * 2 + 1][1], ovf + off);
                }
#pragma unroll
                for (int nt = 0; nt < 8; nt++) mma_f16(o[nt], pf, bvf[nt]);
            }
        }
        __syncthreads();
    }

    // ---- epilogue: normalize, emit fp16 for out-proj ----
#pragma unroll
    for (int half = 0; half < 2; half++) {
        float inv = 1.f / l_i[half];
        int row = warp_row + r1 + half * 8;
        size_t base = (size_t)(b * SEQ + row) * EMB + h * HD;
#pragma unroll
        for (int nt = 0; nt < 8; nt++) {
            int col = nt * 8 + (lid & 3) * 2;
            float v0 = o[nt][half * 2] * inv;
            float v1 = o[nt][half * 2 + 1] * inv;
            *(u32*)&aof[base + col] = pack_f(v0, v1);
        }
    }
}

// ---------------------------------------------------------------------------
// Launch
// ---------------------------------------------------------------------------
extern "C" void kernel_launch(void* const* d_in, const int* in_sizes, int n_in,
                              void* d_out, int out_size)
{
    const float* x  = (const float*)d_in[0];
    const float* Wq = (const float*)d_in[1];
    const float* bq = (const float*)d_in[2];
    const float* Wk = (const float*)d_in[3];
    const float* bk = (const float*)d_in[4];
    const float* Wv = (const float*)d_in[5];
    const float* bv = (const float*)d_in[6];
    const float* Wo = (const float*)d_in[7];
    const float* bo = (const float*)d_in[8];
    float* out = (float*)d_out;

    u16 *af, *bh, *qf, *kf, *vf;
    cudaGetSymbolAddress((void**)&af, g_af);
    cudaGetSymbolAddress((void**)&bh, g_bh);
    cudaGetSymbolAddress((void**)&qf, g_qf);
    cudaGetSymbolAddress((void**)&kf, g_kf);
    cudaGetSymbolAddress((void**)&vf, g_vf);

    cudaFuncSetAttribute(gemm_mma,
                         cudaFuncAttributeMaxDynamicSharedMemorySize, GSMEM);
    cudaFuncSetAttribute(flash_attn_tc,
                         cudaFuncAttributeMaxDynamicSharedMemorySize, ASMEM);

    dim3 ct(32, 8);
    dim3 cg6(EMB / 32, EMB / 32, 6);            // 4 weights + 2 x-halves
    dim3 qkvgrid(3 * EMB / 128, MROWS / 128);   // (48, 32): fused Q,K,V
    dim3 ogrid(EMB / 128, MROWS / 128);         // (16, 32): out proj
    dim3 agrid(SEQ / ABQ, NH, BSZ);             // (16, 32, 2)

    // one fused conversion launch (all fp16, no residuals)
    conv_all<<<cg6, ct>>>(Wq, Wk, Wv, Wo, x, bh, af);

    // fused QKV projection (single-pass fp16)
    gemm_mma<<<qkvgrid, 256, GSMEM>>>(af, bh, bq, bk, bv, bo,
                                      qf, kf, vf, NULL, 0, MROWS, EMB);

    // attention (single-pass fp16) -> fp16 into af
    flash_attn_tc<<<agrid, 256, ASMEM>>>(qf, kf, vf, af);

    // output projection (single-pass, mat 3, fp32 out)
    gemm_mma<<<ogrid, 256, GSMEM>>>(af, bh, bq, bk, bv, bo,
                                    qf, kf, vf, out, 3, MROWS, EMB);
}